// round 4
// baseline (speedup 1.0000x reference)
#include <cuda_runtime.h>
#include <cuda_bf16.h>
#include <cstdint>

#define NN   20000
#define BB   128
#define EE   320000
#define FIN  768
#define RAWF 5000
#define HH   256
#define CC   4

// ---------------- scratch (device globals) ----------------
__device__ __align__(16) __nv_bfloat16 g_hb[NN * HH];    // branch3 h (bf16)
__device__ __align__(16) __nv_bfloat16 g_hb0[NN * HH];   // branch1 h (bf16)
__device__ __align__(16) __nv_bfloat16 g_aggb[NN * HH];  // branch3 activation (bf16)
__device__ __align__(16) float g_l1[BB * 512];
__device__ __align__(16) __nv_bfloat16 g_l1b[BB * 512];
__device__ __align__(16) float g_newx[BB * HH];
__device__ __align__(16) float g_xmax[BB * HH];
__device__ __align__(16) float g_p0[BB * HH];
__device__ __align__(16) float g_p1[BB * HH];
__device__ __align__(16) float g_p2[BB * HH];
__device__ __align__(16) __nv_bfloat16 g_newxinb[BB * 2 * RAWF];
// packed k2-interleaved bf16 weights
#define OFF_W1   0
#define OFF_WC0  98304
#define OFF_WC1  738304
#define OFF_WC2  771072
#define OFF_WL1  803840
#define OFF_WL2  3363840
__device__ __align__(16) uint32_t g_wp[3429376];
__device__ __align__(16) int   g_cnt[NN];
__device__ int   g_cursor[NN];
__device__ __align__(16) int   g_rs0[NN + 4];
__device__ __align__(16) int   g_rs1[NN + 4];
__device__ int   g_src0[EE];
__device__ int   g_src1[EE];
__device__ __align__(16) float g_dinv0[NN];
__device__ __align__(16) float g_dinv1[NN];
__device__ int   g_bounds[BB + 1];

// ---------------- helpers ----------------
__device__ __forceinline__ uint32_t packbf(float lo, float hi) {
    uint32_t r;
    asm("cvt.rn.bf16x2.f32 %0, %1, %2;" : "=r"(r) : "f"(hi), "f"(lo));
    return r;
}
__device__ __forceinline__ void cpasync16(uint32_t dst, const void* src, bool ok) {
    int ss = ok ? 16 : 0;
    asm volatile("cp.async.cg.shared.global [%0], [%1], 16, %2;\n" :: "r"(dst), "l"(src), "r"(ss));
}
__device__ __forceinline__ void cpcommit() { asm volatile("cp.async.commit_group;\n"); }
__device__ __forceinline__ void cpwait0()  { asm volatile("cp.async.wait_group 0;\n"); }
__device__ __forceinline__ void unp(uint32_t w, float& a, float& b) {
    a = __uint_as_float(w << 16);
    b = __uint_as_float(w & 0xffff0000u);
}

// ---------------- segment bounds ----------------
__global__ void bounds_kernel(const int* __restrict__ batch) {
    int b = threadIdx.x;
    if (b > BB) return;
    int lo = 0, hi = NN;
    while (lo < hi) {
        int mid = (lo + hi) >> 1;
        if (batch[mid] < b) lo = mid + 1; else hi = mid;
    }
    g_bounds[b] = lo;
}

// ---------------- weight prep ----------------
__global__ void prep_w_kernel(const float* __restrict__ W, uint32_t* __restrict__ Wp,
                              int cnt, int N) {
    int idx = blockIdx.x * blockDim.x + threadIdx.x;
    if (idx >= cnt) return;
    int p = idx / N, n = idx - p * N;
    Wp[idx] = packbf(W[(size_t)(2 * p) * N + n], W[(size_t)(2 * p + 1) * N + n]);
}

// ---------------- zeroing ----------------
__global__ void zero_pools_kernel() {
    int i = blockIdx.x * blockDim.x + threadIdx.x;
    if (i >= BB * HH) return;
    g_xmax[i] = 0.f; g_p0[i] = 0.f; g_p1[i] = 0.f; g_p2[i] = 0.f;
}

// ---------------- CSR build ----------------
__global__ void zero_cnt_kernel() {
    int i = blockIdx.x * blockDim.x + threadIdx.x;
    if (i < NN) g_cnt[i] = 0;
}
__global__ void hist_kernel(const int* __restrict__ dst) {
    int e = blockIdx.x * blockDim.x + threadIdx.x;
    if (e < EE) atomicAdd(&g_cnt[dst[e]], 1);
}
__global__ void scan_kernel(int* __restrict__ rs, float* __restrict__ dinv) {
    __shared__ int wsum[32];
    int t = threadIdx.x;
    int lane = t & 31, wid = t >> 5;
    int c[20];
    const int4* c4 = (const int4*)g_cnt;
#pragma unroll
    for (int i = 0; i < 5; i++) {
        int idx4 = t * 5 + i;
        int4 v = (idx4 < 5000) ? c4[idx4] : make_int4(0, 0, 0, 0);
        c[i * 4 + 0] = v.x; c[i * 4 + 1] = v.y; c[i * 4 + 2] = v.z; c[i * 4 + 3] = v.w;
    }
    int loc[20];
    int s = 0;
#pragma unroll
    for (int i = 0; i < 20; i++) { loc[i] = s; s += c[i]; }
    int x = s;
#pragma unroll
    for (int off = 1; off < 32; off <<= 1) {
        int y = __shfl_up_sync(0xffffffffu, x, off);
        if (lane >= off) x += y;
    }
    if (lane == 31) wsum[wid] = x;
    __syncthreads();
    if (wid == 0) {
        int v = wsum[lane];
#pragma unroll
        for (int off = 1; off < 32; off <<= 1) {
            int y = __shfl_up_sync(0xffffffffu, v, off);
            if (lane >= off) v += y;
        }
        wsum[lane] = v;
    }
    __syncthreads();
    int offset = (wid ? wsum[wid - 1] : 0) + (x - s);
    int4* rs4 = (int4*)rs;
    float4* dv4 = (float4*)dinv;
#pragma unroll
    for (int i = 0; i < 5; i++) {
        int idx4 = t * 5 + i;
        if (idx4 < 5000) {
            int4 r; float4 d;
            r.x = offset + loc[i * 4 + 0]; d.x = rsqrtf((float)(c[i * 4 + 0] + 1));
            r.y = offset + loc[i * 4 + 1]; d.y = rsqrtf((float)(c[i * 4 + 1] + 1));
            r.z = offset + loc[i * 4 + 2]; d.z = rsqrtf((float)(c[i * 4 + 2] + 1));
            r.w = offset + loc[i * 4 + 3]; d.w = rsqrtf((float)(c[i * 4 + 3] + 1));
            rs4[idx4] = r; dv4[idx4] = d;
        }
    }
    if (t == 0) rs[NN] = EE;
}
__global__ void cursor_kernel(const int* __restrict__ rs) {
    int i = blockIdx.x * blockDim.x + threadIdx.x;
    if (i < NN) g_cursor[i] = rs[i];
}
__global__ void fill_kernel(const int* __restrict__ src, const int* __restrict__ dst,
                            int* __restrict__ out) {
    int e = blockIdx.x * blockDim.x + threadIdx.x;
    if (e >= EE) return;
    int pos = atomicAdd(&g_cursor[dst[e]], 1);
    out[pos] = src[e];
}

// ---------------- fused GCN aggregation + relu + pool ----------------
// h in bf16; accumulate fp32; optional bf16 activation out; pool fused (atomic).
__global__ __launch_bounds__(256)
void gather_kernel(const uint4* __restrict__ hb, const float* __restrict__ bias,
                   const int* __restrict__ rs, const int* __restrict__ csr,
                   const float* __restrict__ dinv, const int* __restrict__ batch,
                   __nv_bfloat16* __restrict__ outb, float* __restrict__ poolsum,
                   int* __restrict__ poolmax) {
    int node = blockIdx.x * 8 + (threadIdx.x >> 5);
    int lane = threadIdx.x & 31;
    float di = dinv[node];
    float sw = di * di;
    float acc[8];
    {
        uint4 hv = hb[(size_t)node * 32 + lane];
        float f0, f1;
        unp(hv.x, f0, f1); acc[0] = f0 * sw; acc[1] = f1 * sw;
        unp(hv.y, f0, f1); acc[2] = f0 * sw; acc[3] = f1 * sw;
        unp(hv.z, f0, f1); acc[4] = f0 * sw; acc[5] = f1 * sw;
        unp(hv.w, f0, f1); acc[6] = f0 * sw; acc[7] = f1 * sw;
    }
    int e0 = rs[node], e1 = rs[node + 1];
    for (int e = e0; e < e1; e++) {
        int s = csr[e];
        float w = dinv[s] * di;
        uint4 hv = hb[(size_t)s * 32 + lane];
        float f0, f1;
        unp(hv.x, f0, f1); acc[0] = fmaf(f0, w, acc[0]); acc[1] = fmaf(f1, w, acc[1]);
        unp(hv.y, f0, f1); acc[2] = fmaf(f0, w, acc[2]); acc[3] = fmaf(f1, w, acc[3]);
        unp(hv.z, f0, f1); acc[4] = fmaf(f0, w, acc[4]); acc[5] = fmaf(f1, w, acc[5]);
        unp(hv.w, f0, f1); acc[6] = fmaf(f0, w, acc[6]); acc[7] = fmaf(f1, w, acc[7]);
    }
    float4 bb0 = ((const float4*)bias)[2 * lane];
    float4 bb1 = ((const float4*)bias)[2 * lane + 1];
    float v[8];
    v[0] = fmaxf(acc[0] + bb0.x, 0.f); v[1] = fmaxf(acc[1] + bb0.y, 0.f);
    v[2] = fmaxf(acc[2] + bb0.z, 0.f); v[3] = fmaxf(acc[3] + bb0.w, 0.f);
    v[4] = fmaxf(acc[4] + bb1.x, 0.f); v[5] = fmaxf(acc[5] + bb1.y, 0.f);
    v[6] = fmaxf(acc[6] + bb1.z, 0.f); v[7] = fmaxf(acc[7] + bb1.w, 0.f);
    if (outb) {
        uint4 o;
        o.x = packbf(v[0], v[1]); o.y = packbf(v[2], v[3]);
        o.z = packbf(v[4], v[5]); o.w = packbf(v[6], v[7]);
        ((uint4*)outb)[(size_t)node * 32 + lane] = o;
    }
    int base = batch[node] * HH + lane * 8;
    if (poolmax) {
#pragma unroll
        for (int j = 0; j < 8; j++) atomicMax(&poolmax[base + j], __float_as_int(v[j]));
    } else {
#pragma unroll
        for (int j = 0; j < 8; j++) atomicAdd(&poolsum[base + j], v[j]);
    }
}

// ---------------- bf16 tensor-core GEMM ----------------
// A: fp32 (AF32=1, converted at LDS) or bf16 row-major. B packed k2-interleaved u32[K/2][N].
// CTA tile 160x256xk32; 8 warps 2m x 4n; warp tile 80x64.
// ATOMIC=1: fp32 atomicAdd into C (split-K). ATOMIC=0: bf16 packed store into Cb.
template<int AF32, int ATOMIC>
__global__ __launch_bounds__(256)
void gemm_bf16(const void* __restrict__ Av, const uint32_t* __restrict__ Bp,
               float* __restrict__ C, uint16_t* __restrict__ Cb,
               int M, int N, int K, int KS) {
    constexpr int ABUFSZ = AF32 ? 23040 : 12800;   // bytes per buffer
    constexpr int BBUFSZ = 16896;
    extern __shared__ __align__(16) uint8_t smraw[];
    int tid = threadIdx.x;
    int lane = tid & 31, wid = tid >> 5;
    int warp_m = wid & 1, warp_n = wid >> 1;
    int bm = blockIdx.y * 160;
    int bn = blockIdx.x * 256;
    int kbeg = blockIdx.z * KS;
    int kend = min(K, kbeg + KS);
    int ntiles = (kend - kbeg + 31) >> 5;
    uint32_t sbase = (uint32_t)__cvta_generic_to_shared(smraw);

    float acc[5][8][4];
#pragma unroll
    for (int mt = 0; mt < 5; mt++)
#pragma unroll
        for (int nt = 0; nt < 8; nt++)
#pragma unroll
            for (int q = 0; q < 4; q++) acc[mt][nt][q] = 0.f;

    auto prefetch = [&](int tile, int pbuf) {
        int k0 = kbeg + tile * 32;
        if (AF32) {
            const float* A = (const float*)Av;
#pragma unroll
            for (int i = 0; i < 5; i++) {
                int c = tid + 256 * i;
                int row = c >> 3, ch = c & 7;
                bool ok = (bm + row < M) && (k0 + ch * 4 < kend);
                const void* src = A + (size_t)(bm + row) * K + k0 + ch * 4;
                cpasync16(sbase + pbuf * ABUFSZ + row * 144 + ch * 16, ok ? src : A, ok);
            }
        } else {
            const __nv_bfloat16* A = (const __nv_bfloat16*)Av;
#pragma unroll
            for (int i = 0; i < 3; i++) {
                int c = tid + 256 * i;
                if (c < 640) {
                    int row = c >> 2, ch = c & 3;
                    bool ok = (bm + row < M) && (k0 + ch * 8 < kend);
                    const void* src = A + (size_t)(bm + row) * K + k0 + ch * 8;
                    cpasync16(sbase + pbuf * ABUFSZ + row * 80 + ch * 16, ok ? src : A, ok);
                }
            }
        }
#pragma unroll
        for (int i = 0; i < 4; i++) {
            int c = tid + 256 * i;
            int row = c >> 6, seg = c & 63;
            bool ok = (k0 + 2 * row < kend);
            const void* src = Bp + (size_t)(k0 / 2 + row) * N + bn + seg * 4;
            cpasync16(sbase + 2 * ABUFSZ + pbuf * BBUFSZ + row * 1056 + seg * 16,
                      ok ? src : Bp, ok);
        }
        cpcommit();
    };

    int buf = 0;
    prefetch(0, 0);
    for (int t = 0; t < ntiles; t++) {
        cpwait0();
        __syncthreads();
        if (t + 1 < ntiles) prefetch(t + 1, buf ^ 1);

        const uint32_t* Bsb = (const uint32_t*)(smraw + 2 * ABUFSZ + buf * BBUFSZ);
#pragma unroll
        for (int ks = 0; ks < 2; ks++) {
            int kk0 = ks * 16 + 2 * (lane & 3);
            uint32_t af[5][4];
            if (AF32) {
                const float* Asf = (const float*)(smraw + buf * ABUFSZ);
#pragma unroll
                for (int mt = 0; mt < 5; mt++) {
                    int r = warp_m * 80 + mt * 16 + (lane >> 2);
                    float2 v0 = *(const float2*)(Asf + r * 36 + kk0);
                    float2 v1 = *(const float2*)(Asf + (r + 8) * 36 + kk0);
                    float2 v2 = *(const float2*)(Asf + r * 36 + kk0 + 8);
                    float2 v3 = *(const float2*)(Asf + (r + 8) * 36 + kk0 + 8);
                    af[mt][0] = packbf(v0.x, v0.y);
                    af[mt][1] = packbf(v1.x, v1.y);
                    af[mt][2] = packbf(v2.x, v2.y);
                    af[mt][3] = packbf(v3.x, v3.y);
                }
            } else {
                const uint16_t* Asb = (const uint16_t*)(smraw + buf * ABUFSZ);
#pragma unroll
                for (int mt = 0; mt < 5; mt++) {
                    int r = warp_m * 80 + mt * 16 + (lane >> 2);
                    af[mt][0] = *(const uint32_t*)(Asb + r * 40 + kk0);
                    af[mt][1] = *(const uint32_t*)(Asb + (r + 8) * 40 + kk0);
                    af[mt][2] = *(const uint32_t*)(Asb + r * 40 + kk0 + 8);
                    af[mt][3] = *(const uint32_t*)(Asb + (r + 8) * 40 + kk0 + 8);
                }
            }
            int p = ks * 8 + (lane & 3);
#pragma unroll
            for (int nt = 0; nt < 8; nt++) {
                int cl = warp_n * 64 + nt * 8 + (lane >> 2);
                uint32_t b0 = Bsb[p * 264 + cl];
                uint32_t b1 = Bsb[(p + 4) * 264 + cl];
#pragma unroll
                for (int mt = 0; mt < 5; mt++) {
                    asm volatile(
                        "mma.sync.aligned.m16n8k16.row.col.f32.bf16.bf16.f32 "
                        "{%0,%1,%2,%3}, {%4,%5,%6,%7}, {%8,%9}, {%0,%1,%2,%3};\n"
                        : "+f"(acc[mt][nt][0]), "+f"(acc[mt][nt][1]),
                          "+f"(acc[mt][nt][2]), "+f"(acc[mt][nt][3])
                        : "r"(af[mt][0]), "r"(af[mt][1]), "r"(af[mt][2]), "r"(af[mt][3]),
                          "r"(b0), "r"(b1));
                }
            }
        }
        buf ^= 1;
        __syncthreads();
    }

#pragma unroll
    for (int mt = 0; mt < 5; mt++) {
#pragma unroll
        for (int nt = 0; nt < 8; nt++) {
            int row = bm + warp_m * 80 + mt * 16 + (lane >> 2);
            int col = bn + warp_n * 64 + nt * 8 + 2 * (lane & 3);
            if (ATOMIC) {
                if (row < M) {
                    atomicAdd(&C[(size_t)row * N + col],     acc[mt][nt][0]);
                    atomicAdd(&C[(size_t)row * N + col + 1], acc[mt][nt][1]);
                }
                if (row + 8 < M) {
                    atomicAdd(&C[(size_t)(row + 8) * N + col],     acc[mt][nt][2]);
                    atomicAdd(&C[(size_t)(row + 8) * N + col + 1], acc[mt][nt][3]);
                }
            } else {
                uint32_t* Cb32 = (uint32_t*)Cb;
                if (row < M)
                    Cb32[((size_t)row * N + col) >> 1] = packbf(acc[mt][nt][0], acc[mt][nt][1]);
                if (row + 8 < M)
                    Cb32[((size_t)(row + 8) * N + col) >> 1] = packbf(acc[mt][nt][2], acc[mt][nt][3]);
            }
        }
    }
}

// ---------------- branch2 front ----------------
__global__ void meanraw_kernel(const float* __restrict__ dx) {
    int f = blockIdx.x * 256 + threadIdx.x;
    if (f >= RAWF) return;
    int b = blockIdx.y;
    int s = g_bounds[b], e = g_bounds[b + 1];
    float acc = 0.f;
    for (int i = s; i < e; i++) acc += dx[(size_t)i * RAWF + f];
    int cnt = e - s; if (cnt < 1) cnt = 1;
    g_newxinb[(size_t)b * (2 * RAWF) + f] = __float2bfloat16(acc / (float)cnt);
}
__global__ void root_kernel(const float* __restrict__ dx, const int* __restrict__ root) {
    int f = blockIdx.x * 256 + threadIdx.x;
    if (f >= RAWF) return;
    int b = blockIdx.y;
    g_newxinb[(size_t)b * (2 * RAWF) + RAWF + f] =
        __float2bfloat16(dx[(size_t)root[b] * RAWF + f]);
}

// ---------------- small elementwise ----------------
__global__ void init_bias_kernel(float* __restrict__ p, const float* __restrict__ bias,
                                 int n, int mask) {
    int i = blockIdx.x * blockDim.x + threadIdx.x;
    if (i < n) p[i] = bias[i & mask];
}
__global__ void prelu_kernel(float* __restrict__ p, int n, const float* __restrict__ pa,
                             __nv_bfloat16* __restrict__ outb) {
    int i = blockIdx.x * blockDim.x + threadIdx.x;
    if (i >= n) return;
    float a = *pa;
    float v = p[i];
    v = v >= 0.f ? v : a * v;
    if (outb) outb[i] = __float2bfloat16(v);
    else p[i] = v;
}

// ---------------- final projection + log_softmax ----------------
__global__ void final_kernel(const float* __restrict__ W5, const float* __restrict__ b5,
                             float* __restrict__ out) {
    __shared__ float red[4][256];
    int b = blockIdx.x, t = threadIdx.x;
    int cnt = g_bounds[b + 1] - g_bounds[b];
    float inv = 1.f / (float)(cnt < 1 ? 1 : cnt);
    float acc[4] = {0.f, 0.f, 0.f, 0.f};
    for (int k = t; k < 5 * HH; k += 256) {
        int seg = k >> 8, f = k & 255;
        float v;
        if      (seg == 0) v = g_p0[b * HH + f] * inv;
        else if (seg == 1) v = g_p1[b * HH + f] * inv;
        else if (seg == 2) v = g_p2[b * HH + f] * inv;
        else if (seg == 3) v = g_newx[b * HH + f];
        else               v = g_xmax[b * HH + f];
#pragma unroll
        for (int c = 0; c < 4; c++) acc[c] += v * W5[k * 4 + c];
    }
#pragma unroll
    for (int c = 0; c < 4; c++) red[c][t] = acc[c];
    __syncthreads();
    for (int s = 128; s > 0; s >>= 1) {
        if (t < s) {
#pragma unroll
            for (int c = 0; c < 4; c++) red[c][t] += red[c][t + s];
        }
        __syncthreads();
    }
    if (t == 0) {
        float z[4];
#pragma unroll
        for (int c = 0; c < 4; c++) z[c] = red[c][0] + b5[c];
        float m = z[0];
#pragma unroll
        for (int c = 1; c < 4; c++) m = fmaxf(m, z[c]);
        float ssum = 0.f;
#pragma unroll
        for (int c = 0; c < 4; c++) ssum += expf(z[c] - m);
        float ls = logf(ssum);
#pragma unroll
        for (int c = 0; c < 4; c++) out[b * 4 + c] = z[c] - m - ls;
    }
}

// ---------------- host ----------------
extern "C" void kernel_launch(void* const* d_in, const int* in_sizes, int n_in,
                              void* d_out, int out_size) {
    const float* graph_x = (const float*)d_in[0];
    const float* data_x  = (const float*)d_in[2];
    const int*   ei      = (const int*)d_in[3];
    const int*   rei     = (const int*)d_in[4];
    const int*   gbatch  = (const int*)d_in[5];
    const int*   root    = (const int*)d_in[7];
    const float* W1  = (const float*)d_in[8];
    const float* b1  = (const float*)d_in[9];
    const float* Wc0 = (const float*)d_in[10];
    const float* bc0 = (const float*)d_in[11];
    const float* Wc1 = (const float*)d_in[12];
    const float* bc1 = (const float*)d_in[13];
    const float* Wc2 = (const float*)d_in[14];
    const float* bc2 = (const float*)d_in[15];
    const float* Wl1 = (const float*)d_in[16];
    const float* bl1 = (const float*)d_in[17];
    const float* Wl2 = (const float*)d_in[18];
    const float* bl2 = (const float*)d_in[19];
    const float* pa  = (const float*)d_in[20];
    const float* W5  = (const float*)d_in[21];
    const float* b5  = (const float*)d_in[22];
    float* out = (float*)d_out;

    static bool s_init = false;
    static cudaStream_t s1, s2;
    static cudaEvent_t evStart, evBounds, evCSR2, evB1, evB2;
    if (!s_init) {
        cudaStreamCreateWithFlags(&s1, cudaStreamNonBlocking);
        cudaStreamCreateWithFlags(&s2, cudaStreamNonBlocking);
        cudaEventCreateWithFlags(&evStart,  cudaEventDisableTiming);
        cudaEventCreateWithFlags(&evBounds, cudaEventDisableTiming);
        cudaEventCreateWithFlags(&evCSR2,   cudaEventDisableTiming);
        cudaEventCreateWithFlags(&evB1,     cudaEventDisableTiming);
        cudaEventCreateWithFlags(&evB2,     cudaEventDisableTiming);
        cudaFuncSetAttribute(gemm_bf16<1, 0>, cudaFuncAttributeMaxDynamicSharedMemorySize, 79872);
        cudaFuncSetAttribute(gemm_bf16<0, 0>, cudaFuncAttributeMaxDynamicSharedMemorySize, 59392);
        cudaFuncSetAttribute(gemm_bf16<0, 1>, cudaFuncAttributeMaxDynamicSharedMemorySize, 59392);
        s_init = true;
    }

    __nv_bfloat16 *phb, *phb0, *paggb, *pl1b, *pnewxinb;
    float *pl1, *pnewx, *pxmax, *pp0, *pp1, *pp2;
    int *prs0, *prs1, *psrc0, *psrc1;
    float *pdinv0, *pdinv1;
    uint32_t *pwp;
    cudaGetSymbolAddress((void**)&phb,      g_hb);
    cudaGetSymbolAddress((void**)&phb0,     g_hb0);
    cudaGetSymbolAddress((void**)&paggb,    g_aggb);
    cudaGetSymbolAddress((void**)&pl1,      g_l1);
    cudaGetSymbolAddress((void**)&pl1b,     g_l1b);
    cudaGetSymbolAddress((void**)&pnewx,    g_newx);
    cudaGetSymbolAddress((void**)&pxmax,    g_xmax);
    cudaGetSymbolAddress((void**)&pp0,      g_p0);
    cudaGetSymbolAddress((void**)&pp1,      g_p1);
    cudaGetSymbolAddress((void**)&pp2,      g_p2);
    cudaGetSymbolAddress((void**)&pnewxinb, g_newxinb);
    cudaGetSymbolAddress((void**)&prs0,     g_rs0);
    cudaGetSymbolAddress((void**)&prs1,     g_rs1);
    cudaGetSymbolAddress((void**)&psrc0,    g_src0);
    cudaGetSymbolAddress((void**)&psrc1,    g_src1);
    cudaGetSymbolAddress((void**)&pdinv0,   g_dinv0);
    cudaGetSymbolAddress((void**)&pdinv1,   g_dinv1);
    cudaGetSymbolAddress((void**)&pwp,      g_wp);

    dim3 nodeGrid(1, (NN + 159) / 160, 1);   // 125 CTAs
    const int NB = (NN + 255) / 256, EB = (EE + 255) / 256;
    dim3 rawGrid((RAWF + 255) / 256, BB);

    cudaEventRecord(evStart, 0);
    cudaStreamWaitEvent(s1, evStart, 0);
    cudaStreamWaitEvent(s2, evStart, 0);

    // ===== stream s1: bounds, pools-zero, both CSRs, branch 1 =====
    bounds_kernel<<<1, 160, 0, s1>>>(gbatch);
    cudaEventRecord(evBounds, s1);
    zero_pools_kernel<<<(BB * HH + 255) / 256, 256, 0, s1>>>();
    // CSR for branch1 graph (ei)
    zero_cnt_kernel<<<NB, 256, 0, s1>>>();
    hist_kernel<<<EB, 256, 0, s1>>>(ei + EE);
    scan_kernel<<<1, 1024, 0, s1>>>(prs0, pdinv0);
    cursor_kernel<<<NB, 256, 0, s1>>>(prs0);
    fill_kernel<<<EB, 256, 0, s1>>>(ei, ei + EE, psrc0);
    // CSR for branch3 graph (rei)
    zero_cnt_kernel<<<NB, 256, 0, s1>>>();
    hist_kernel<<<EB, 256, 0, s1>>>(rei + EE);
    scan_kernel<<<1, 1024, 0, s1>>>(prs1, pdinv1);
    cursor_kernel<<<NB, 256, 0, s1>>>(prs1);
    fill_kernel<<<EB, 256, 0, s1>>>(rei, rei + EE, psrc1);
    cudaEventRecord(evCSR2, s1);
    // branch 1
    prep_w_kernel<<<((FIN / 2) * HH + 255) / 256, 256, 0, s1>>>(W1, pwp + OFF_W1, (FIN / 2) * HH, HH);
    gemm_bf16<1, 0><<<nodeGrid, 256, 79872, s1>>>(graph_x, pwp + OFF_W1, nullptr,
                                                  (uint16_t*)phb0, NN, HH, FIN, FIN);
    gather_kernel<<<NN / 8, 256, 0, s1>>>((const uint4*)phb0, b1, prs0, psrc0, pdinv0,
                                          gbatch, nullptr, nullptr, (int*)pxmax);
    cudaEventRecord(evB1, s1);

    // ===== stream s2: branch 2 =====
    cudaStreamWaitEvent(s2, evBounds, 0);
    prep_w_kernel<<<(RAWF * 512 + 255) / 256, 256, 0, s2>>>(Wl1, pwp + OFF_WL1, RAWF * 512, 512);
    prep_w_kernel<<<(256 * HH + 255) / 256, 256, 0, s2>>>(Wl2, pwp + OFF_WL2, 256 * HH, HH);
    meanraw_kernel<<<rawGrid, 256, 0, s2>>>(data_x);
    root_kernel<<<rawGrid, 256, 0, s2>>>(data_x, root);
    init_bias_kernel<<<(BB * 512 + 255) / 256, 256, 0, s2>>>(pl1, bl1, BB * 512, 511);
    gemm_bf16<0, 1><<<dim3(2, 1, 63), 256, 59392, s2>>>(pnewxinb, pwp + OFF_WL1, pl1,
                                                        nullptr, BB, 512, 2 * RAWF, 160);
    prelu_kernel<<<(BB * 512 + 255) / 256, 256, 0, s2>>>(pl1, BB * 512, pa, pl1b);
    init_bias_kernel<<<(BB * 256 + 255) / 256, 256, 0, s2>>>(pnewx, bl2, BB * 256, 255);
    gemm_bf16<0, 1><<<dim3(1, 1, 8), 256, 59392, s2>>>(pl1b, pwp + OFF_WL2, pnewx,
                                                       nullptr, BB, HH, 512, 64);
    prelu_kernel<<<(BB * 256 + 255) / 256, 256, 0, s2>>>(pnewx, BB * 256, pa, nullptr);
    cudaEventRecord(evB2, s2);

    // ===== stream 0 (critical path): branch 3 =====
    prep_w_kernel<<<((RAWF / 2) * HH + 255) / 256, 256>>>(Wc0, pwp + OFF_WC0, (RAWF / 2) * HH, HH);
    prep_w_kernel<<<((HH / 2) * HH + 255) / 256, 256>>>(Wc1, pwp + OFF_WC1, (HH / 2) * HH, HH);
    prep_w_kernel<<<((HH / 2) * HH + 255) / 256, 256>>>(Wc2, pwp + OFF_WC2, (HH / 2) * HH, HH);
    gemm_bf16<1, 0><<<nodeGrid, 256, 79872>>>(data_x, pwp + OFF_WC0, nullptr,
                                              (uint16_t*)phb, NN, HH, RAWF, RAWF);
    cudaStreamWaitEvent(0, evCSR2, 0);
    gather_kernel<<<NN / 8, 256>>>((const uint4*)phb, bc0, prs1, psrc1, pdinv1,
                                   gbatch, paggb, pp0, nullptr);
    gemm_bf16<0, 0><<<nodeGrid, 256, 59392>>>(paggb, pwp + OFF_WC1, nullptr,
                                              (uint16_t*)phb, NN, HH, HH, HH);
    gather_kernel<<<NN / 8, 256>>>((const uint4*)phb, bc1, prs1, psrc1, pdinv1,
                                   gbatch, paggb, pp1, nullptr);
    gemm_bf16<0, 0><<<nodeGrid, 256, 59392>>>(paggb, pwp + OFF_WC2, nullptr,
                                              (uint16_t*)phb, NN, HH, HH, HH);
    gather_kernel<<<NN / 8, 256>>>((const uint4*)phb, bc2, prs1, psrc1, pdinv1,
                                   gbatch, nullptr, pp2, nullptr);
    cudaStreamWaitEvent(0, evB1, 0);
    cudaStreamWaitEvent(0, evB2, 0);
    final_kernel<<<BB, 256>>>(W5, b5, out);
}

// round 6
// speedup vs baseline: 1.0969x; 1.0969x over previous
#include <cuda_runtime.h>
#include <cuda_bf16.h>
#include <cstdint>

#define NN   20000
#define BB   128
#define EE   320000
#define FIN  768
#define RAWF 5000
#define HH   256
#define CC   4

// ---------------- scratch (device globals) ----------------
__device__ __align__(16) __nv_bfloat16 g_hb[NN * HH];    // h (bf16)
__device__ __align__(16) __nv_bfloat16 g_aggb[NN * HH];  // activation (bf16)
__device__ __align__(16) float g_l1[BB * 512];
__device__ __align__(16) __nv_bfloat16 g_l1b[BB * 512];
__device__ __align__(16) float g_newx[BB * HH];
__device__ __align__(16) float g_xmax[BB * HH];
__device__ __align__(16) float g_p0[BB * HH];
__device__ __align__(16) float g_p1[BB * HH];
__device__ __align__(16) float g_p2[BB * HH];
__device__ __align__(16) __nv_bfloat16 g_newxinb[BB * 2 * RAWF];
// packed k2-interleaved bf16 weights
#define OFF_W1   0
#define OFF_WC0  98304
#define OFF_WC1  738304
#define OFF_WC2  771072
#define OFF_WL1  803840
#define OFF_WL2  3363840
__device__ __align__(16) uint32_t g_wp[3429376];
__device__ __align__(16) int   g_cnt[NN];
__device__ int   g_cursor[NN];
__device__ __align__(16) int   g_rs0[NN + 4];
__device__ __align__(16) int   g_rs1[NN + 4];
__device__ int   g_src0[EE];
__device__ int   g_src1[EE];
__device__ __align__(16) float g_dinv0[NN];
__device__ __align__(16) float g_dinv1[NN];
__device__ int   g_bounds[BB + 1];

// ---------------- helpers ----------------
__device__ __forceinline__ uint32_t packbf(float lo, float hi) {
    uint32_t r;
    asm("cvt.rn.bf16x2.f32 %0, %1, %2;" : "=r"(r) : "f"(hi), "f"(lo));
    return r;
}
__device__ __forceinline__ void cpasync16(uint32_t dst, const void* src, bool ok) {
    int ss = ok ? 16 : 0;
    asm volatile("cp.async.cg.shared.global [%0], [%1], 16, %2;\n" :: "r"(dst), "l"(src), "r"(ss));
}
__device__ __forceinline__ void cpcommit() { asm volatile("cp.async.commit_group;\n"); }
__device__ __forceinline__ void cpwait0()  { asm volatile("cp.async.wait_group 0;\n"); }
__device__ __forceinline__ void unp(uint32_t w, float& a, float& b) {
    a = __uint_as_float(w << 16);
    b = __uint_as_float(w & 0xffff0000u);
}

// ---------------- segment bounds ----------------
__global__ void bounds_kernel(const int* __restrict__ batch) {
    int b = threadIdx.x;
    if (b > BB) return;
    int lo = 0, hi = NN;
    while (lo < hi) {
        int mid = (lo + hi) >> 1;
        if (batch[mid] < b) lo = mid + 1; else hi = mid;
    }
    g_bounds[b] = lo;
}

// ---------------- weight prep ----------------
__global__ void prep_w_kernel(const float* __restrict__ W, uint32_t* __restrict__ Wp,
                              int cnt, int N) {
    int idx = blockIdx.x * blockDim.x + threadIdx.x;
    if (idx >= cnt) return;
    int p = idx / N, n = idx - p * N;
    Wp[idx] = packbf(W[(size_t)(2 * p) * N + n], W[(size_t)(2 * p + 1) * N + n]);
}

// ---------------- zeroing (pools + cnt in one pass) ----------------
__global__ void zero_all_kernel() {
    int i = blockIdx.x * blockDim.x + threadIdx.x;
    if (i < BB * HH) { g_xmax[i] = 0.f; g_p0[i] = 0.f; g_p1[i] = 0.f; g_p2[i] = 0.f; }
    if (i < NN) g_cnt[i] = 0;
}
__global__ void zero_cnt_kernel() {
    int i = blockIdx.x * blockDim.x + threadIdx.x;
    if (i < NN) g_cnt[i] = 0;
}

// ---------------- CSR build ----------------
__global__ void hist_kernel(const int* __restrict__ dst) {
    int i = blockIdx.x * blockDim.x + threadIdx.x;
    if (i >= EE / 4) return;
    int4 d = ((const int4*)dst)[i];
    atomicAdd(&g_cnt[d.x], 1);
    atomicAdd(&g_cnt[d.y], 1);
    atomicAdd(&g_cnt[d.z], 1);
    atomicAdd(&g_cnt[d.w], 1);
}
__global__ void scan_kernel(int* __restrict__ rs, float* __restrict__ dinv) {
    __shared__ int wsum[32];
    int t = threadIdx.x;
    int lane = t & 31, wid = t >> 5;
    int c[20];
    const int4* c4 = (const int4*)g_cnt;
#pragma unroll
    for (int i = 0; i < 5; i++) {
        int idx4 = t * 5 + i;
        int4 v = (idx4 < 5000) ? c4[idx4] : make_int4(0, 0, 0, 0);
        c[i * 4 + 0] = v.x; c[i * 4 + 1] = v.y; c[i * 4 + 2] = v.z; c[i * 4 + 3] = v.w;
    }
    int loc[20];
    int s = 0;
#pragma unroll
    for (int i = 0; i < 20; i++) { loc[i] = s; s += c[i]; }
    int x = s;
#pragma unroll
    for (int off = 1; off < 32; off <<= 1) {
        int y = __shfl_up_sync(0xffffffffu, x, off);
        if (lane >= off) x += y;
    }
    if (lane == 31) wsum[wid] = x;
    __syncthreads();
    if (wid == 0) {
        int v = wsum[lane];
#pragma unroll
        for (int off = 1; off < 32; off <<= 1) {
            int y = __shfl_up_sync(0xffffffffu, v, off);
            if (lane >= off) v += y;
        }
        wsum[lane] = v;
    }
    __syncthreads();
    int offset = (wid ? wsum[wid - 1] : 0) + (x - s);
    int4* rs4 = (int4*)rs;
    float4* dv4 = (float4*)dinv;
#pragma unroll
    for (int i = 0; i < 5; i++) {
        int idx4 = t * 5 + i;
        if (idx4 < 5000) {
            int4 r; float4 d;
            r.x = offset + loc[i * 4 + 0]; d.x = rsqrtf((float)(c[i * 4 + 0] + 1));
            r.y = offset + loc[i * 4 + 1]; d.y = rsqrtf((float)(c[i * 4 + 1] + 1));
            r.z = offset + loc[i * 4 + 2]; d.z = rsqrtf((float)(c[i * 4 + 2] + 1));
            r.w = offset + loc[i * 4 + 3]; d.w = rsqrtf((float)(c[i * 4 + 3] + 1));
            rs4[idx4] = r; dv4[idx4] = d;
        }
    }
    if (t == 0) rs[NN] = EE;
}
__global__ void cursor_kernel(const int* __restrict__ rs) {
    int i = blockIdx.x * blockDim.x + threadIdx.x;
    if (i < NN) g_cursor[i] = rs[i];
}
__global__ void fill_kernel(const int* __restrict__ src, const int* __restrict__ dst,
                            int* __restrict__ out) {
    int i = blockIdx.x * blockDim.x + threadIdx.x;
    if (i >= EE / 4) return;
    int4 d = ((const int4*)dst)[i];
    int4 s = ((const int4*)src)[i];
    out[atomicAdd(&g_cursor[d.x], 1)] = s.x;
    out[atomicAdd(&g_cursor[d.y], 1)] = s.y;
    out[atomicAdd(&g_cursor[d.z], 1)] = s.z;
    out[atomicAdd(&g_cursor[d.w], 1)] = s.w;
}

// ---------------- fused GCN aggregation + relu + pool ----------------
__global__ __launch_bounds__(256)
void gather_kernel(const uint4* __restrict__ hb, const float* __restrict__ bias,
                   const int* __restrict__ rs, const int* __restrict__ csr,
                   const float* __restrict__ dinv, const int* __restrict__ batch,
                   __nv_bfloat16* __restrict__ outb, float* __restrict__ poolsum,
                   int* __restrict__ poolmax) {
    int node = blockIdx.x * 8 + (threadIdx.x >> 5);
    int lane = threadIdx.x & 31;
    float di = dinv[node];
    float sw = di * di;
    float acc[8];
    {
        uint4 hv = hb[(size_t)node * 32 + lane];
        float f0, f1;
        unp(hv.x, f0, f1); acc[0] = f0 * sw; acc[1] = f1 * sw;
        unp(hv.y, f0, f1); acc[2] = f0 * sw; acc[3] = f1 * sw;
        unp(hv.z, f0, f1); acc[4] = f0 * sw; acc[5] = f1 * sw;
        unp(hv.w, f0, f1); acc[6] = f0 * sw; acc[7] = f1 * sw;
    }
    int e0 = rs[node], e1 = rs[node + 1];
    for (int e = e0; e < e1; e++) {
        int s = csr[e];
        float w = dinv[s] * di;
        uint4 hv = hb[(size_t)s * 32 + lane];
        float f0, f1;
        unp(hv.x, f0, f1); acc[0] = fmaf(f0, w, acc[0]); acc[1] = fmaf(f1, w, acc[1]);
        unp(hv.y, f0, f1); acc[2] = fmaf(f0, w, acc[2]); acc[3] = fmaf(f1, w, acc[3]);
        unp(hv.z, f0, f1); acc[4] = fmaf(f0, w, acc[4]); acc[5] = fmaf(f1, w, acc[5]);
        unp(hv.w, f0, f1); acc[6] = fmaf(f0, w, acc[6]); acc[7] = fmaf(f1, w, acc[7]);
    }
    float4 bb0 = ((const float4*)bias)[2 * lane];
    float4 bb1 = ((const float4*)bias)[2 * lane + 1];
    float v[8];
    v[0] = fmaxf(acc[0] + bb0.x, 0.f); v[1] = fmaxf(acc[1] + bb0.y, 0.f);
    v[2] = fmaxf(acc[2] + bb0.z, 0.f); v[3] = fmaxf(acc[3] + bb0.w, 0.f);
    v[4] = fmaxf(acc[4] + bb1.x, 0.f); v[5] = fmaxf(acc[5] + bb1.y, 0.f);
    v[6] = fmaxf(acc[6] + bb1.z, 0.f); v[7] = fmaxf(acc[7] + bb1.w, 0.f);
    if (outb) {
        uint4 o;
        o.x = packbf(v[0], v[1]); o.y = packbf(v[2], v[3]);
        o.z = packbf(v[4], v[5]); o.w = packbf(v[6], v[7]);
        ((uint4*)outb)[(size_t)node * 32 + lane] = o;
    }
    int base = batch[node] * HH + lane * 8;
    if (poolmax) {
#pragma unroll
        for (int j = 0; j < 8; j++) atomicMax(&poolmax[base + j], __float_as_int(v[j]));
    } else {
#pragma unroll
        for (int j = 0; j < 8; j++) atomicAdd(&poolsum[base + j], v[j]);
    }
}

// ---------------- bf16 tensor-core GEMM ----------------
// A: fp32 (AF32=1, converted at LDS) or bf16 row-major. B packed k2-interleaved u32[K/2][N].
// CTA tile 160x256xk32; 8 warps 2m x 4n; warp tile 80x64.
// ATOMIC=1: fp32 atomicAdd into C (split-K). ATOMIC=0: bf16 packed store into Cb.
template<int AF32, int ATOMIC>
__global__ __launch_bounds__(256)
void gemm_bf16(const void* __restrict__ Av, const uint32_t* __restrict__ Bp,
               float* __restrict__ C, uint16_t* __restrict__ Cb,
               int M, int N, int K, int KS) {
    constexpr int ABUFSZ = AF32 ? 23040 : 12800;   // bytes per buffer
    constexpr int BBUFSZ = 16896;
    extern __shared__ __align__(16) uint8_t smraw[];
    int tid = threadIdx.x;
    int lane = tid & 31, wid = tid >> 5;
    int warp_m = wid & 1, warp_n = wid >> 1;
    int bm = blockIdx.y * 160;
    int bn = blockIdx.x * 256;
    int kbeg = blockIdx.z * KS;
    int kend = min(K, kbeg + KS);
    int ntiles = (kend - kbeg + 31) >> 5;
    uint32_t sbase = (uint32_t)__cvta_generic_to_shared(smraw);

    float acc[5][8][4];
#pragma unroll
    for (int mt = 0; mt < 5; mt++)
#pragma unroll
        for (int nt = 0; nt < 8; nt++)
#pragma unroll
            for (int q = 0; q < 4; q++) acc[mt][nt][q] = 0.f;

    auto prefetch = [&](int tile, int pbuf) {
        int k0 = kbeg + tile * 32;
        if (AF32) {
            const float* A = (const float*)Av;
#pragma unroll
            for (int i = 0; i < 5; i++) {
                int c = tid + 256 * i;
                int row = c >> 3, ch = c & 7;
                bool ok = (bm + row < M) && (k0 + ch * 4 < kend);
                const void* src = A + (size_t)(bm + row) * K + k0 + ch * 4;
                cpasync16(sbase + pbuf * ABUFSZ + row * 144 + ch * 16, ok ? src : A, ok);
            }
        } else {
            const __nv_bfloat16* A = (const __nv_bfloat16*)Av;
#pragma unroll
            for (int i = 0; i < 3; i++) {
                int c = tid + 256 * i;
                if (c < 640) {
                    int row = c >> 2, ch = c & 3;
                    bool ok = (bm + row < M) && (k0 + ch * 8 < kend);
                    const void* src = A + (size_t)(bm + row) * K + k0 + ch * 8;
                    cpasync16(sbase + pbuf * ABUFSZ + row * 80 + ch * 16, ok ? src : A, ok);
                }
            }
        }
#pragma unroll
        for (int i = 0; i < 4; i++) {
            int c = tid + 256 * i;
            int row = c >> 6, seg = c & 63;
            bool ok = (k0 + 2 * row < kend);
            const void* src = Bp + (size_t)(k0 / 2 + row) * N + bn + seg * 4;
            cpasync16(sbase + 2 * ABUFSZ + pbuf * BBUFSZ + row * 1056 + seg * 16,
                      ok ? src : Bp, ok);
        }
        cpcommit();
    };

    int buf = 0;
    prefetch(0, 0);
    for (int t = 0; t < ntiles; t++) {
        cpwait0();
        __syncthreads();
        if (t + 1 < ntiles) prefetch(t + 1, buf ^ 1);

        const uint32_t* Bsb = (const uint32_t*)(smraw + 2 * ABUFSZ + buf * BBUFSZ);
#pragma unroll
        for (int ks = 0; ks < 2; ks++) {
            int kk0 = ks * 16 + 2 * (lane & 3);
            uint32_t af[5][4];
            if (AF32) {
                const float* Asf = (const float*)(smraw + buf * ABUFSZ);
#pragma unroll
                for (int mt = 0; mt < 5; mt++) {
                    int r = warp_m * 80 + mt * 16 + (lane >> 2);
                    float2 v0 = *(const float2*)(Asf + r * 36 + kk0);
                    float2 v1 = *(const float2*)(Asf + (r + 8) * 36 + kk0);
                    float2 v2 = *(const float2*)(Asf + r * 36 + kk0 + 8);
                    float2 v3 = *(const float2*)(Asf + (r + 8) * 36 + kk0 + 8);
                    af[mt][0] = packbf(v0.x, v0.y);
                    af[mt][1] = packbf(v1.x, v1.y);
                    af[mt][2] = packbf(v2.x, v2.y);
                    af[mt][3] = packbf(v3.x, v3.y);
                }
            } else {
                const uint16_t* Asb = (const uint16_t*)(smraw + buf * ABUFSZ);
#pragma unroll
                for (int mt = 0; mt < 5; mt++) {
                    int r = warp_m * 80 + mt * 16 + (lane >> 2);
                    af[mt][0] = *(const uint32_t*)(Asb + r * 40 + kk0);
                    af[mt][1] = *(const uint32_t*)(Asb + (r + 8) * 40 + kk0);
                    af[mt][2] = *(const uint32_t*)(Asb + r * 40 + kk0 + 8);
                    af[mt][3] = *(const uint32_t*)(Asb + (r + 8) * 40 + kk0 + 8);
                }
            }
            int p = ks * 8 + (lane & 3);
#pragma unroll
            for (int nt = 0; nt < 8; nt++) {
                int cl = warp_n * 64 + nt * 8 + (lane >> 2);
                uint32_t b0 = Bsb[p * 264 + cl];
                uint32_t b1 = Bsb[(p + 4) * 264 + cl];
#pragma unroll
                for (int mt = 0; mt < 5; mt++) {
                    asm volatile(
                        "mma.sync.aligned.m16n8k16.row.col.f32.bf16.bf16.f32 "
                        "{%0,%1,%2,%3}, {%4,%5,%6,%7}, {%8,%9}, {%0,%1,%2,%3};\n"
                        : "+f"(acc[mt][nt][0]), "+f"(acc[mt][nt][1]),
                          "+f"(acc[mt][nt][2]), "+f"(acc[mt][nt][3])
                        : "r"(af[mt][0]), "r"(af[mt][1]), "r"(af[mt][2]), "r"(af[mt][3]),
                          "r"(b0), "r"(b1));
                }
            }
        }
        buf ^= 1;
        __syncthreads();
    }

#pragma unroll
    for (int mt = 0; mt < 5; mt++) {
#pragma unroll
        for (int nt = 0; nt < 8; nt++) {
            int row = bm + warp_m * 80 + mt * 16 + (lane >> 2);
            int col = bn + warp_n * 64 + nt * 8 + 2 * (lane & 3);
            if (ATOMIC) {
                if (row < M) {
                    atomicAdd(&C[(size_t)row * N + col],     acc[mt][nt][0]);
                    atomicAdd(&C[(size_t)row * N + col + 1], acc[mt][nt][1]);
                }
                if (row + 8 < M) {
                    atomicAdd(&C[(size_t)(row + 8) * N + col],     acc[mt][nt][2]);
                    atomicAdd(&C[(size_t)(row + 8) * N + col + 1], acc[mt][nt][3]);
                }
            } else {
                uint32_t* Cb32 = (uint32_t*)Cb;
                if (row < M)
                    Cb32[((size_t)row * N + col) >> 1] = packbf(acc[mt][nt][0], acc[mt][nt][1]);
                if (row + 8 < M)
                    Cb32[((size_t)(row + 8) * N + col) >> 1] = packbf(acc[mt][nt][2], acc[mt][nt][3]);
            }
        }
    }
}

// ---------------- branch2 front ----------------
__global__ void meanraw_kernel(const float* __restrict__ dx) {
    int f = blockIdx.x * 256 + threadIdx.x;
    if (f >= RAWF) return;
    int b = blockIdx.y;
    int s = g_bounds[b], e = g_bounds[b + 1];
    float acc = 0.f;
    for (int i = s; i < e; i++) acc += dx[(size_t)i * RAWF + f];
    int cnt = e - s; if (cnt < 1) cnt = 1;
    g_newxinb[(size_t)b * (2 * RAWF) + f] = __float2bfloat16(acc / (float)cnt);
}
__global__ void root_kernel(const float* __restrict__ dx, const int* __restrict__ root) {
    int f = blockIdx.x * 256 + threadIdx.x;
    if (f >= RAWF) return;
    int b = blockIdx.y;
    g_newxinb[(size_t)b * (2 * RAWF) + RAWF + f] =
        __float2bfloat16(dx[(size_t)root[b] * RAWF + f]);
}

// ---------------- small elementwise ----------------
__global__ void init_bias_kernel(float* __restrict__ p, const float* __restrict__ bias,
                                 int n, int mask) {
    int i = blockIdx.x * blockDim.x + threadIdx.x;
    if (i < n) p[i] = bias[i & mask];
}
__global__ void prelu_kernel(float* __restrict__ p, int n, const float* __restrict__ pa,
                             __nv_bfloat16* __restrict__ outb) {
    int i = blockIdx.x * blockDim.x + threadIdx.x;
    if (i >= n) return;
    float a = *pa;
    float v = p[i];
    v = v >= 0.f ? v : a * v;
    if (outb) outb[i] = __float2bfloat16(v);
    else p[i] = v;
}

// ---------------- final projection + log_softmax ----------------
__global__ void final_kernel(const float* __restrict__ W5, const float* __restrict__ b5,
                             float* __restrict__ out) {
    __shared__ float red[4][256];
    int b = blockIdx.x, t = threadIdx.x;
    int cnt = g_bounds[b + 1] - g_bounds[b];
    float inv = 1.f / (float)(cnt < 1 ? 1 : cnt);
    float acc[4] = {0.f, 0.f, 0.f, 0.f};
    for (int k = t; k < 5 * HH; k += 256) {
        int seg = k >> 8, f = k & 255;
        float v;
        if      (seg == 0) v = g_p0[b * HH + f] * inv;
        else if (seg == 1) v = g_p1[b * HH + f] * inv;
        else if (seg == 2) v = g_p2[b * HH + f] * inv;
        else if (seg == 3) v = g_newx[b * HH + f];
        else               v = g_xmax[b * HH + f];
#pragma unroll
        for (int c = 0; c < 4; c++) acc[c] += v * W5[k * 4 + c];
    }
#pragma unroll
    for (int c = 0; c < 4; c++) red[c][t] = acc[c];
    __syncthreads();
    for (int s = 128; s > 0; s >>= 1) {
        if (t < s) {
#pragma unroll
            for (int c = 0; c < 4; c++) red[c][t] += red[c][t + s];
        }
        __syncthreads();
    }
    if (t == 0) {
        float z[4];
#pragma unroll
        for (int c = 0; c < 4; c++) z[c] = red[c][0] + b5[c];
        float m = z[0];
#pragma unroll
        for (int c = 1; c < 4; c++) m = fmaxf(m, z[c]);
        float ssum = 0.f;
#pragma unroll
        for (int c = 0; c < 4; c++) ssum += expf(z[c] - m);
        float ls = logf(ssum);
#pragma unroll
        for (int c = 0; c < 4; c++) out[b * 4 + c] = z[c] - m - ls;
    }
}

// ---------------- host ----------------
extern "C" void kernel_launch(void* const* d_in, const int* in_sizes, int n_in,
                              void* d_out, int out_size) {
    const float* graph_x = (const float*)d_in[0];
    const float* data_x  = (const float*)d_in[2];
    const int*   ei      = (const int*)d_in[3];
    const int*   rei     = (const int*)d_in[4];
    const int*   gbatch  = (const int*)d_in[5];
    const int*   root    = (const int*)d_in[7];
    const float* W1  = (const float*)d_in[8];
    const float* b1  = (const float*)d_in[9];
    const float* Wc0 = (const float*)d_in[10];
    const float* bc0 = (const float*)d_in[11];
    const float* Wc1 = (const float*)d_in[12];
    const float* bc1 = (const float*)d_in[13];
    const float* Wc2 = (const float*)d_in[14];
    const float* bc2 = (const float*)d_in[15];
    const float* Wl1 = (const float*)d_in[16];
    const float* bl1 = (const float*)d_in[17];
    const float* Wl2 = (const float*)d_in[18];
    const float* bl2 = (const float*)d_in[19];
    const float* pa  = (const float*)d_in[20];
    const float* W5  = (const float*)d_in[21];
    const float* b5  = (const float*)d_in[22];
    float* out = (float*)d_out;

    static bool s_init = false;
    if (!s_init) {
        cudaFuncSetAttribute(gemm_bf16<1, 0>, cudaFuncAttributeMaxDynamicSharedMemorySize, 79872);
        cudaFuncSetAttribute(gemm_bf16<0, 0>, cudaFuncAttributeMaxDynamicSharedMemorySize, 59392);
        cudaFuncSetAttribute(gemm_bf16<0, 1>, cudaFuncAttributeMaxDynamicSharedMemorySize, 59392);
        s_init = true;
    }

    __nv_bfloat16 *phb, *paggb, *pl1b, *pnewxinb;
    float *pl1, *pnewx, *pxmax, *pp0, *pp1, *pp2;
    int *prs0, *prs1, *psrc0, *psrc1;
    float *pdinv0, *pdinv1;
    uint32_t *pwp;
    cudaGetSymbolAddress((void**)&phb,      g_hb);
    cudaGetSymbolAddress((void**)&paggb,    g_aggb);
    cudaGetSymbolAddress((void**)&pl1,      g_l1);
    cudaGetSymbolAddress((void**)&pl1b,     g_l1b);
    cudaGetSymbolAddress((void**)&pnewx,    g_newx);
    cudaGetSymbolAddress((void**)&pxmax,    g_xmax);
    cudaGetSymbolAddress((void**)&pp0,      g_p0);
    cudaGetSymbolAddress((void**)&pp1,      g_p1);
    cudaGetSymbolAddress((void**)&pp2,      g_p2);
    cudaGetSymbolAddress((void**)&pnewxinb, g_newxinb);
    cudaGetSymbolAddress((void**)&prs0,     g_rs0);
    cudaGetSymbolAddress((void**)&prs1,     g_rs1);
    cudaGetSymbolAddress((void**)&psrc0,    g_src0);
    cudaGetSymbolAddress((void**)&psrc1,    g_src1);
    cudaGetSymbolAddress((void**)&pdinv0,   g_dinv0);
    cudaGetSymbolAddress((void**)&pdinv1,   g_dinv1);
    cudaGetSymbolAddress((void**)&pwp,      g_wp);

    dim3 nodeGrid(1, (NN + 159) / 160, 1);   // 125 CTAs, one wave
    const int NB = (NN + 255) / 256, E4 = (EE / 4 + 255) / 256;
    dim3 rawGrid((RAWF + 255) / 256, BB);

    // ---- setup ----
    bounds_kernel<<<1, 160>>>(gbatch);
    zero_all_kernel<<<(BB * HH + 255) / 256, 256>>>();

    // CSR for branch1 graph (ei)
    hist_kernel<<<E4, 256>>>(ei + EE);
    scan_kernel<<<1, 1024>>>(prs0, pdinv0);
    cursor_kernel<<<NB, 256>>>(prs0);
    fill_kernel<<<E4, 256>>>(ei, ei + EE, psrc0);
    // CSR for branch3 graph (rei)
    zero_cnt_kernel<<<NB, 256>>>();
    hist_kernel<<<E4, 256>>>(rei + EE);
    scan_kernel<<<1, 1024>>>(prs1, pdinv1);
    cursor_kernel<<<NB, 256>>>(prs1);
    fill_kernel<<<E4, 256>>>(rei, rei + EE, psrc1);

    // weight prep
    prep_w_kernel<<<((FIN / 2) * HH + 255) / 256, 256>>>(W1,  pwp + OFF_W1,  (FIN / 2) * HH, HH);
    prep_w_kernel<<<((RAWF / 2) * HH + 255) / 256, 256>>>(Wc0, pwp + OFF_WC0, (RAWF / 2) * HH, HH);
    prep_w_kernel<<<((HH / 2) * HH + 255) / 256, 256>>>(Wc1, pwp + OFF_WC1, (HH / 2) * HH, HH);
    prep_w_kernel<<<((HH / 2) * HH + 255) / 256, 256>>>(Wc2, pwp + OFF_WC2, (HH / 2) * HH, HH);
    prep_w_kernel<<<(RAWF * 512 + 255) / 256, 256>>>(Wl1, pwp + OFF_WL1, RAWF * 512, 512);
    prep_w_kernel<<<(256 * HH + 255) / 256, 256>>>(Wl2, pwp + OFF_WL2, 256 * HH, HH);

    // ---------- branch 1 ----------
    gemm_bf16<1, 0><<<nodeGrid, 256, 79872>>>(graph_x, pwp + OFF_W1, nullptr,
                                              (uint16_t*)phb, NN, HH, FIN, FIN);
    gather_kernel<<<NN / 8, 256>>>((const uint4*)phb, b1, prs0, psrc0, pdinv0,
                                   gbatch, nullptr, nullptr, (int*)pxmax);

    // ---------- branch 2 ----------
    meanraw_kernel<<<rawGrid, 256>>>(data_x);
    root_kernel<<<rawGrid, 256>>>(data_x, root);
    init_bias_kernel<<<(BB * 512 + 255) / 256, 256>>>(pl1, bl1, BB * 512, 511);
    gemm_bf16<0, 1><<<dim3(2, 1, 63), 256, 59392>>>(pnewxinb, pwp + OFF_WL1, pl1,
                                                    nullptr, BB, 512, 2 * RAWF, 160);
    prelu_kernel<<<(BB * 512 + 255) / 256, 256>>>(pl1, BB * 512, pa, pl1b);
    init_bias_kernel<<<(BB * 256 + 255) / 256, 256>>>(pnewx, bl2, BB * 256, 255);
    gemm_bf16<0, 1><<<dim3(1, 1, 8), 256, 59392>>>(pl1b, pwp + OFF_WL2, pnewx,
                                                   nullptr, BB, HH, 512, 64);
    prelu_kernel<<<(BB * 256 + 255) / 256, 256>>>(pnewx, BB * 256, pa, nullptr);

    // ---------- branch 3 ----------
    gemm_bf16<1, 0><<<nodeGrid, 256, 79872>>>(data_x, pwp + OFF_WC0, nullptr,
                                              (uint16_t*)phb, NN, HH, RAWF, RAWF);
    gather_kernel<<<NN / 8, 256>>>((const uint4*)phb, bc0, prs1, psrc1, pdinv1,
                                   gbatch, paggb, pp0, nullptr);
    gemm_bf16<0, 0><<<nodeGrid, 256, 59392>>>(paggb, pwp + OFF_WC1, nullptr,
                                              (uint16_t*)phb, NN, HH, HH, HH);
    gather_kernel<<<NN / 8, 256>>>((const uint4*)phb, bc1, prs1, psrc1, pdinv1,
                                   gbatch, paggb, pp1, nullptr);
    gemm_bf16<0, 0><<<nodeGrid, 256, 59392>>>(paggb, pwp + OFF_WC2, nullptr,
                                              (uint16_t*)phb, NN, HH, HH, HH);
    gather_kernel<<<NN / 8, 256>>>((const uint4*)phb, bc2, prs1, psrc1, pdinv1,
                                   gbatch, nullptr, pp2, nullptr);

    // ---------- final ----------
    final_kernel<<<BB, 256>>>(W5, b5, out);
}

// round 9
// speedup vs baseline: 1.4447x; 1.3171x over previous
#include <cuda_runtime.h>
#include <cuda_bf16.h>
#include <cstdint>

#define NN   20000
#define BB   128
#define EE   320000
#define FIN  768
#define RAWF 5000
#define HH   256
#define CC   4

// ---------------- scratch (device globals) ----------------
__device__ __align__(16) __nv_bfloat16 g_hb[NN * HH];    // GEMM output h (bf16)
__device__ __align__(16) __nv_bfloat16 g_aggb[NN * HH];  // activation (bf16)
__device__ __align__(16) __nv_bfloat16 g_datab[(size_t)NN * RAWF]; // bf16 data_x
__device__ __align__(16) float g_l1[BB * 512];
__device__ __align__(16) __nv_bfloat16 g_l1b[BB * 512];
__device__ __align__(16) float g_newx[BB * HH];
__device__ __align__(16) float g_xmax[BB * HH];
__device__ __align__(16) float g_p0[BB * HH];
__device__ __align__(16) float g_p1[BB * HH];
__device__ __align__(16) float g_p2[BB * HH];
__device__ __align__(16) __nv_bfloat16 g_newxinb[BB * 2 * RAWF];
// packed k2-interleaved bf16 weights
#define OFF_W1   0
#define OFF_WC0  98304
#define OFF_WC1  738304
#define OFF_WC2  771072
#define OFF_WL1  803840
#define OFF_WL2  3363840
__device__ __align__(16) uint32_t g_wp[3429376];
__device__ __align__(16) int   g_cnt[NN];
__device__ int   g_cursor[NN];
__device__ __align__(16) int   g_rs0[NN + 4];
__device__ __align__(16) int   g_rs1[NN + 4];
__device__ int   g_src0[EE];
__device__ int   g_src1[EE];
__device__ __align__(16) float g_dinv0[NN];
__device__ __align__(16) float g_dinv1[NN];
__device__ int   g_bounds[BB + 1];

// ---------------- helpers ----------------
__device__ __forceinline__ uint32_t packbf(float lo, float hi) {
    uint32_t r;
    asm("cvt.rn.bf16x2.f32 %0, %1, %2;" : "=r"(r) : "f"(hi), "f"(lo));
    return r;
}
__device__ __forceinline__ void cpasync16(uint32_t dst, const void* src, bool ok) {
    int ss = ok ? 16 : 0;
    asm volatile("cp.async.cg.shared.global [%0], [%1], 16, %2;\n" :: "r"(dst), "l"(src), "r"(ss));
}
__device__ __forceinline__ void cpcommit() { asm volatile("cp.async.commit_group;\n"); }
__device__ __forceinline__ void cpwait0()  { asm volatile("cp.async.wait_group 0;\n"); }
__device__ __forceinline__ void unp(uint32_t w, float& a, float& b) {
    a = __uint_as_float(w << 16);
    b = __uint_as_float(w & 0xffff0000u);
}

// ---------------- segment bounds ----------------
__global__ void bounds_kernel(const int* __restrict__ batch) {
    int b = threadIdx.x;
    if (b > BB) return;
    int lo = 0, hi = NN;
    while (lo < hi) {
        int mid = (lo + hi) >> 1;
        if (batch[mid] < b) lo = mid + 1; else hi = mid;
    }
    g_bounds[b] = lo;
}

// ---------------- weight prep ----------------
__global__ void prep_w_kernel(const float* __restrict__ W, uint32_t* __restrict__ Wp,
                              int cnt, int N) {
    int idx = blockIdx.x * blockDim.x + threadIdx.x;
    if (idx >= cnt) return;
    int p = idx / N, n = idx - p * N;
    Wp[idx] = packbf(W[(size_t)(2 * p) * N + n], W[(size_t)(2 * p + 1) * N + n]);
}

__global__ void zero_cnt_kernel() {
    int i = blockIdx.x * blockDim.x + threadIdx.x;
    if (i < NN) g_cnt[i] = 0;
}

// ---------------- CSR build ----------------
__global__ void hist_kernel(const int* __restrict__ dst) {
    int i = blockIdx.x * blockDim.x + threadIdx.x;
    if (i >= EE / 4) return;
    int4 d = ((const int4*)dst)[i];
    atomicAdd(&g_cnt[d.x], 1);
    atomicAdd(&g_cnt[d.y], 1);
    atomicAdd(&g_cnt[d.z], 1);
    atomicAdd(&g_cnt[d.w], 1);
}
__global__ void scan_kernel(int* __restrict__ rs, float* __restrict__ dinv) {
    __shared__ int wsum[32];
    int t = threadIdx.x;
    int lane = t & 31, wid = t >> 5;
    int c[20];
    const int4* c4 = (const int4*)g_cnt;
#pragma unroll
    for (int i = 0; i < 5; i++) {
        int idx4 = t * 5 + i;
        int4 v = (idx4 < 5000) ? c4[idx4] : make_int4(0, 0, 0, 0);
        c[i * 4 + 0] = v.x; c[i * 4 + 1] = v.y; c[i * 4 + 2] = v.z; c[i * 4 + 3] = v.w;
    }
    int loc[20];
    int s = 0;
#pragma unroll
    for (int i = 0; i < 20; i++) { loc[i] = s; s += c[i]; }
    int x = s;
#pragma unroll
    for (int off = 1; off < 32; off <<= 1) {
        int y = __shfl_up_sync(0xffffffffu, x, off);
        if (lane >= off) x += y;
    }
    if (lane == 31) wsum[wid] = x;
    __syncthreads();
    if (wid == 0) {
        int v = wsum[lane];
#pragma unroll
        for (int off = 1; off < 32; off <<= 1) {
            int y = __shfl_up_sync(0xffffffffu, v, off);
            if (lane >= off) v += y;
        }
        wsum[lane] = v;
    }
    __syncthreads();
    int offset = (wid ? wsum[wid - 1] : 0) + (x - s);
    int4* rs4 = (int4*)rs;
    float4* dv4 = (float4*)dinv;
#pragma unroll
    for (int i = 0; i < 5; i++) {
        int idx4 = t * 5 + i;
        if (idx4 < 5000) {
            int4 r; float4 d;
            r.x = offset + loc[i * 4 + 0]; d.x = rsqrtf((float)(c[i * 4 + 0] + 1));
            r.y = offset + loc[i * 4 + 1]; d.y = rsqrtf((float)(c[i * 4 + 1] + 1));
            r.z = offset + loc[i * 4 + 2]; d.z = rsqrtf((float)(c[i * 4 + 2] + 1));
            r.w = offset + loc[i * 4 + 3]; d.w = rsqrtf((float)(c[i * 4 + 3] + 1));
            rs4[idx4] = r; dv4[idx4] = d;
        }
    }
    if (t == 0) rs[NN] = EE;
}
__global__ void cursor_kernel(const int* __restrict__ rs) {
    int i = blockIdx.x * blockDim.x + threadIdx.x;
    if (i < NN) g_cursor[i] = rs[i];
}
__global__ void fill_kernel(const int* __restrict__ src, const int* __restrict__ dst,
                            int* __restrict__ out) {
    int i = blockIdx.x * blockDim.x + threadIdx.x;
    if (i >= EE / 4) return;
    int4 d = ((const int4*)dst)[i];
    int4 s = ((const int4*)src)[i];
    out[atomicAdd(&g_cursor[d.x], 1)] = s.x;
    out[atomicAdd(&g_cursor[d.y], 1)] = s.y;
    out[atomicAdd(&g_cursor[d.z], 1)] = s.z;
    out[atomicAdd(&g_cursor[d.w], 1)] = s.w;
}

// ---------------- fused GCN aggregation + relu (bf16 in/out) ----------------
__global__ __launch_bounds__(256)
void gather_kernel(const uint4* __restrict__ hb, const float* __restrict__ bias,
                   const int* __restrict__ rs, const int* __restrict__ csr,
                   const float* __restrict__ dinv, __nv_bfloat16* __restrict__ outb) {
    int node = blockIdx.x * 8 + (threadIdx.x >> 5);
    int lane = threadIdx.x & 31;
    float di = dinv[node];
    float sw = di * di;
    float acc[8];
    {
        uint4 hv = hb[(size_t)node * 32 + lane];
        float f0, f1;
        unp(hv.x, f0, f1); acc[0] = f0 * sw; acc[1] = f1 * sw;
        unp(hv.y, f0, f1); acc[2] = f0 * sw; acc[3] = f1 * sw;
        unp(hv.z, f0, f1); acc[4] = f0 * sw; acc[5] = f1 * sw;
        unp(hv.w, f0, f1); acc[6] = f0 * sw; acc[7] = f1 * sw;
    }
    int e0 = rs[node], e1 = rs[node + 1];
    for (int e = e0; e < e1; e++) {
        int s = csr[e];
        float w = dinv[s] * di;
        uint4 hv = hb[(size_t)s * 32 + lane];
        float f0, f1;
        unp(hv.x, f0, f1); acc[0] = fmaf(f0, w, acc[0]); acc[1] = fmaf(f1, w, acc[1]);
        unp(hv.y, f0, f1); acc[2] = fmaf(f0, w, acc[2]); acc[3] = fmaf(f1, w, acc[3]);
        unp(hv.z, f0, f1); acc[4] = fmaf(f0, w, acc[4]); acc[5] = fmaf(f1, w, acc[5]);
        unp(hv.w, f0, f1); acc[6] = fmaf(f0, w, acc[6]); acc[7] = fmaf(f1, w, acc[7]);
    }
    float4 bb0 = ((const float4*)bias)[2 * lane];
    float4 bb1 = ((const float4*)bias)[2 * lane + 1];
    float v[8];
    v[0] = fmaxf(acc[0] + bb0.x, 0.f); v[1] = fmaxf(acc[1] + bb0.y, 0.f);
    v[2] = fmaxf(acc[2] + bb0.z, 0.f); v[3] = fmaxf(acc[3] + bb0.w, 0.f);
    v[4] = fmaxf(acc[4] + bb1.x, 0.f); v[5] = fmaxf(acc[5] + bb1.y, 0.f);
    v[6] = fmaxf(acc[6] + bb1.z, 0.f); v[7] = fmaxf(acc[7] + bb1.w, 0.f);
    uint4 o;
    o.x = packbf(v[0], v[1]); o.y = packbf(v[2], v[3]);
    o.z = packbf(v[4], v[5]); o.w = packbf(v[6], v[7]);
    ((uint4*)outb)[(size_t)node * 32 + lane] = o;
}

// ---------------- pooling over contiguous segments (bf16 input, no atomics) ----------------
// 1024 threads: 64 col-groups (uint2 = 4 cols) x 16 row partitions.
// ISMAX=1: max (inputs >= 0 after relu, identity 0 valid). ISMAX=0: sum (divided in final).
template<int ISMAX>
__global__ void pool_kernel(const uint2* __restrict__ xb, float* __restrict__ out) {
    __shared__ float red[16 * 256];
    int b = blockIdx.x, t = threadIdx.x;
    int q = t & 63;          // which uint2 (4 cols)
    int rp = t >> 6;         // 0..15 row partition
    int s = g_bounds[b], e = g_bounds[b + 1];
    float a0 = 0.f, a1 = 0.f, a2 = 0.f, a3 = 0.f;
    for (int i = s + rp; i < e; i += 16) {
        uint2 v = xb[(size_t)i * 64 + q];
        float f0, f1, f2, f3;
        unp(v.x, f0, f1); unp(v.y, f2, f3);
        if (ISMAX) {
            a0 = fmaxf(a0, f0); a1 = fmaxf(a1, f1);
            a2 = fmaxf(a2, f2); a3 = fmaxf(a3, f3);
        } else {
            a0 += f0; a1 += f1; a2 += f2; a3 += f3;
        }
    }
    red[rp * 256 + q * 4 + 0] = a0;
    red[rp * 256 + q * 4 + 1] = a1;
    red[rp * 256 + q * 4 + 2] = a2;
    red[rp * 256 + q * 4 + 3] = a3;
    __syncthreads();
    if (t < 256) {
        float r = red[t];
#pragma unroll
        for (int p = 1; p < 16; p++) {
            if (ISMAX) r = fmaxf(r, red[p * 256 + t]);
            else       r += red[p * 256 + t];
        }
        out[b * HH + t] = r;
    }
}

// ---------------- bf16 tensor-core GEMM ----------------
// A: fp32 (AF32=1, converted at LDS) or bf16 row-major. B packed k2-interleaved u32[K/2][N].
// CTA tile 160x256xk32; 8 warps 2m x 4n; warp tile 80x64.
// ATOMIC=1: fp32 atomicAdd into C (split-K). ATOMIC=0: bf16 packed store into Cb.
template<int AF32, int ATOMIC>
__global__ __launch_bounds__(256)
void gemm_bf16(const void* __restrict__ Av, const uint32_t* __restrict__ Bp,
               float* __restrict__ C, uint16_t* __restrict__ Cb,
               int M, int N, int K, int KS) {
    constexpr int ABUFSZ = AF32 ? 23040 : 12800;
    constexpr int BBUFSZ = 16896;
    extern __shared__ __align__(16) uint8_t smraw[];
    int tid = threadIdx.x;
    int lane = tid & 31, wid = tid >> 5;
    int warp_m = wid & 1, warp_n = wid >> 1;
    int bm = blockIdx.y * 160;
    int bn = blockIdx.x * 256;
    int kbeg = blockIdx.z * KS;
    int kend = min(K, kbeg + KS);
    int ntiles = (kend - kbeg + 31) >> 5;
    uint32_t sbase = (uint32_t)__cvta_generic_to_shared(smraw);

    float acc[5][8][4];
#pragma unroll
    for (int mt = 0; mt < 5; mt++)
#pragma unroll
        for (int nt = 0; nt < 8; nt++)
#pragma unroll
            for (int q = 0; q < 4; q++) acc[mt][nt][q] = 0.f;

    auto prefetch = [&](int tile, int pbuf) {
        int k0 = kbeg + tile * 32;
        if (AF32) {
            const float* A = (const float*)Av;
#pragma unroll
            for (int i = 0; i < 5; i++) {
                int c = tid + 256 * i;
                int row = c >> 3, ch = c & 7;
                bool ok = (bm + row < M) && (k0 + ch * 4 < kend);
                const void* src = A + (size_t)(bm + row) * K + k0 + ch * 4;
                cpasync16(sbase + pbuf * ABUFSZ + row * 144 + ch * 16, ok ? src : A, ok);
            }
        } else {
            const __nv_bfloat16* A = (const __nv_bfloat16*)Av;
#pragma unroll
            for (int i = 0; i < 3; i++) {
                int c = tid + 256 * i;
                if (c < 640) {
                    int row = c >> 2, ch = c & 3;
                    bool ok = (bm + row < M) && (k0 + ch * 8 < kend);
                    const void* src = A + (size_t)(bm + row) * K + k0 + ch * 8;
                    cpasync16(sbase + pbuf * ABUFSZ + row * 80 + ch * 16, ok ? src : A, ok);
                }
            }
        }
#pragma unroll
        for (int i = 0; i < 4; i++) {
            int c = tid + 256 * i;
            int row = c >> 6, seg = c & 63;
            bool ok = (k0 + 2 * row < kend);
            const void* src = Bp + (size_t)(k0 / 2 + row) * N + bn + seg * 4;
            cpasync16(sbase + 2 * ABUFSZ + pbuf * BBUFSZ + row * 1056 + seg * 16,
                      ok ? src : Bp, ok);
        }
        cpcommit();
    };

    int buf = 0;
    prefetch(0, 0);
    for (int t = 0; t < ntiles; t++) {
        cpwait0();
        __syncthreads();
        if (t + 1 < ntiles) prefetch(t + 1, buf ^ 1);

        const uint32_t* Bsb = (const uint32_t*)(smraw + 2 * ABUFSZ + buf * BBUFSZ);
#pragma unroll
        for (int ks = 0; ks < 2; ks++) {
            int kk0 = ks * 16 + 2 * (lane & 3);
            uint32_t af[5][4];
            if (AF32) {
                const float* Asf = (const float*)(smraw + buf * ABUFSZ);
#pragma unroll
                for (int mt = 0; mt < 5; mt++) {
                    int r = warp_m * 80 + mt * 16 + (lane >> 2);
                    float2 v0 = *(const float2*)(Asf + r * 36 + kk0);
                    float2 v1 = *(const float2*)(Asf + (r + 8) * 36 + kk0);
                    float2 v2 = *(const float2*)(Asf + r * 36 + kk0 + 8);
                    float2 v3 = *(const float2*)(Asf + (r + 8) * 36 + kk0 + 8);
                    af[mt][0] = packbf(v0.x, v0.y);
                    af[mt][1] = packbf(v1.x, v1.y);
                    af[mt][2] = packbf(v2.x, v2.y);
                    af[mt][3] = packbf(v3.x, v3.y);
                }
            } else {
                const uint16_t* Asb = (const uint16_t*)(smraw + buf * ABUFSZ);
#pragma unroll
                for (int mt = 0; mt < 5; mt++) {
                    int r = warp_m * 80 + mt * 16 + (lane >> 2);
                    af[mt][0] = *(const uint32_t*)(Asb + r * 40 + kk0);
                    af[mt][1] = *(const uint32_t*)(Asb + (r + 8) * 40 + kk0);
                    af[mt][2] = *(const uint32_t*)(Asb + r * 40 + kk0 + 8);
                    af[mt][3] = *(const uint32_t*)(Asb + (r + 8) * 40 + kk0 + 8);
                }
            }
            int p = ks * 8 + (lane & 3);
#pragma unroll
            for (int nt = 0; nt < 8; nt++) {
                int cl = warp_n * 64 + nt * 8 + (lane >> 2);
                uint32_t b0 = Bsb[p * 264 + cl];
                uint32_t b1 = Bsb[(p + 4) * 264 + cl];
#pragma unroll
                for (int mt = 0; mt < 5; mt++) {
                    asm volatile(
                        "mma.sync.aligned.m16n8k16.row.col.f32.bf16.bf16.f32 "
                        "{%0,%1,%2,%3}, {%4,%5,%6,%7}, {%8,%9}, {%0,%1,%2,%3};\n"
                        : "+f"(acc[mt][nt][0]), "+f"(acc[mt][nt][1]),
                          "+f"(acc[mt][nt][2]), "+f"(acc[mt][nt][3])
                        : "r"(af[mt][0]), "r"(af[mt][1]), "r"(af[mt][2]), "r"(af[mt][3]),
                          "r"(b0), "r"(b1));
                }
            }
        }
        buf ^= 1;
        __syncthreads();
    }

#pragma unroll
    for (int mt = 0; mt < 5; mt++) {
#pragma unroll
        for (int nt = 0; nt < 8; nt++) {
            int row = bm + warp_m * 80 + mt * 16 + (lane >> 2);
            int col = bn + warp_n * 64 + nt * 8 + 2 * (lane & 3);
            if (ATOMIC) {
                if (row < M) {
                    atomicAdd(&C[(size_t)row * N + col],     acc[mt][nt][0]);
                    atomicAdd(&C[(size_t)row * N + col + 1], acc[mt][nt][1]);
                }
                if (row + 8 < M) {
                    atomicAdd(&C[(size_t)(row + 8) * N + col],     acc[mt][nt][2]);
                    atomicAdd(&C[(size_t)(row + 8) * N + col + 1], acc[mt][nt][3]);
                }
            } else {
                uint32_t* Cb32 = (uint32_t*)Cb;
                if (row < M)
                    Cb32[((size_t)row * N + col) >> 1] = packbf(acc[mt][nt][0], acc[mt][nt][1]);
                if (row + 8 < M)
                    Cb32[((size_t)(row + 8) * N + col) >> 1] = packbf(acc[mt][nt][2], acc[mt][nt][3]);
            }
        }
    }
}

// ---------------- branch2 front: mean + bf16 conversion of data_x ----------------
__global__ void meanraw_kernel(const float* __restrict__ dx) {
    int f = blockIdx.x * 256 + threadIdx.x;
    if (f >= RAWF) return;
    int b = blockIdx.y;
    int s = g_bounds[b], e = g_bounds[b + 1];
    float acc = 0.f;
    for (int i = s; i < e; i++) {
        float v = dx[(size_t)i * RAWF + f];
        acc += v;
        g_datab[(size_t)i * RAWF + f] = __float2bfloat16(v);
    }
    int cnt = e - s; if (cnt < 1) cnt = 1;
    g_newxinb[(size_t)b * (2 * RAWF) + f] = __float2bfloat16(acc / (float)cnt);
}
__global__ void root_kernel(const float* __restrict__ dx, const int* __restrict__ root) {
    int f = blockIdx.x * 256 + threadIdx.x;
    if (f >= RAWF) return;
    int b = blockIdx.y;
    g_newxinb[(size_t)b * (2 * RAWF) + RAWF + f] =
        __float2bfloat16(dx[(size_t)root[b] * RAWF + f]);
}

// ---------------- small elementwise ----------------
__global__ void init_bias_kernel(float* __restrict__ p, const float* __restrict__ bias,
                                 int n, int mask) {
    int i = blockIdx.x * blockDim.x + threadIdx.x;
    if (i < n) p[i] = bias[i & mask];
}
__global__ void prelu_kernel(float* __restrict__ p, int n, const float* __restrict__ pa,
                             __nv_bfloat16* __restrict__ outb) {
    int i = blockIdx.x * blockDim.x + threadIdx.x;
    if (i >= n) return;
    float a = *pa;
    float v = p[i];
    v = v >= 0.f ? v : a * v;
    if (outb) outb[i] = __float2bfloat16(v);
    else p[i] = v;
}

// ---------------- final projection + log_softmax ----------------
__global__ void final_kernel(const float* __restrict__ W5, const float* __restrict__ b5,
                             float* __restrict__ out) {
    __shared__ float red[4][256];
    int b = blockIdx.x, t = threadIdx.x;
    int cnt = g_bounds[b + 1] - g_bounds[b];
    float inv = 1.f / (float)(cnt < 1 ? 1 : cnt);
    float acc[4] = {0.f, 0.f, 0.f, 0.f};
    for (int k = t; k < 5 * HH; k += 256) {
        int seg = k >> 8, f = k & 255;
        float v;
        if      (seg == 0) v = g_p0[b * HH + f] * inv;
        else if (seg == 1) v = g_p1[b * HH + f] * inv;
        else if (seg == 2) v = g_p2[b * HH + f] * inv;
        else if (seg == 3) v = g_newx[b * HH + f];
        else               v = g_xmax[b * HH + f];
#pragma unroll
        for (int c = 0; c < 4; c++) acc[c] += v * W5[k * 4 + c];
    }
#pragma unroll
    for (int c = 0; c < 4; c++) red[c][t] = acc[c];
    __syncthreads();
    for (int s = 128; s > 0; s >>= 1) {
        if (t < s) {
#pragma unroll
            for (int c = 0; c < 4; c++) red[c][t] += red[c][t + s];
        }
        __syncthreads();
    }
    if (t == 0) {
        float z[4];
#pragma unroll
        for (int c = 0; c < 4; c++) z[c] = red[c][0] + b5[c];
        float m = z[0];
#pragma unroll
        for (int c = 1; c < 4; c++) m = fmaxf(m, z[c]);
        float ssum = 0.f;
#pragma unroll
        for (int c = 0; c < 4; c++) ssum += expf(z[c] - m);
        float ls = logf(ssum);
#pragma unroll
        for (int c = 0; c < 4; c++) out[b * 4 + c] = z[c] - m - ls;
    }
}

// ---------------- host ----------------
extern "C" void kernel_launch(void* const* d_in, const int* in_sizes, int n_in,
                              void* d_out, int out_size) {
    const float* graph_x = (const float*)d_in[0];
    const float* data_x  = (const float*)d_in[2];
    const int*   ei      = (const int*)d_in[3];
    const int*   rei     = (const int*)d_in[4];
    const int*   gbatch  = (const int*)d_in[5];
    const int*   root    = (const int*)d_in[7];
    const float* W1  = (const float*)d_in[8];
    const float* b1  = (const float*)d_in[9];
    const float* Wc0 = (const float*)d_in[10];
    const float* bc0 = (const float*)d_in[11];
    const float* Wc1 = (const float*)d_in[12];
    const float* bc1 = (const float*)d_in[13];
    const float* Wc2 = (const float*)d_in[14];
    const float* bc2 = (const float*)d_in[15];
    const float* Wl1 = (const float*)d_in[16];
    const float* bl1 = (const float*)d_in[17];
    const float* Wl2 = (const float*)d_in[18];
    const float* bl2 = (const float*)d_in[19];
    const float* pa  = (const float*)d_in[20];
    const float* W5  = (const float*)d_in[21];
    const float* b5  = (const float*)d_in[22];
    float* out = (float*)d_out;

    static bool s_init = false;
    if (!s_init) {
        cudaFuncSetAttribute(gemm_bf16<1, 0>, cudaFuncAttributeMaxDynamicSharedMemorySize, 79872);
        cudaFuncSetAttribute(gemm_bf16<0, 0>, cudaFuncAttributeMaxDynamicSharedMemorySize, 59392);
        cudaFuncSetAttribute(gemm_bf16<0, 1>, cudaFuncAttributeMaxDynamicSharedMemorySize, 59392);
        s_init = true;
    }

    __nv_bfloat16 *phb, *paggb, *pdatab, *pl1b, *pnewxinb;
    float *pl1, *pnewx, *pxmax, *pp0, *pp1, *pp2;
    int *prs0, *prs1, *psrc0, *psrc1;
    float *pdinv0, *pdinv1;
    uint32_t *pwp;
    cudaGetSymbolAddress((void**)&phb,      g_hb);
    cudaGetSymbolAddress((void**)&paggb,    g_aggb);
    cudaGetSymbolAddress((void**)&pdatab,   g_datab);
    cudaGetSymbolAddress((void**)&pl1,      g_l1);
    cudaGetSymbolAddress((void**)&pl1b,     g_l1b);
    cudaGetSymbolAddress((void**)&pnewx,    g_newx);
    cudaGetSymbolAddress((void**)&pxmax,    g_xmax);
    cudaGetSymbolAddress((void**)&pp0,      g_p0);
    cudaGetSymbolAddress((void**)&pp1,      g_p1);
    cudaGetSymbolAddress((void**)&pp2,      g_p2);
    cudaGetSymbolAddress((void**)&pnewxinb, g_newxinb);
    cudaGetSymbolAddress((void**)&prs0,     g_rs0);
    cudaGetSymbolAddress((void**)&prs1,     g_rs1);
    cudaGetSymbolAddress((void**)&psrc0,    g_src0);
    cudaGetSymbolAddress((void**)&psrc1,    g_src1);
    cudaGetSymbolAddress((void**)&pdinv0,   g_dinv0);
    cudaGetSymbolAddress((void**)&pdinv1,   g_dinv1);
    cudaGetSymbolAddress((void**)&pwp,      g_wp);

    dim3 nodeGrid(1, (NN + 159) / 160, 1);   // 125 CTAs, one wave
    const int NB = (NN + 255) / 256, E4 = (EE / 4 + 255) / 256;
    dim3 rawGrid((RAWF + 255) / 256, BB);

    // ---- setup ----
    bounds_kernel<<<1, 160>>>(gbatch);

    // CSR for branch1 graph (ei)
    zero_cnt_kernel<<<NB, 256>>>();
    hist_kernel<<<E4, 256>>>(ei + EE);
    scan_kernel<<<1, 1024>>>(prs0, pdinv0);
    cursor_kernel<<<NB, 256>>>(prs0);
    fill_kernel<<<E4, 256>>>(ei, ei + EE, psrc0);
    // CSR for branch3 graph (rei)
    zero_cnt_kernel<<<NB, 256>>>();
    hist_kernel<<<E4, 256>>>(rei + EE);
    scan_kernel<<<1, 1024>>>(prs1, pdinv1);
    cursor_kernel<<<NB, 256>>>(prs1);
    fill_kernel<<<E4, 256>>>(rei, rei + EE, psrc1);

    // weight prep
    prep_w_kernel<<<((FIN / 2) * HH + 255) / 256, 256>>>(W1,  pwp + OFF_W1,  (FIN / 2) * HH, HH);
    prep_w_kernel<<<((RAWF / 2) * HH + 255) / 256, 256>>>(Wc0, pwp + OFF_WC0, (RAWF / 2) * HH, HH);
    prep_w_kernel<<<((HH / 2) * HH + 255) / 256, 256>>>(Wc1, pwp + OFF_WC1, (HH / 2) * HH, HH);
    prep_w_kernel<<<((HH / 2) * HH + 255) / 256, 256>>>(Wc2, pwp + OFF_WC2, (HH / 2) * HH, HH);
    prep_w_kernel<<<(RAWF * 512 + 255) / 256, 256>>>(Wl1, pwp + OFF_WL1, RAWF * 512, 512);
    prep_w_kernel<<<(256 * HH + 255) / 256, 256>>>(Wl2, pwp + OFF_WL2, 256 * HH, HH);

    // branch2 front (also produces bf16 data_x for branch 3)
    meanraw_kernel<<<rawGrid, 256>>>(data_x);
    root_kernel<<<rawGrid, 256>>>(data_x, root);

    // ---------- branch 1 ----------
    gemm_bf16<1, 0><<<nodeGrid, 256, 79872>>>(graph_x, pwp + OFF_W1, nullptr,
                                              (uint16_t*)phb, NN, HH, FIN, FIN);
    gather_kernel<<<NN / 8, 256>>>((const uint4*)phb, b1, prs0, psrc0, pdinv0, paggb);
    pool_kernel<1><<<BB, 1024>>>((const uint2*)paggb, pxmax);

    // ---------- branch 2 ----------
    init_bias_kernel<<<(BB * 512 + 255) / 256, 256>>>(pl1, bl1, BB * 512, 511);
    gemm_bf16<0, 1><<<dim3(2, 1, 63), 256, 59392>>>(pnewxinb, pwp + OFF_WL1, pl1,
                                                    nullptr, BB, 512, 2 * RAWF, 160);
    prelu_kernel<<<(BB * 512 + 255) / 256, 256>>>(pl1, BB * 512, pa, pl1b);
    init_bias_kernel<<<(BB * 256 + 255) / 256, 256>>>(pnewx, bl2, BB * 256, 255);
    gemm_bf16<0, 1><<<dim3(1, 1, 8), 256, 59392>>>(pl1b, pwp + OFF_WL2, pnewx,
                                                   nullptr, BB, HH, 512, 64);
    prelu_kernel<<<(BB * 256 + 255) / 256, 256>>>(pnewx, BB * 256, pa, nullptr);

    // ---------- branch 3 ----------
    gemm_bf16<0, 0><<<nodeGrid, 256, 59392>>>(pdatab, pwp + OFF_WC0, nullptr,
                                              (uint16_t*)phb, NN, HH, RAWF, RAWF);
    gather_kernel<<<NN / 8, 256>>>((const uint4*)phb, bc0, prs1, psrc1, pdinv1, paggb);
    pool_kernel<0><<<BB, 1024>>>((const uint2*)paggb, pp0);
    gemm_bf16<0, 0><<<nodeGrid, 256, 59392>>>(paggb, pwp + OFF_WC1, nullptr,
                                              (uint16_t*)phb, NN, HH, HH, HH);
    gather_kernel<<<NN / 8, 256>>>((const uint4*)phb, bc1, prs1, psrc1, pdinv1, paggb);
    pool_kernel<0><<<BB, 1024>>>((const uint2*)paggb, pp1);
    gemm_bf16<0, 0><<<nodeGrid, 256, 59392>>>(paggb, pwp + OFF_WC2, nullptr,
                                              (uint16_t*)phb, NN, HH, HH, HH);
    gather_kernel<<<NN / 8, 256>>>((const uint4*)phb, bc2, prs1, psrc1, pdinv1, paggb);
    pool_kernel<0><<<BB, 1024>>>((const uint2*)paggb, pp2);

    // ---------- final ----------
    final_kernel<<<BB, 256>>>(W5, b5, out);
}

// round 12
// speedup vs baseline: 1.4809x; 1.0250x over previous
#include <cuda_runtime.h>
#include <cuda_bf16.h>
#include <cstdint>

#define NN   20000
#define BB   128
#define EE   320000
#define FIN  768
#define RAWF 5000
#define HH   256
#define CC   4

// ---------------- scratch (device globals) ----------------
__device__ __align__(16) __nv_bfloat16 g_hb[NN * HH];    // GEMM output h (bf16)
__device__ __align__(16) __nv_bfloat16 g_aggb[NN * HH];  // activation (bf16)
__device__ __align__(16) __nv_bfloat16 g_datab[(size_t)NN * RAWF]; // bf16 data_x
__device__ __align__(16) float g_l1[BB * 512];
__device__ __align__(16) __nv_bfloat16 g_l1b[BB * 512];
__device__ __align__(16) float g_newx[BB * HH];
__device__ __align__(16) float g_xmax[BB * HH];
__device__ __align__(16) float g_p0[BB * HH];
__device__ __align__(16) float g_p1[BB * HH];
__device__ __align__(16) float g_p2[BB * HH];
__device__ __align__(16) __nv_bfloat16 g_newxinb[BB * 2 * RAWF];
// packed k2-interleaved bf16 weights
#define OFF_W1   0
#define OFF_WC0  98304
#define OFF_WC1  738304
#define OFF_WC2  771072
#define OFF_WL1  803840
#define OFF_WL2  3363840
__device__ __align__(16) uint32_t g_wp[3429376];
__device__ __align__(16) int   g_cnt0[NN];
__device__ __align__(16) int   g_cnt1[NN];
__device__ int   g_cur0[NN];
__device__ int   g_cur1[NN];
__device__ __align__(16) int   g_rs0[NN + 4];
__device__ __align__(16) int   g_rs1[NN + 4];
__device__ int   g_src0[EE];
__device__ int   g_src1[EE];
__device__ __align__(16) float g_dinv0[NN];
__device__ __align__(16) float g_dinv1[NN];
__device__ int   g_bounds[BB + 1];

// ---------------- helpers ----------------
__device__ __forceinline__ uint32_t packbf(float lo, float hi) {
    uint32_t r;
    asm("cvt.rn.bf16x2.f32 %0, %1, %2;" : "=r"(r) : "f"(hi), "f"(lo));
    return r;
}
__device__ __forceinline__ void cpasync16(uint32_t dst, const void* src, bool ok) {
    int ss = ok ? 16 : 0;
    asm volatile("cp.async.cg.shared.global [%0], [%1], 16, %2;\n" :: "r"(dst), "l"(src), "r"(ss));
}
__device__ __forceinline__ void cpcommit() { asm volatile("cp.async.commit_group;\n"); }
__device__ __forceinline__ void cpwait0()  { asm volatile("cp.async.wait_group 0;\n"); }
__device__ __forceinline__ void unp(uint32_t w, float& a, float& b) {
    a = __uint_as_float(w << 16);
    b = __uint_as_float(w & 0xffff0000u);
}

// ---------------- segment bounds ----------------
__global__ void bounds_kernel(const int* __restrict__ batch) {
    int b = threadIdx.x;
    if (b > BB) return;
    int lo = 0, hi = NN;
    while (lo < hi) {
        int mid = (lo + hi) >> 1;
        if (batch[mid] < b) lo = mid + 1; else hi = mid;
    }
    g_bounds[b] = lo;
}

// ---------------- weight prep ----------------
__global__ void prep_w_kernel(const float* __restrict__ W, uint32_t* __restrict__ Wp,
                              int cnt, int N) {
    int idx = blockIdx.x * blockDim.x + threadIdx.x;
    if (idx >= cnt) return;
    int p = idx / N, n = idx - p * N;
    Wp[idx] = packbf(W[(size_t)(2 * p) * N + n], W[(size_t)(2 * p + 1) * N + n]);
}

// ---------------- CSR build (both graphs in shared kernels) ----------------
__global__ void zero2_kernel() {
    int i = blockIdx.x * blockDim.x + threadIdx.x;
    if (i < NN) { g_cnt0[i] = 0; g_cnt1[i] = 0; }
}
__global__ void hist2_kernel(const int* __restrict__ ei, const int* __restrict__ rei) {
    int i = blockIdx.x * blockDim.x + threadIdx.x;
    if (i >= EE / 4) return;
    const int* dst;
    int* cnt;
    if (blockIdx.y == 0) { dst = ei + EE;  cnt = g_cnt0; }
    else                 { dst = rei + EE; cnt = g_cnt1; }
    int4 d = ((const int4*)dst)[i];
    atomicAdd(&cnt[d.x], 1);
    atomicAdd(&cnt[d.y], 1);
    atomicAdd(&cnt[d.z], 1);
    atomicAdd(&cnt[d.w], 1);
}
// 2 blocks: block g scans graph g's counts -> rowstart, cursor, dinv
__global__ void scan2_kernel() {
    __shared__ int wsum[32];
    int g = blockIdx.x;
    const int* cnt = g ? g_cnt1 : g_cnt0;
    int* rs        = g ? g_rs1  : g_rs0;
    int* cur       = g ? g_cur1 : g_cur0;
    float* dinv    = g ? g_dinv1 : g_dinv0;
    int t = threadIdx.x;
    int lane = t & 31, wid = t >> 5;
    int c[20];
    const int4* c4 = (const int4*)cnt;
#pragma unroll
    for (int i = 0; i < 5; i++) {
        int idx4 = t * 5 + i;
        int4 v = (idx4 < 5000) ? c4[idx4] : make_int4(0, 0, 0, 0);
        c[i * 4 + 0] = v.x; c[i * 4 + 1] = v.y; c[i * 4 + 2] = v.z; c[i * 4 + 3] = v.w;
    }
    int loc[20];
    int s = 0;
#pragma unroll
    for (int i = 0; i < 20; i++) { loc[i] = s; s += c[i]; }
    int x = s;
#pragma unroll
    for (int off = 1; off < 32; off <<= 1) {
        int y = __shfl_up_sync(0xffffffffu, x, off);
        if (lane >= off) x += y;
    }
    if (lane == 31) wsum[wid] = x;
    __syncthreads();
    if (wid == 0) {
        int v = wsum[lane];
#pragma unroll
        for (int off = 1; off < 32; off <<= 1) {
            int y = __shfl_up_sync(0xffffffffu, v, off);
            if (lane >= off) v += y;
        }
        wsum[lane] = v;
    }
    __syncthreads();
    int offset = (wid ? wsum[wid - 1] : 0) + (x - s);
    int4* rs4 = (int4*)rs;
    int4* cu4 = (int4*)cur;
    float4* dv4 = (float4*)dinv;
#pragma unroll
    for (int i = 0; i < 5; i++) {
        int idx4 = t * 5 + i;
        if (idx4 < 5000) {
            int4 r; float4 d;
            r.x = offset + loc[i * 4 + 0]; d.x = rsqrtf((float)(c[i * 4 + 0] + 1));
            r.y = offset + loc[i * 4 + 1]; d.y = rsqrtf((float)(c[i * 4 + 1] + 1));
            r.z = offset + loc[i * 4 + 2]; d.z = rsqrtf((float)(c[i * 4 + 2] + 1));
            r.w = offset + loc[i * 4 + 3]; d.w = rsqrtf((float)(c[i * 4 + 3] + 1));
            rs4[idx4] = r; cu4[idx4] = r; dv4[idx4] = d;
        }
    }
    if (t == 0) rs[NN] = EE;
}
__global__ void fill2_kernel(const int* __restrict__ ei, const int* __restrict__ rei) {
    int i = blockIdx.x * blockDim.x + threadIdx.x;
    if (i >= EE / 4) return;
    const int* src;
    const int* dst;
    int* cur;
    int* outp;
    if (blockIdx.y == 0) { src = ei;  dst = ei + EE;  cur = g_cur0; outp = g_src0; }
    else                 { src = rei; dst = rei + EE; cur = g_cur1; outp = g_src1; }
    int4 d = ((const int4*)dst)[i];
    int4 s = ((const int4*)src)[i];
    outp[atomicAdd(&cur[d.x], 1)] = s.x;
    outp[atomicAdd(&cur[d.y], 1)] = s.y;
    outp[atomicAdd(&cur[d.z], 1)] = s.z;
    outp[atomicAdd(&cur[d.w], 1)] = s.w;
}

// ---------------- fused GCN aggregation + relu (bf16 in/out), edge loop unrolled x4 ----------------
__global__ __launch_bounds__(256)
void gather_kernel(const uint4* __restrict__ hb, const float* __restrict__ bias,
                   const int* __restrict__ rs, const int* __restrict__ csr,
                   const float* __restrict__ dinv, __nv_bfloat16* __restrict__ outb) {
    int node = blockIdx.x * 8 + (threadIdx.x >> 5);
    int lane = threadIdx.x & 31;
    float di = dinv[node];
    float sw = di * di;
    float acc[8];
    {
        uint4 hv = hb[(size_t)node * 32 + lane];
        float f0, f1;
        unp(hv.x, f0, f1); acc[0] = f0 * sw; acc[1] = f1 * sw;
        unp(hv.y, f0, f1); acc[2] = f0 * sw; acc[3] = f1 * sw;
        unp(hv.z, f0, f1); acc[4] = f0 * sw; acc[5] = f1 * sw;
        unp(hv.w, f0, f1); acc[6] = f0 * sw; acc[7] = f1 * sw;
    }
    int e0 = rs[node], e1 = rs[node + 1];
    int e = e0;
    for (; e + 4 <= e1; e += 4) {
        int s0 = csr[e], s1 = csr[e + 1], s2 = csr[e + 2], s3 = csr[e + 3];
        float w0 = dinv[s0] * di, w1 = dinv[s1] * di;
        float w2 = dinv[s2] * di, w3 = dinv[s3] * di;
        uint4 h0 = hb[(size_t)s0 * 32 + lane];
        uint4 h1 = hb[(size_t)s1 * 32 + lane];
        uint4 h2 = hb[(size_t)s2 * 32 + lane];
        uint4 h3 = hb[(size_t)s3 * 32 + lane];
        float f0, f1;
        unp(h0.x, f0, f1); acc[0] = fmaf(f0, w0, acc[0]); acc[1] = fmaf(f1, w0, acc[1]);
        unp(h0.y, f0, f1); acc[2] = fmaf(f0, w0, acc[2]); acc[3] = fmaf(f1, w0, acc[3]);
        unp(h0.z, f0, f1); acc[4] = fmaf(f0, w0, acc[4]); acc[5] = fmaf(f1, w0, acc[5]);
        unp(h0.w, f0, f1); acc[6] = fmaf(f0, w0, acc[6]); acc[7] = fmaf(f1, w0, acc[7]);
        unp(h1.x, f0, f1); acc[0] = fmaf(f0, w1, acc[0]); acc[1] = fmaf(f1, w1, acc[1]);
        unp(h1.y, f0, f1); acc[2] = fmaf(f0, w1, acc[2]); acc[3] = fmaf(f1, w1, acc[3]);
        unp(h1.z, f0, f1); acc[4] = fmaf(f0, w1, acc[4]); acc[5] = fmaf(f1, w1, acc[5]);
        unp(h1.w, f0, f1); acc[6] = fmaf(f0, w1, acc[6]); acc[7] = fmaf(f1, w1, acc[7]);
        unp(h2.x, f0, f1); acc[0] = fmaf(f0, w2, acc[0]); acc[1] = fmaf(f1, w2, acc[1]);
        unp(h2.y, f0, f1); acc[2] = fmaf(f0, w2, acc[2]); acc[3] = fmaf(f1, w2, acc[3]);
        unp(h2.z, f0, f1); acc[4] = fmaf(f0, w2, acc[4]); acc[5] = fmaf(f1, w2, acc[5]);
        unp(h2.w, f0, f1); acc[6] = fmaf(f0, w2, acc[6]); acc[7] = fmaf(f1, w2, acc[7]);
        unp(h3.x, f0, f1); acc[0] = fmaf(f0, w3, acc[0]); acc[1] = fmaf(f1, w3, acc[1]);
        unp(h3.y, f0, f1); acc[2] = fmaf(f0, w3, acc[2]); acc[3] = fmaf(f1, w3, acc[3]);
        unp(h3.z, f0, f1); acc[4] = fmaf(f0, w3, acc[4]); acc[5] = fmaf(f1, w3, acc[5]);
        unp(h3.w, f0, f1); acc[6] = fmaf(f0, w3, acc[6]); acc[7] = fmaf(f1, w3, acc[7]);
    }
    for (; e < e1; e++) {
        int s = csr[e];
        float w = dinv[s] * di;
        uint4 hv = hb[(size_t)s * 32 + lane];
        float f0, f1;
        unp(hv.x, f0, f1); acc[0] = fmaf(f0, w, acc[0]); acc[1] = fmaf(f1, w, acc[1]);
        unp(hv.y, f0, f1); acc[2] = fmaf(f0, w, acc[2]); acc[3] = fmaf(f1, w, acc[3]);
        unp(hv.z, f0, f1); acc[4] = fmaf(f0, w, acc[4]); acc[5] = fmaf(f1, w, acc[5]);
        unp(hv.w, f0, f1); acc[6] = fmaf(f0, w, acc[6]); acc[7] = fmaf(f1, w, acc[7]);
    }
    float4 bb0 = ((const float4*)bias)[2 * lane];
    float4 bb1 = ((const float4*)bias)[2 * lane + 1];
    float v[8];
    v[0] = fmaxf(acc[0] + bb0.x, 0.f); v[1] = fmaxf(acc[1] + bb0.y, 0.f);
    v[2] = fmaxf(acc[2] + bb0.z, 0.f); v[3] = fmaxf(acc[3] + bb0.w, 0.f);
    v[4] = fmaxf(acc[4] + bb1.x, 0.f); v[5] = fmaxf(acc[5] + bb1.y, 0.f);
    v[6] = fmaxf(acc[6] + bb1.z, 0.f); v[7] = fmaxf(acc[7] + bb1.w, 0.f);
    uint4 o;
    o.x = packbf(v[0], v[1]); o.y = packbf(v[2], v[3]);
    o.z = packbf(v[4], v[5]); o.w = packbf(v[6], v[7]);
    ((uint4*)outb)[(size_t)node * 32 + lane] = o;
}

// ---------------- pooling over contiguous segments (bf16 input, no atomics) ----------------
template<int ISMAX>
__global__ void pool_kernel(const uint2* __restrict__ xb, float* __restrict__ out) {
    __shared__ float red[16 * 256];
    int b = blockIdx.x, t = threadIdx.x;
    int q = t & 63;
    int rp = t >> 6;         // 0..15
    int s = g_bounds[b], e = g_bounds[b + 1];
    float a0 = 0.f, a1 = 0.f, a2 = 0.f, a3 = 0.f;
    for (int i = s + rp; i < e; i += 16) {
        uint2 v = xb[(size_t)i * 64 + q];
        float f0, f1, f2, f3;
        unp(v.x, f0, f1); unp(v.y, f2, f3);
        if (ISMAX) {
            a0 = fmaxf(a0, f0); a1 = fmaxf(a1, f1);
            a2 = fmaxf(a2, f2); a3 = fmaxf(a3, f3);
        } else {
            a0 += f0; a1 += f1; a2 += f2; a3 += f3;
        }
    }
    red[rp * 256 + q * 4 + 0] = a0;
    red[rp * 256 + q * 4 + 1] = a1;
    red[rp * 256 + q * 4 + 2] = a2;
    red[rp * 256 + q * 4 + 3] = a3;
    __syncthreads();
    if (t < 256) {
        float r = red[t];
#pragma unroll
        for (int p = 1; p < 16; p++) {
            if (ISMAX) r = fmaxf(r, red[p * 256 + t]);
            else       r += red[p * 256 + t];
        }
        out[b * HH + t] = r;
    }
}

// ---------------- bf16 tensor-core GEMM (mma.sync) ----------------
// A: fp32 (AF32=1, converted at LDS) or bf16 row-major. B packed k2-interleaved u32[K/2][N].
// CTA tile 160x256xk32; 8 warps 2m x 4n; warp tile 80x64.
// ATOMIC=1: fp32 atomicAdd into C (split-K). ATOMIC=0: bf16 packed store into Cb.
template<int AF32, int ATOMIC>
__global__ __launch_bounds__(256)
void gemm_bf16(const void* __restrict__ Av, const uint32_t* __restrict__ Bp,
               float* __restrict__ C, uint16_t* __restrict__ Cb,
               int M, int N, int K, int KS) {
    constexpr int ABUFSZ = AF32 ? 23040 : 12800;
    constexpr int BBUFSZ = 16896;
    extern __shared__ __align__(16) uint8_t smraw[];
    int tid = threadIdx.x;
    int lane = tid & 31, wid = tid >> 5;
    int warp_m = wid & 1, warp_n = wid >> 1;
    int bm = blockIdx.y * 160;
    int bn = blockIdx.x * 256;
    int kbeg = blockIdx.z * KS;
    int kend = min(K, kbeg + KS);
    int ntiles = (kend - kbeg + 31) >> 5;
    uint32_t sbase = (uint32_t)__cvta_generic_to_shared(smraw);

    float acc[5][8][4];
#pragma unroll
    for (int mt = 0; mt < 5; mt++)
#pragma unroll
        for (int nt = 0; nt < 8; nt++)
#pragma unroll
            for (int q = 0; q < 4; q++) acc[mt][nt][q] = 0.f;

    auto prefetch = [&](int tile, int pbuf) {
        int k0 = kbeg + tile * 32;
        if (AF32) {
            const float* A = (const float*)Av;
#pragma unroll
            for (int i = 0; i < 5; i++) {
                int c = tid + 256 * i;
                int row = c >> 3, ch = c & 7;
                bool ok = (bm + row < M) && (k0 + ch * 4 < kend);
                const void* src = A + (size_t)(bm + row) * K + k0 + ch * 4;
                cpasync16(sbase + pbuf * ABUFSZ + row * 144 + ch * 16, ok ? src : A, ok);
            }
        } else {
            const __nv_bfloat16* A = (const __nv_bfloat16*)Av;
#pragma unroll
            for (int i = 0; i < 3; i++) {
                int c = tid + 256 * i;
                if (c < 640) {
                    int row = c >> 2, ch = c & 3;
                    bool ok = (bm + row < M) && (k0 + ch * 8 < kend);
                    const void* src = A + (size_t)(bm + row) * K + k0 + ch * 8;
                    cpasync16(sbase + pbuf * ABUFSZ + row * 80 + ch * 16, ok ? src : A, ok);
                }
            }
        }
#pragma unroll
        for (int i = 0; i < 4; i++) {
            int c = tid + 256 * i;
            int row = c >> 6, seg = c & 63;
            bool ok = (k0 + 2 * row < kend);
            const void* src = Bp + (size_t)(k0 / 2 + row) * N + bn + seg * 4;
            cpasync16(sbase + 2 * ABUFSZ + pbuf * BBUFSZ + row * 1056 + seg * 16,
                      ok ? src : Bp, ok);
        }
        cpcommit();
    };

    int buf = 0;
    prefetch(0, 0);
    for (int t = 0; t < ntiles; t++) {
        cpwait0();
        __syncthreads();
        if (t + 1 < ntiles) prefetch(t + 1, buf ^ 1);

        const uint32_t* Bsb = (const uint32_t*)(smraw + 2 * ABUFSZ + buf * BBUFSZ);
#pragma unroll
        for (int ks = 0; ks < 2; ks++) {
            int kk0 = ks * 16 + 2 * (lane & 3);
            uint32_t af[5][4];
            if (AF32) {
                const float* Asf = (const float*)(smraw + buf * ABUFSZ);
#pragma unroll
                for (int mt = 0; mt < 5; mt++) {
                    int r = warp_m * 80 + mt * 16 + (lane >> 2);
                    float2 v0 = *(const float2*)(Asf + r * 36 + kk0);
                    float2 v1 = *(const float2*)(Asf + (r + 8) * 36 + kk0);
                    float2 v2 = *(const float2*)(Asf + r * 36 + kk0 + 8);
                    float2 v3 = *(const float2*)(Asf + (r + 8) * 36 + kk0 + 8);
                    af[mt][0] = packbf(v0.x, v0.y);
                    af[mt][1] = packbf(v1.x, v1.y);
                    af[mt][2] = packbf(v2.x, v2.y);
                    af[mt][3] = packbf(v3.x, v3.y);
                }
            } else {
                const uint16_t* Asb = (const uint16_t*)(smraw + buf * ABUFSZ);
#pragma unroll
                for (int mt = 0; mt < 5; mt++) {
                    int r = warp_m * 80 + mt * 16 + (lane >> 2);
                    af[mt][0] = *(const uint32_t*)(Asb + r * 40 + kk0);
                    af[mt][1] = *(const uint32_t*)(Asb + (r + 8) * 40 + kk0);
                    af[mt][2] = *(const uint32_t*)(Asb + r * 40 + kk0 + 8);
                    af[mt][3] = *(const uint32_t*)(Asb + (r + 8) * 40 + kk0 + 8);
                }
            }
            int p = ks * 8 + (lane & 3);
#pragma unroll
            for (int nt = 0; nt < 8; nt++) {
                int cl = warp_n * 64 + nt * 8 + (lane >> 2);
                uint32_t b0 = Bsb[p * 264 + cl];
                uint32_t b1 = Bsb[(p + 4) * 264 + cl];
#pragma unroll
                for (int mt = 0; mt < 5; mt++) {
                    asm volatile(
                        "mma.sync.aligned.m16n8k16.row.col.f32.bf16.bf16.f32 "
                        "{%0,%1,%2,%3}, {%4,%5,%6,%7}, {%8,%9}, {%0,%1,%2,%3};\n"
                        : "+f"(acc[mt][nt][0]), "+f"(acc[mt][nt][1]),
                          "+f"(acc[mt][nt][2]), "+f"(acc[mt][nt][3])
                        : "r"(af[mt][0]), "r"(af[mt][1]), "r"(af[mt][2]), "r"(af[mt][3]),
                          "r"(b0), "r"(b1));
                }
            }
        }
        buf ^= 1;
        __syncthreads();
    }

#pragma unroll
    for (int mt = 0; mt < 5; mt++) {
#pragma unroll
        for (int nt = 0; nt < 8; nt++) {
            int row = bm + warp_m * 80 + mt * 16 + (lane >> 2);
            int col = bn + warp_n * 64 + nt * 8 + 2 * (lane & 3);
            if (ATOMIC) {
                if (row < M) {
                    atomicAdd(&C[(size_t)row * N + col],     acc[mt][nt][0]);
                    atomicAdd(&C[(size_t)row * N + col + 1], acc[mt][nt][1]);
                }
                if (row + 8 < M) {
                    atomicAdd(&C[(size_t)(row + 8) * N + col],     acc[mt][nt][2]);
                    atomicAdd(&C[(size_t)(row + 8) * N + col + 1], acc[mt][nt][3]);
                }
            } else {
                uint32_t* Cb32 = (uint32_t*)Cb;
                if (row < M)
                    Cb32[((size_t)row * N + col) >> 1] = packbf(acc[mt][nt][0], acc[mt][nt][1]);
                if (row + 8 < M)
                    Cb32[((size_t)(row + 8) * N + col) >> 1] = packbf(acc[mt][nt][2], acc[mt][nt][3]);
            }
        }
    }
}

// ---------------- branch2 front: mean + bf16 conversion of data_x ----------------
__global__ void meanraw_kernel(const float* __restrict__ dx) {
    int f = blockIdx.x * 256 + threadIdx.x;
    if (f >= RAWF) return;
    int b = blockIdx.y;
    int s = g_bounds[b], e = g_bounds[b + 1];
    float acc = 0.f;
    for (int i = s; i < e; i++) {
        float v = dx[(size_t)i * RAWF + f];
        acc += v;
        g_datab[(size_t)i * RAWF + f] = __float2bfloat16(v);
    }
    int cnt = e - s; if (cnt < 1) cnt = 1;
    g_newxinb[(size_t)b * (2 * RAWF) + f] = __float2bfloat16(acc / (float)cnt);
}
__global__ void root_kernel(const float* __restrict__ dx, const int* __restrict__ root) {
    int f = blockIdx.x * 256 + threadIdx.x;
    if (f >= RAWF) return;
    int b = blockIdx.y;
    g_newxinb[(size_t)b * (2 * RAWF) + RAWF + f] =
        __float2bfloat16(dx[(size_t)root[b] * RAWF + f]);
}

// ---------------- small elementwise ----------------
__global__ void init_bias_kernel(float* __restrict__ p, const float* __restrict__ bias,
                                 int n, int mask) {
    int i = blockIdx.x * blockDim.x + threadIdx.x;
    if (i < n) p[i] = bias[i & mask];
}
__global__ void prelu_kernel(float* __restrict__ p, int n, const float* __restrict__ pa,
                             __nv_bfloat16* __restrict__ outb) {
    int i = blockIdx.x * blockDim.x + threadIdx.x;
    if (i >= n) return;
    float a = *pa;
    float v = p[i];
    v = v >= 0.f ? v : a * v;
    if (outb) outb[i] = __float2bfloat16(v);
    else p[i] = v;
}

// ---------------- final projection + log_softmax ----------------
__global__ void final_kernel(const float* __restrict__ W5, const float* __restrict__ b5,
                             float* __restrict__ out) {
    __shared__ float red[4][256];
    int b = blockIdx.x, t = threadIdx.x;
    int cnt = g_bounds[b + 1] - g_bounds[b];
    float inv = 1.f / (float)(cnt < 1 ? 1 : cnt);
    float acc[4] = {0.f, 0.f, 0.f, 0.f};
    for (int k = t; k < 5 * HH; k += 256) {
        int seg = k >> 8, f = k & 255;
        float v;
        if      (seg == 0) v = g_p0[b * HH + f] * inv;
        else if (seg == 1) v = g_p1[b * HH + f] * inv;
        else if (seg == 2) v = g_p2[b * HH + f] * inv;
        else if (seg == 3) v = g_newx[b * HH + f];
        else               v = g_xmax[b * HH + f];
#pragma unroll
        for (int c = 0; c < 4; c++) acc[c] += v * W5[k * 4 + c];
    }
#pragma unroll
    for (int c = 0; c < 4; c++) red[c][t] = acc[c];
    __syncthreads();
    for (int s = 128; s > 0; s >>= 1) {
        if (t < s) {
#pragma unroll
            for (int c = 0; c < 4; c++) red[c][t] += red[c][t + s];
        }
        __syncthreads();
    }
    if (t == 0) {
        float z[4];
#pragma unroll
        for (int c = 0; c < 4; c++) z[c] = red[c][0] + b5[c];
        float m = z[0];
#pragma unroll
        for (int c = 1; c < 4; c++) m = fmaxf(m, z[c]);
        float ssum = 0.f;
#pragma unroll
        for (int c = 0; c < 4; c++) ssum += expf(z[c] - m);
        float ls = logf(ssum);
#pragma unroll
        for (int c = 0; c < 4; c++) out[b * 4 + c] = z[c] - m - ls;
    }
}

// ---------------- host ----------------
extern "C" void kernel_launch(void* const* d_in, const int* in_sizes, int n_in,
                              void* d_out, int out_size) {
    const float* graph_x = (const float*)d_in[0];
    const float* data_x  = (const float*)d_in[2];
    const int*   ei      = (const int*)d_in[3];
    const int*   rei     = (const int*)d_in[4];
    const int*   gbatch  = (const int*)d_in[5];
    const int*   root    = (const int*)d_in[7];
    const float* W1  = (const float*)d_in[8];
    const float* b1  = (const float*)d_in[9];
    const float* Wc0 = (const float*)d_in[10];
    const float* bc0 = (const float*)d_in[11];
    const float* Wc1 = (const float*)d_in[12];
    const float* bc1 = (const float*)d_in[13];
    const float* Wc2 = (const float*)d_in[14];
    const float* bc2 = (const float*)d_in[15];
    const float* Wl1 = (const float*)d_in[16];
    const float* bl1 = (const float*)d_in[17];
    const float* Wl2 = (const float*)d_in[18];
    const float* bl2 = (const float*)d_in[19];
    const float* pa  = (const float*)d_in[20];
    const float* W5  = (const float*)d_in[21];
    const float* b5  = (const float*)d_in[22];
    float* out = (float*)d_out;

    static bool s_init = false;
    if (!s_init) {
        cudaFuncSetAttribute(gemm_bf16<1, 0>, cudaFuncAttributeMaxDynamicSharedMemorySize, 79872);
        cudaFuncSetAttribute(gemm_bf16<0, 0>, cudaFuncAttributeMaxDynamicSharedMemorySize, 59392);
        cudaFuncSetAttribute(gemm_bf16<0, 1>, cudaFuncAttributeMaxDynamicSharedMemorySize, 59392);
        s_init = true;
    }

    __nv_bfloat16 *phb, *paggb, *pdatab, *pl1b, *pnewxinb;
    float *pl1, *pnewx, *pxmax, *pp0, *pp1, *pp2;
    int *prs0, *prs1, *psrc0, *psrc1;
    float *pdinv0, *pdinv1;
    uint32_t *pwp;
    cudaGetSymbolAddress((void**)&phb,      g_hb);
    cudaGetSymbolAddress((void**)&paggb,    g_aggb);
    cudaGetSymbolAddress((void**)&pdatab,   g_datab);
    cudaGetSymbolAddress((void**)&pl1,      g_l1);
    cudaGetSymbolAddress((void**)&pl1b,     g_l1b);
    cudaGetSymbolAddress((void**)&pnewx,    g_newx);
    cudaGetSymbolAddress((void**)&pxmax,    g_xmax);
    cudaGetSymbolAddress((void**)&pp0,      g_p0);
    cudaGetSymbolAddress((void**)&pp1,      g_p1);
    cudaGetSymbolAddress((void**)&pp2,      g_p2);
    cudaGetSymbolAddress((void**)&pnewxinb, g_newxinb);
    cudaGetSymbolAddress((void**)&prs0,     g_rs0);
    cudaGetSymbolAddress((void**)&prs1,     g_rs1);
    cudaGetSymbolAddress((void**)&psrc0,    g_src0);
    cudaGetSymbolAddress((void**)&psrc1,    g_src1);
    cudaGetSymbolAddress((void**)&pdinv0,   g_dinv0);
    cudaGetSymbolAddress((void**)&pdinv1,   g_dinv1);
    cudaGetSymbolAddress((void**)&pwp,      g_wp);

    dim3 nodeGrid(1, (NN + 159) / 160, 1);   // 125 CTAs, one wave
    const int NB = (NN + 255) / 256;
    dim3 edgeGrid((EE / 4 + 255) / 256, 2);
    dim3 rawGrid((RAWF + 255) / 256, BB);

    // ---- setup ----
    bounds_kernel<<<1, 160>>>(gbatch);

    // CSR for both graphs (combined kernels, 2-block parallel scan)
    zero2_kernel<<<NB, 256>>>();
    hist2_kernel<<<edgeGrid, 256>>>(ei, rei);
    scan2_kernel<<<2, 1024>>>();
    fill2_kernel<<<edgeGrid, 256>>>(ei, rei);

    // weight prep
    prep_w_kernel<<<((FIN / 2) * HH + 255) / 256, 256>>>(W1,  pwp + OFF_W1,  (FIN / 2) * HH, HH);
    prep_w_kernel<<<((RAWF / 2) * HH + 255) / 256, 256>>>(Wc0, pwp + OFF_WC0, (RAWF / 2) * HH, HH);
    prep_w_kernel<<<((HH / 2) * HH + 255) / 256, 256>>>(Wc1, pwp + OFF_WC1, (HH / 2) * HH, HH);
    prep_w_kernel<<<((HH / 2) * HH + 255) / 256, 256>>>(Wc2, pwp + OFF_WC2, (HH / 2) * HH, HH);
    prep_w_kernel<<<(RAWF * 512 + 255) / 256, 256>>>(Wl1, pwp + OFF_WL1, RAWF * 512, 512);
    prep_w_kernel<<<(256 * HH + 255) / 256, 256>>>(Wl2, pwp + OFF_WL2, 256 * HH, HH);

    // branch2 front (also produces bf16 data_x for branch 3)
    meanraw_kernel<<<rawGrid, 256>>>(data_x);
    root_kernel<<<rawGrid, 256>>>(data_x, root);

    // ---------- branch 1 ----------
    gemm_bf16<1, 0><<<nodeGrid, 256, 79872>>>(graph_x, pwp + OFF_W1, nullptr,
                                              (uint16_t*)phb, NN, HH, FIN, FIN);
    gather_kernel<<<NN / 8, 256>>>((const uint4*)phb, b1, prs0, psrc0, pdinv0, paggb);
    pool_kernel<1><<<BB, 1024>>>((const uint2*)paggb, pxmax);

    // ---------- branch 2 ----------
    init_bias_kernel<<<(BB * 512 + 255) / 256, 256>>>(pl1, bl1, BB * 512, 511);
    gemm_bf16<0, 1><<<dim3(2, 1, 63), 256, 59392>>>(pnewxinb, pwp + OFF_WL1, pl1,
                                                    nullptr, BB, 512, 2 * RAWF, 160);
    prelu_kernel<<<(BB * 512 + 255) / 256, 256>>>(pl1, BB * 512, pa, pl1b);
    init_bias_kernel<<<(BB * 256 + 255) / 256, 256>>>(pnewx, bl2, BB * 256, 255);
    gemm_bf16<0, 1><<<dim3(1, 1, 8), 256, 59392>>>(pl1b, pwp + OFF_WL2, pnewx,
                                                   nullptr, BB, HH, 512, 64);
    prelu_kernel<<<(BB * 256 + 255) / 256, 256>>>(pnewx, BB * 256, pa, nullptr);

    // ---------- branch 3 ----------
    gemm_bf16<0, 0><<<nodeGrid, 256, 59392>>>(pdatab, pwp + OFF_WC0, nullptr,
                                              (uint16_t*)phb, NN, HH, RAWF, RAWF);
    gather_kernel<<<NN / 8, 256>>>((const uint4*)phb, bc0, prs1, psrc1, pdinv1, paggb);
    pool_kernel<0><<<BB, 1024>>>((const uint2*)paggb, pp0);
    gemm_bf16<0, 0><<<nodeGrid, 256, 59392>>>(paggb, pwp + OFF_WC1, nullptr,
                                              (uint16_t*)phb, NN, HH, HH, HH);
    gather_kernel<<<NN / 8, 256>>>((const uint4*)phb, bc1, prs1, psrc1, pdinv1, paggb);
    pool_kernel<0><<<BB, 1024>>>((const uint2*)paggb, pp1);
    gemm_bf16<0, 0><<<nodeGrid, 256, 59392>>>(paggb, pwp + OFF_WC2, nullptr,
                                              (uint16_t*)phb, NN, HH, HH, HH);
    gather_kernel<<<NN / 8, 256>>>((const uint4*)phb, bc2, prs1, psrc1, pdinv1, paggb);
    pool_kernel<0><<<BB, 1024>>>((const uint2*)paggb, pp2);

    // ---------- final ----------
    final_kernel<<<BB, 256>>>(W5, b5, out);
}

// round 13
// speedup vs baseline: 1.5528x; 1.0486x over previous
#include <cuda_runtime.h>
#include <cuda_bf16.h>
#include <cstdint>

#define NN   20000
#define BB   128
#define EE   320000
#define FIN  768
#define RAWF 5000
#define HH   256
#define CC   4

// ---------------- scratch (device globals) ----------------
__device__ __align__(16) __nv_bfloat16 g_hb[NN * HH];    // GEMM output h (bf16)
__device__ __align__(16) __nv_bfloat16 g_aggb[NN * HH];  // activation (bf16)
__device__ __align__(16) float g_l1[BB * 512];
__device__ __align__(16) __nv_bfloat16 g_l1b[BB * 512];
__device__ __align__(16) float g_newx[BB * HH];
__device__ __align__(16) float g_xmax[BB * HH];
__device__ __align__(16) float g_p0[BB * HH];
__device__ __align__(16) float g_p1[BB * HH];
__device__ __align__(16) float g_p2[BB * HH];
__device__ __align__(16) __nv_bfloat16 g_newxinb[BB * 2 * RAWF];
// packed k2-interleaved bf16 weights
#define OFF_W1   0
#define OFF_WC0  98304
#define OFF_WC1  738304
#define OFF_WC2  771072
#define OFF_WL1  803840
#define OFF_WL2  3363840
__device__ __align__(16) uint32_t g_wp[3429376];
__device__ __align__(16) int   g_cnt0[NN];
__device__ __align__(16) int   g_cnt1[NN];
__device__ int   g_cur0[NN];
__device__ int   g_cur1[NN];
__device__ __align__(16) int   g_rs0[NN + 4];
__device__ __align__(16) int   g_rs1[NN + 4];
__device__ int   g_src0[EE];
__device__ int   g_src1[EE];
__device__ __align__(16) float g_dinv0[NN];
__device__ __align__(16) float g_dinv1[NN];
__device__ int   g_bounds[BB + 1];

// ---------------- helpers ----------------
__device__ __forceinline__ uint32_t packbf(float lo, float hi) {
    uint32_t r;
    asm("cvt.rn.bf16x2.f32 %0, %1, %2;" : "=r"(r) : "f"(hi), "f"(lo));
    return r;
}
__device__ __forceinline__ void cpasync16(uint32_t dst, const void* src, bool ok) {
    int ss = ok ? 16 : 0;
    asm volatile("cp.async.cg.shared.global [%0], [%1], 16, %2;\n" :: "r"(dst), "l"(src), "r"(ss));
}
__device__ __forceinline__ void cpcommit() { asm volatile("cp.async.commit_group;\n"); }
__device__ __forceinline__ void cpwait0()  { asm volatile("cp.async.wait_group 0;\n"); }
__device__ __forceinline__ void unp(uint32_t w, float& a, float& b) {
    a = __uint_as_float(w << 16);
    b = __uint_as_float(w & 0xffff0000u);
}

// ---------------- segment bounds ----------------
__global__ void bounds_kernel(const int* __restrict__ batch) {
    int b = threadIdx.x;
    if (b > BB) return;
    int lo = 0, hi = NN;
    while (lo < hi) {
        int mid = (lo + hi) >> 1;
        if (batch[mid] < b) lo = mid + 1; else hi = mid;
    }
    g_bounds[b] = lo;
}

// ---------------- weight prep ----------------
__global__ void prep_w_kernel(const float* __restrict__ W, uint32_t* __restrict__ Wp,
                              int cnt, int N) {
    int idx = blockIdx.x * blockDim.x + threadIdx.x;
    if (idx >= cnt) return;
    int p = idx / N, n = idx - p * N;
    Wp[idx] = packbf(W[(size_t)(2 * p) * N + n], W[(size_t)(2 * p + 1) * N + n]);
}

// ---------------- CSR build (both graphs in shared kernels) ----------------
__global__ void zero2_kernel() {
    int i = blockIdx.x * blockDim.x + threadIdx.x;
    if (i < NN) { g_cnt0[i] = 0; g_cnt1[i] = 0; }
}
__global__ void hist2_kernel(const int* __restrict__ ei, const int* __restrict__ rei) {
    int i = blockIdx.x * blockDim.x + threadIdx.x;
    if (i >= EE / 4) return;
    const int* dst;
    int* cnt;
    if (blockIdx.y == 0) { dst = ei + EE;  cnt = g_cnt0; }
    else                 { dst = rei + EE; cnt = g_cnt1; }
    int4 d = ((const int4*)dst)[i];
    atomicAdd(&cnt[d.x], 1);
    atomicAdd(&cnt[d.y], 1);
    atomicAdd(&cnt[d.z], 1);
    atomicAdd(&cnt[d.w], 1);
}
__global__ void scan2_kernel() {
    __shared__ int wsum[32];
    int g = blockIdx.x;
    const int* cnt = g ? g_cnt1 : g_cnt0;
    int* rs        = g ? g_rs1  : g_rs0;
    int* cur       = g ? g_cur1 : g_cur0;
    float* dinv    = g ? g_dinv1 : g_dinv0;
    int t = threadIdx.x;
    int lane = t & 31, wid = t >> 5;
    int c[20];
    const int4* c4 = (const int4*)cnt;
#pragma unroll
    for (int i = 0; i < 5; i++) {
        int idx4 = t * 5 + i;
        int4 v = (idx4 < 5000) ? c4[idx4] : make_int4(0, 0, 0, 0);
        c[i * 4 + 0] = v.x; c[i * 4 + 1] = v.y; c[i * 4 + 2] = v.z; c[i * 4 + 3] = v.w;
    }
    int loc[20];
    int s = 0;
#pragma unroll
    for (int i = 0; i < 20; i++) { loc[i] = s; s += c[i]; }
    int x = s;
#pragma unroll
    for (int off = 1; off < 32; off <<= 1) {
        int y = __shfl_up_sync(0xffffffffu, x, off);
        if (lane >= off) x += y;
    }
    if (lane == 31) wsum[wid] = x;
    __syncthreads();
    if (wid == 0) {
        int v = wsum[lane];
#pragma unroll
        for (int off = 1; off < 32; off <<= 1) {
            int y = __shfl_up_sync(0xffffffffu, v, off);
            if (lane >= off) v += y;
        }
        wsum[lane] = v;
    }
    __syncthreads();
    int offset = (wid ? wsum[wid - 1] : 0) + (x - s);
    int4* rs4 = (int4*)rs;
    int4* cu4 = (int4*)cur;
    float4* dv4 = (float4*)dinv;
#pragma unroll
    for (int i = 0; i < 5; i++) {
        int idx4 = t * 5 + i;
        if (idx4 < 5000) {
            int4 r; float4 d;
            r.x = offset + loc[i * 4 + 0]; d.x = rsqrtf((float)(c[i * 4 + 0] + 1));
            r.y = offset + loc[i * 4 + 1]; d.y = rsqrtf((float)(c[i * 4 + 1] + 1));
            r.z = offset + loc[i * 4 + 2]; d.z = rsqrtf((float)(c[i * 4 + 2] + 1));
            r.w = offset + loc[i * 4 + 3]; d.w = rsqrtf((float)(c[i * 4 + 3] + 1));
            rs4[idx4] = r; cu4[idx4] = r; dv4[idx4] = d;
        }
    }
    if (t == 0) rs[NN] = EE;
}
__global__ void fill2_kernel(const int* __restrict__ ei, const int* __restrict__ rei) {
    int i = blockIdx.x * blockDim.x + threadIdx.x;
    if (i >= EE / 4) return;
    const int* src;
    const int* dst;
    int* cur;
    int* outp;
    if (blockIdx.y == 0) { src = ei;  dst = ei + EE;  cur = g_cur0; outp = g_src0; }
    else                 { src = rei; dst = rei + EE; cur = g_cur1; outp = g_src1; }
    int4 d = ((const int4*)dst)[i];
    int4 s = ((const int4*)src)[i];
    outp[atomicAdd(&cur[d.x], 1)] = s.x;
    outp[atomicAdd(&cur[d.y], 1)] = s.y;
    outp[atomicAdd(&cur[d.z], 1)] = s.z;
    outp[atomicAdd(&cur[d.w], 1)] = s.w;
}

// ---------------- fused GCN aggregation + relu (bf16 in/out), edge loop unrolled x4 ----------------
__global__ __launch_bounds__(256)
void gather_kernel(const uint4* __restrict__ hb, const float* __restrict__ bias,
                   const int* __restrict__ rs, const int* __restrict__ csr,
                   const float* __restrict__ dinv, __nv_bfloat16* __restrict__ outb) {
    int node = blockIdx.x * 8 + (threadIdx.x >> 5);
    int lane = threadIdx.x & 31;
    float di = dinv[node];
    float sw = di * di;
    float acc[8];
    {
        uint4 hv = hb[(size_t)node * 32 + lane];
        float f0, f1;
        unp(hv.x, f0, f1); acc[0] = f0 * sw; acc[1] = f1 * sw;
        unp(hv.y, f0, f1); acc[2] = f0 * sw; acc[3] = f1 * sw;
        unp(hv.z, f0, f1); acc[4] = f0 * sw; acc[5] = f1 * sw;
        unp(hv.w, f0, f1); acc[6] = f0 * sw; acc[7] = f1 * sw;
    }
    int e0 = rs[node], e1 = rs[node + 1];
    int e = e0;
    for (; e + 4 <= e1; e += 4) {
        int s0 = csr[e], s1 = csr[e + 1], s2 = csr[e + 2], s3 = csr[e + 3];
        float w0 = dinv[s0] * di, w1 = dinv[s1] * di;
        float w2 = dinv[s2] * di, w3 = dinv[s3] * di;
        uint4 h0 = hb[(size_t)s0 * 32 + lane];
        uint4 h1 = hb[(size_t)s1 * 32 + lane];
        uint4 h2 = hb[(size_t)s2 * 32 + lane];
        uint4 h3 = hb[(size_t)s3 * 32 + lane];
        float f0, f1;
        unp(h0.x, f0, f1); acc[0] = fmaf(f0, w0, acc[0]); acc[1] = fmaf(f1, w0, acc[1]);
        unp(h0.y, f0, f1); acc[2] = fmaf(f0, w0, acc[2]); acc[3] = fmaf(f1, w0, acc[3]);
        unp(h0.z, f0, f1); acc[4] = fmaf(f0, w0, acc[4]); acc[5] = fmaf(f1, w0, acc[5]);
        unp(h0.w, f0, f1); acc[6] = fmaf(f0, w0, acc[6]); acc[7] = fmaf(f1, w0, acc[7]);
        unp(h1.x, f0, f1); acc[0] = fmaf(f0, w1, acc[0]); acc[1] = fmaf(f1, w1, acc[1]);
        unp(h1.y, f0, f1); acc[2] = fmaf(f0, w1, acc[2]); acc[3] = fmaf(f1, w1, acc[3]);
        unp(h1.z, f0, f1); acc[4] = fmaf(f0, w1, acc[4]); acc[5] = fmaf(f1, w1, acc[5]);
        unp(h1.w, f0, f1); acc[6] = fmaf(f0, w1, acc[6]); acc[7] = fmaf(f1, w1, acc[7]);
        unp(h2.x, f0, f1); acc[0] = fmaf(f0, w2, acc[0]); acc[1] = fmaf(f1, w2, acc[1]);
        unp(h2.y, f0, f1); acc[2] = fmaf(f0, w2, acc[2]); acc[3] = fmaf(f1, w2, acc[3]);
        unp(h2.z, f0, f1); acc[4] = fmaf(f0, w2, acc[4]); acc[5] = fmaf(f1, w2, acc[5]);
        unp(h2.w, f0, f1); acc[6] = fmaf(f0, w2, acc[6]); acc[7] = fmaf(f1, w2, acc[7]);
        unp(h3.x, f0, f1); acc[0] = fmaf(f0, w3, acc[0]); acc[1] = fmaf(f1, w3, acc[1]);
        unp(h3.y, f0, f1); acc[2] = fmaf(f0, w3, acc[2]); acc[3] = fmaf(f1, w3, acc[3]);
        unp(h3.z, f0, f1); acc[4] = fmaf(f0, w3, acc[4]); acc[5] = fmaf(f1, w3, acc[5]);
        unp(h3.w, f0, f1); acc[6] = fmaf(f0, w3, acc[6]); acc[7] = fmaf(f1, w3, acc[7]);
    }
    for (; e < e1; e++) {
        int s = csr[e];
        float w = dinv[s] * di;
        uint4 hv = hb[(size_t)s * 32 + lane];
        float f0, f1;
        unp(hv.x, f0, f1); acc[0] = fmaf(f0, w, acc[0]); acc[1] = fmaf(f1, w, acc[1]);
        unp(hv.y, f0, f1); acc[2] = fmaf(f0, w, acc[2]); acc[3] = fmaf(f1, w, acc[3]);
        unp(hv.z, f0, f1); acc[4] = fmaf(f0, w, acc[4]); acc[5] = fmaf(f1, w, acc[5]);
        unp(hv.w, f0, f1); acc[6] = fmaf(f0, w, acc[6]); acc[7] = fmaf(f1, w, acc[7]);
    }
    float4 bb0 = ((const float4*)bias)[2 * lane];
    float4 bb1 = ((const float4*)bias)[2 * lane + 1];
    float v[8];
    v[0] = fmaxf(acc[0] + bb0.x, 0.f); v[1] = fmaxf(acc[1] + bb0.y, 0.f);
    v[2] = fmaxf(acc[2] + bb0.z, 0.f); v[3] = fmaxf(acc[3] + bb0.w, 0.f);
    v[4] = fmaxf(acc[4] + bb1.x, 0.f); v[5] = fmaxf(acc[5] + bb1.y, 0.f);
    v[6] = fmaxf(acc[6] + bb1.z, 0.f); v[7] = fmaxf(acc[7] + bb1.w, 0.f);
    uint4 o;
    o.x = packbf(v[0], v[1]); o.y = packbf(v[2], v[3]);
    o.z = packbf(v[4], v[5]); o.w = packbf(v[6], v[7]);
    ((uint4*)outb)[(size_t)node * 32 + lane] = o;
}

// ---------------- pooling over contiguous segments (bf16 input, no atomics) ----------------
template<int ISMAX>
__global__ void pool_kernel(const uint2* __restrict__ xb, float* __restrict__ out) {
    __shared__ float red[16 * 256];
    int b = blockIdx.x, t = threadIdx.x;
    int q = t & 63;
    int rp = t >> 6;         // 0..15
    int s = g_bounds[b], e = g_bounds[b + 1];
    float a0 = 0.f, a1 = 0.f, a2 = 0.f, a3 = 0.f;
    for (int i = s + rp; i < e; i += 16) {
        uint2 v = xb[(size_t)i * 64 + q];
        float f0, f1, f2, f3;
        unp(v.x, f0, f1); unp(v.y, f2, f3);
        if (ISMAX) {
            a0 = fmaxf(a0, f0); a1 = fmaxf(a1, f1);
            a2 = fmaxf(a2, f2); a3 = fmaxf(a3, f3);
        } else {
            a0 += f0; a1 += f1; a2 += f2; a3 += f3;
        }
    }
    red[rp * 256 + q * 4 + 0] = a0;
    red[rp * 256 + q * 4 + 1] = a1;
    red[rp * 256 + q * 4 + 2] = a2;
    red[rp * 256 + q * 4 + 3] = a3;
    __syncthreads();
    if (t < 256) {
        float r = red[t];
#pragma unroll
        for (int p = 1; p < 16; p++) {
            if (ISMAX) r = fmaxf(r, red[p * 256 + t]);
            else       r += red[p * 256 + t];
        }
        out[b * HH + t] = r;
    }
}

// ---------------- bf16 tensor-core GEMM (mma.sync) ----------------
template<int AF32, int ATOMIC>
__global__ __launch_bounds__(256)
void gemm_bf16(const void* __restrict__ Av, const uint32_t* __restrict__ Bp,
               float* __restrict__ C, uint16_t* __restrict__ Cb,
               int M, int N, int K, int KS) {
    constexpr int ABUFSZ = AF32 ? 23040 : 12800;
    constexpr int BBUFSZ = 16896;
    extern __shared__ __align__(16) uint8_t smraw[];
    int tid = threadIdx.x;
    int lane = tid & 31, wid = tid >> 5;
    int warp_m = wid & 1, warp_n = wid >> 1;
    int bm = blockIdx.y * 160;
    int bn = blockIdx.x * 256;
    int kbeg = blockIdx.z * KS;
    int kend = min(K, kbeg + KS);
    int ntiles = (kend - kbeg + 31) >> 5;
    uint32_t sbase = (uint32_t)__cvta_generic_to_shared(smraw);

    float acc[5][8][4];
#pragma unroll
    for (int mt = 0; mt < 5; mt++)
#pragma unroll
        for (int nt = 0; nt < 8; nt++)
#pragma unroll
            for (int q = 0; q < 4; q++) acc[mt][nt][q] = 0.f;

    auto prefetch = [&](int tile, int pbuf) {
        int k0 = kbeg + tile * 32;
        if (AF32) {
            const float* A = (const float*)Av;
#pragma unroll
            for (int i = 0; i < 5; i++) {
                int c = tid + 256 * i;
                int row = c >> 3, ch = c & 7;
                bool ok = (bm + row < M) && (k0 + ch * 4 < kend);
                const void* src = A + (size_t)(bm + row) * K + k0 + ch * 4;
                cpasync16(sbase + pbuf * ABUFSZ + row * 144 + ch * 16, ok ? src : A, ok);
            }
        } else {
            const __nv_bfloat16* A = (const __nv_bfloat16*)Av;
#pragma unroll
            for (int i = 0; i < 3; i++) {
                int c = tid + 256 * i;
                if (c < 640) {
                    int row = c >> 2, ch = c & 3;
                    bool ok = (bm + row < M) && (k0 + ch * 8 < kend);
                    const void* src = A + (size_t)(bm + row) * K + k0 + ch * 8;
                    cpasync16(sbase + pbuf * ABUFSZ + row * 80 + ch * 16, ok ? src : A, ok);
                }
            }
        }
#pragma unroll
        for (int i = 0; i < 4; i++) {
            int c = tid + 256 * i;
            int row = c >> 6, seg = c & 63;
            bool ok = (k0 + 2 * row < kend);
            const void* src = Bp + (size_t)(k0 / 2 + row) * N + bn + seg * 4;
            cpasync16(sbase + 2 * ABUFSZ + pbuf * BBUFSZ + row * 1056 + seg * 16,
                      ok ? src : Bp, ok);
        }
        cpcommit();
    };

    int buf = 0;
    prefetch(0, 0);
    for (int t = 0; t < ntiles; t++) {
        cpwait0();
        __syncthreads();
        if (t + 1 < ntiles) prefetch(t + 1, buf ^ 1);

        const uint32_t* Bsb = (const uint32_t*)(smraw + 2 * ABUFSZ + buf * BBUFSZ);
#pragma unroll
        for (int ks = 0; ks < 2; ks++) {
            int kk0 = ks * 16 + 2 * (lane & 3);
            uint32_t af[5][4];
            if (AF32) {
                const float* Asf = (const float*)(smraw + buf * ABUFSZ);
#pragma unroll
                for (int mt = 0; mt < 5; mt++) {
                    int r = warp_m * 80 + mt * 16 + (lane >> 2);
                    float2 v0 = *(const float2*)(Asf + r * 36 + kk0);
                    float2 v1 = *(const float2*)(Asf + (r + 8) * 36 + kk0);
                    float2 v2 = *(const float2*)(Asf + r * 36 + kk0 + 8);
                    float2 v3 = *(const float2*)(Asf + (r + 8) * 36 + kk0 + 8);
                    af[mt][0] = packbf(v0.x, v0.y);
                    af[mt][1] = packbf(v1.x, v1.y);
                    af[mt][2] = packbf(v2.x, v2.y);
                    af[mt][3] = packbf(v3.x, v3.y);
                }
            } else {
                const uint16_t* Asb = (const uint16_t*)(smraw + buf * ABUFSZ);
#pragma unroll
                for (int mt = 0; mt < 5; mt++) {
                    int r = warp_m * 80 + mt * 16 + (lane >> 2);
                    af[mt][0] = *(const uint32_t*)(Asb + r * 40 + kk0);
                    af[mt][1] = *(const uint32_t*)(Asb + (r + 8) * 40 + kk0);
                    af[mt][2] = *(const uint32_t*)(Asb + r * 40 + kk0 + 8);
                    af[mt][3] = *(const uint32_t*)(Asb + (r + 8) * 40 + kk0 + 8);
                }
            }
            int p = ks * 8 + (lane & 3);
#pragma unroll
            for (int nt = 0; nt < 8; nt++) {
                int cl = warp_n * 64 + nt * 8 + (lane >> 2);
                uint32_t b0 = Bsb[p * 264 + cl];
                uint32_t b1 = Bsb[(p + 4) * 264 + cl];
#pragma unroll
                for (int mt = 0; mt < 5; mt++) {
                    asm volatile(
                        "mma.sync.aligned.m16n8k16.row.col.f32.bf16.bf16.f32 "
                        "{%0,%1,%2,%3}, {%4,%5,%6,%7}, {%8,%9}, {%0,%1,%2,%3};\n"
                        : "+f"(acc[mt][nt][0]), "+f"(acc[mt][nt][1]),
                          "+f"(acc[mt][nt][2]), "+f"(acc[mt][nt][3])
                        : "r"(af[mt][0]), "r"(af[mt][1]), "r"(af[mt][2]), "r"(af[mt][3]),
                          "r"(b0), "r"(b1));
                }
            }
        }
        buf ^= 1;
        __syncthreads();
    }

#pragma unroll
    for (int mt = 0; mt < 5; mt++) {
#pragma unroll
        for (int nt = 0; nt < 8; nt++) {
            int row = bm + warp_m * 80 + mt * 16 + (lane >> 2);
            int col = bn + warp_n * 64 + nt * 8 + 2 * (lane & 3);
            if (ATOMIC) {
                if (row < M) {
                    atomicAdd(&C[(size_t)row * N + col],     acc[mt][nt][0]);
                    atomicAdd(&C[(size_t)row * N + col + 1], acc[mt][nt][1]);
                }
                if (row + 8 < M) {
                    atomicAdd(&C[(size_t)(row + 8) * N + col],     acc[mt][nt][2]);
                    atomicAdd(&C[(size_t)(row + 8) * N + col + 1], acc[mt][nt][3]);
                }
            } else {
                uint32_t* Cb32 = (uint32_t*)Cb;
                if (row < M)
                    Cb32[((size_t)row * N + col) >> 1] = packbf(acc[mt][nt][0], acc[mt][nt][1]);
                if (row + 8 < M)
                    Cb32[((size_t)(row + 8) * N + col) >> 1] = packbf(acc[mt][nt][2], acc[mt][nt][3]);
            }
        }
    }
}

// ---------------- branch2 front: segment mean only (no datab write) ----------------
__global__ void meanraw_kernel(const float* __restrict__ dx) {
    int f = blockIdx.x * 256 + threadIdx.x;
    if (f >= RAWF) return;
    int b = blockIdx.y;
    int s = g_bounds[b], e = g_bounds[b + 1];
    float acc = 0.f;
    for (int i = s; i < e; i++) acc += dx[(size_t)i * RAWF + f];
    int cnt = e - s; if (cnt < 1) cnt = 1;
    g_newxinb[(size_t)b * (2 * RAWF) + f] = __float2bfloat16(acc / (float)cnt);
}
__global__ void root_kernel(const float* __restrict__ dx, const int* __restrict__ root) {
    int f = blockIdx.x * 256 + threadIdx.x;
    if (f >= RAWF) return;
    int b = blockIdx.y;
    g_newxinb[(size_t)b * (2 * RAWF) + RAWF + f] =
        __float2bfloat16(dx[(size_t)root[b] * RAWF + f]);
}

// ---------------- small elementwise ----------------
__global__ void init_bias_kernel(float* __restrict__ p, const float* __restrict__ bias,
                                 int n, int mask) {
    int i = blockIdx.x * blockDim.x + threadIdx.x;
    if (i < n) p[i] = bias[i & mask];
}
__global__ void prelu_kernel(float* __restrict__ p, int n, const float* __restrict__ pa,
                             __nv_bfloat16* __restrict__ outb) {
    int i = blockIdx.x * blockDim.x + threadIdx.x;
    if (i >= n) return;
    float a = *pa;
    float v = p[i];
    v = v >= 0.f ? v : a * v;
    if (outb) outb[i] = __float2bfloat16(v);
    else p[i] = v;
}

// ---------------- final projection + log_softmax ----------------
__global__ void final_kernel(const float* __restrict__ W5, const float* __restrict__ b5,
                             float* __restrict__ out) {
    __shared__ float red[4][256];
    int b = blockIdx.x, t = threadIdx.x;
    int cnt = g_bounds[b + 1] - g_bounds[b];
    float inv = 1.f / (float)(cnt < 1 ? 1 : cnt);
    float acc[4] = {0.f, 0.f, 0.f, 0.f};
    for (int k = t; k < 5 * HH; k += 256) {
        int seg = k >> 8, f = k & 255;
        float v;
        if      (seg == 0) v = g_p0[b * HH + f] * inv;
        else if (seg == 1) v = g_p1[b * HH + f] * inv;
        else if (seg == 2) v = g_p2[b * HH + f] * inv;
        else if (seg == 3) v = g_newx[b * HH + f];
        else               v = g_xmax[b * HH + f];
#pragma unroll
        for (int c = 0; c < 4; c++) acc[c] += v * W5[k * 4 + c];
    }
#pragma unroll
    for (int c = 0; c < 4; c++) red[c][t] = acc[c];
    __syncthreads();
    for (int s = 128; s > 0; s >>= 1) {
        if (t < s) {
#pragma unroll
            for (int c = 0; c < 4; c++) red[c][t] += red[c][t + s];
        }
        __syncthreads();
    }
    if (t == 0) {
        float z[4];
#pragma unroll
        for (int c = 0; c < 4; c++) z[c] = red[c][0] + b5[c];
        float m = z[0];
#pragma unroll
        for (int c = 1; c < 4; c++) m = fmaxf(m, z[c]);
        float ssum = 0.f;
#pragma unroll
        for (int c = 0; c < 4; c++) ssum += expf(z[c] - m);
        float ls = logf(ssum);
#pragma unroll
        for (int c = 0; c < 4; c++) out[b * 4 + c] = z[c] - m - ls;
    }
}

// ---------------- host ----------------
extern "C" void kernel_launch(void* const* d_in, const int* in_sizes, int n_in,
                              void* d_out, int out_size) {
    const float* graph_x = (const float*)d_in[0];
    const float* data_x  = (const float*)d_in[2];
    const int*   ei      = (const int*)d_in[3];
    const int*   rei     = (const int*)d_in[4];
    const int*   gbatch  = (const int*)d_in[5];
    const int*   root    = (const int*)d_in[7];
    const float* W1  = (const float*)d_in[8];
    const float* b1  = (const float*)d_in[9];
    const float* Wc0 = (const float*)d_in[10];
    const float* bc0 = (const float*)d_in[11];
    const float* Wc1 = (const float*)d_in[12];
    const float* bc1 = (const float*)d_in[13];
    const float* Wc2 = (const float*)d_in[14];
    const float* bc2 = (const float*)d_in[15];
    const float* Wl1 = (const float*)d_in[16];
    const float* bl1 = (const float*)d_in[17];
    const float* Wl2 = (const float*)d_in[18];
    const float* bl2 = (const float*)d_in[19];
    const float* pa  = (const float*)d_in[20];
    const float* W5  = (const float*)d_in[21];
    const float* b5  = (const float*)d_in[22];
    float* out = (float*)d_out;

    static bool s_init = false;
    static cudaStream_t s1;
    static cudaEvent_t evStart, evBounds, evB2;
    if (!s_init) {
        cudaStreamCreateWithFlags(&s1, cudaStreamNonBlocking);
        cudaEventCreateWithFlags(&evStart,  cudaEventDisableTiming);
        cudaEventCreateWithFlags(&evBounds, cudaEventDisableTiming);
        cudaEventCreateWithFlags(&evB2,     cudaEventDisableTiming);
        cudaFuncSetAttribute(gemm_bf16<1, 0>, cudaFuncAttributeMaxDynamicSharedMemorySize, 79872);
        cudaFuncSetAttribute(gemm_bf16<0, 0>, cudaFuncAttributeMaxDynamicSharedMemorySize, 59392);
        cudaFuncSetAttribute(gemm_bf16<0, 1>, cudaFuncAttributeMaxDynamicSharedMemorySize, 59392);
        s_init = true;
    }

    __nv_bfloat16 *phb, *paggb, *pl1b, *pnewxinb;
    float *pl1, *pnewx, *pxmax, *pp0, *pp1, *pp2;
    int *prs0, *prs1, *psrc0, *psrc1;
    float *pdinv0, *pdinv1;
    uint32_t *pwp;
    cudaGetSymbolAddress((void**)&phb,      g_hb);
    cudaGetSymbolAddress((void**)&paggb,    g_aggb);
    cudaGetSymbolAddress((void**)&pl1,      g_l1);
    cudaGetSymbolAddress((void**)&pl1b,     g_l1b);
    cudaGetSymbolAddress((void**)&pnewx,    g_newx);
    cudaGetSymbolAddress((void**)&pxmax,    g_xmax);
    cudaGetSymbolAddress((void**)&pp0,      g_p0);
    cudaGetSymbolAddress((void**)&pp1,      g_p1);
    cudaGetSymbolAddress((void**)&pp2,      g_p2);
    cudaGetSymbolAddress((void**)&pnewxinb, g_newxinb);
    cudaGetSymbolAddress((void**)&prs0,     g_rs0);
    cudaGetSymbolAddress((void**)&prs1,     g_rs1);
    cudaGetSymbolAddress((void**)&psrc0,    g_src0);
    cudaGetSymbolAddress((void**)&psrc1,    g_src1);
    cudaGetSymbolAddress((void**)&pdinv0,   g_dinv0);
    cudaGetSymbolAddress((void**)&pdinv1,   g_dinv1);
    cudaGetSymbolAddress((void**)&pwp,      g_wp);

    dim3 nodeGrid(1, (NN + 159) / 160, 1);   // 125 CTAs, one wave
    const int NB = (NN + 255) / 256;
    dim3 edgeGrid((EE / 4 + 255) / 256, 2);
    dim3 rawGrid((RAWF + 255) / 256, BB);

    // ===== stream 0 (default): bounds + CSR + branch1 + branch3 =====
    bounds_kernel<<<1, 160>>>(gbatch);
    cudaEventRecord(evBounds, 0);
    cudaStreamWaitEvent(s1, evBounds, 0);

    zero2_kernel<<<NB, 256>>>();
    hist2_kernel<<<edgeGrid, 256>>>(ei, rei);
    scan2_kernel<<<2, 1024>>>();
    fill2_kernel<<<edgeGrid, 256>>>(ei, rei);

    prep_w_kernel<<<((FIN / 2) * HH + 255) / 256, 256>>>(W1,  pwp + OFF_W1,  (FIN / 2) * HH, HH);
    prep_w_kernel<<<((RAWF / 2) * HH + 255) / 256, 256>>>(Wc0, pwp + OFF_WC0, (RAWF / 2) * HH, HH);
    prep_w_kernel<<<((HH / 2) * HH + 255) / 256, 256>>>(Wc1, pwp + OFF_WC1, (HH / 2) * HH, HH);
    prep_w_kernel<<<((HH / 2) * HH + 255) / 256, 256>>>(Wc2, pwp + OFF_WC2, (HH / 2) * HH, HH);

    // branch 1
    gemm_bf16<1, 0><<<nodeGrid, 256, 79872>>>(graph_x, pwp + OFF_W1, nullptr,
                                              (uint16_t*)phb, NN, HH, FIN, FIN);
    gather_kernel<<<NN / 8, 256>>>((const uint4*)phb, b1, prs0, psrc0, pdinv0, paggb);
    pool_kernel<1><<<BB, 1024>>>((const uint2*)paggb, pxmax);

    // branch 3 (layer 0 reads data_x directly: fp32-A GEMM, independent of stream 1)
    gemm_bf16<1, 0><<<nodeGrid, 256, 79872>>>(data_x, pwp + OFF_WC0, nullptr,
                                              (uint16_t*)phb, NN, HH, RAWF, RAWF);
    gather_kernel<<<NN / 8, 256>>>((const uint4*)phb, bc0, prs1, psrc1, pdinv1, paggb);
    pool_kernel<0><<<BB, 1024>>>((const uint2*)paggb, pp0);
    gemm_bf16<0, 0><<<nodeGrid, 256, 59392>>>(paggb, pwp + OFF_WC1, nullptr,
                                              (uint16_t*)phb, NN, HH, HH, HH);
    gather_kernel<<<NN / 8, 256>>>((const uint4*)phb, bc1, prs1, psrc1, pdinv1, paggb);
    pool_kernel<0><<<BB, 1024>>>((const uint2*)paggb, pp1);
    gemm_bf16<0, 0><<<nodeGrid, 256, 59392>>>(paggb, pwp + OFF_WC2, nullptr,
                                              (uint16_t*)phb, NN, HH, HH, HH);
    gather_kernel<<<NN / 8, 256>>>((const uint4*)phb, bc2, prs1, psrc1, pdinv1, paggb);
    pool_kernel<0><<<BB, 1024>>>((const uint2*)paggb, pp2);

    // ===== stream 1: branch 2 (memory-bound; overlaps with tensor-bound stream 0) =====
    prep_w_kernel<<<(RAWF * 512 + 255) / 256, 256, 0, s1>>>(Wl1, pwp + OFF_WL1, RAWF * 512, 512);
    prep_w_kernel<<<(256 * HH + 255) / 256, 256, 0, s1>>>(Wl2, pwp + OFF_WL2, 256 * HH, HH);
    meanraw_kernel<<<rawGrid, 256, 0, s1>>>(data_x);
    root_kernel<<<rawGrid, 256, 0, s1>>>(data_x, root);
    init_bias_kernel<<<(BB * 512 + 255) / 256, 256, 0, s1>>>(pl1, bl1, BB * 512, 511);
    gemm_bf16<0, 1><<<dim3(2, 1, 63), 256, 59392, s1>>>(pnewxinb, pwp + OFF_WL1, pl1,
                                                        nullptr, BB, 512, 2 * RAWF, 160);
    prelu_kernel<<<(BB * 512 + 255) / 256, 256, 0, s1>>>(pl1, BB * 512, pa, pl1b);
    init_bias_kernel<<<(BB * 256 + 255) / 256, 256, 0, s1>>>(pnewx, bl2, BB * 256, 255);
    gemm_bf16<0, 1><<<dim3(1, 1, 8), 256, 59392, s1>>>(pl1b, pwp + OFF_WL2, pnewx,
                                                       nullptr, BB, HH, 512, 64);
    prelu_kernel<<<(BB * 256 + 255) / 256, 256, 0, s1>>>(pnewx, BB * 256, pa, nullptr);
    cudaEventRecord(evB2, s1);

    // ===== join + final =====
    cudaStreamWaitEvent(0, evB2, 0);
    final_kernel<<<BB, 256>>>(W5, b5, out);
}

// round 14
// speedup vs baseline: 1.6212x; 1.0440x over previous
#include <cuda_runtime.h>
#include <cuda_bf16.h>
#include <cstdint>

#define NN   20000
#define BB   128
#define EE   320000
#define FIN  768
#define RAWF 5000
#define HH   256
#define CC   4

// ---------------- scratch (device globals) ----------------
__device__ __align__(16) __nv_bfloat16 g_hb[NN * HH];    // GEMM output h (bf16)
__device__ __align__(16) __nv_bfloat16 g_aggb[NN * HH];  // activation (bf16)
__device__ __align__(16) float g_l1[BB * 512];
__device__ __align__(16) __nv_bfloat16 g_l1b[BB * 512];
__device__ __align__(16) float g_newx[BB * HH];
__device__ __align__(16) float g_xmax[BB * HH];
__device__ __align__(16) float g_p0[BB * HH];
__device__ __align__(16) float g_p1[BB * HH];
__device__ __align__(16) float g_p2[BB * HH];
__device__ __align__(16) __nv_bfloat16 g_newxinb[BB * 2 * RAWF];
// packed k2-interleaved bf16 weights
#define OFF_W1   0
#define OFF_WC0  98304
#define OFF_WC1  738304
#define OFF_WC2  771072
#define OFF_WL1  803840
#define OFF_WL2  3363840
__device__ __align__(16) uint32_t g_wp[3429376];
__device__ __align__(16) int   g_cnt0[NN];
__device__ __align__(16) int   g_cnt1[NN];
__device__ int   g_cur0[NN];
__device__ int   g_cur1[NN];
__device__ __align__(16) int   g_rs0[NN + 4];
__device__ __align__(16) int   g_rs1[NN + 4];
__device__ int   g_src0[EE];
__device__ int   g_src1[EE];
__device__ __align__(16) float g_dinv0[NN];
__device__ __align__(16) float g_dinv1[NN];
__device__ int   g_bounds[BB + 1];

// ---------------- helpers ----------------
__device__ __forceinline__ uint32_t packbf(float lo, float hi) {
    uint32_t r;
    asm("cvt.rn.bf16x2.f32 %0, %1, %2;" : "=r"(r) : "f"(hi), "f"(lo));
    return r;
}
__device__ __forceinline__ void cpasync16(uint32_t dst, const void* src, bool ok) {
    int ss = ok ? 16 : 0;
    asm volatile("cp.async.cg.shared.global [%0], [%1], 16, %2;\n" :: "r"(dst), "l"(src), "r"(ss));
}
__device__ __forceinline__ void cpcommit() { asm volatile("cp.async.commit_group;\n"); }
__device__ __forceinline__ void cpwait0()  { asm volatile("cp.async.wait_group 0;\n"); }
__device__ __forceinline__ void unp(uint32_t w, float& a, float& b) {
    a = __uint_as_float(w << 16);
    b = __uint_as_float(w & 0xffff0000u);
}

// ---------------- segment bounds ----------------
__global__ void bounds_kernel(const int* __restrict__ batch) {
    int b = threadIdx.x;
    if (b > BB) return;
    int lo = 0, hi = NN;
    while (lo < hi) {
        int mid = (lo + hi) >> 1;
        if (batch[mid] < b) lo = mid + 1; else hi = mid;
    }
    g_bounds[b] = lo;
}

// ---------------- weight prep ----------------
__global__ void prep_w_kernel(const float* __restrict__ W, uint32_t* __restrict__ Wp,
                              int cnt, int N) {
    int idx = blockIdx.x * blockDim.x + threadIdx.x;
    if (idx >= cnt) return;
    int p = idx / N, n = idx - p * N;
    Wp[idx] = packbf(W[(size_t)(2 * p) * N + n], W[(size_t)(2 * p + 1) * N + n]);
}

// ---------------- CSR build (both graphs in shared kernels) ----------------
__global__ void zero2_kernel() {
    int i = blockIdx.x * blockDim.x + threadIdx.x;
    if (i < NN) { g_cnt0[i] = 0; g_cnt1[i] = 0; }
}
__global__ void hist2_kernel(const int* __restrict__ ei, const int* __restrict__ rei) {
    int i = blockIdx.x * blockDim.x + threadIdx.x;
    if (i >= EE / 4) return;
    const int* dst;
    int* cnt;
    if (blockIdx.y == 0) { dst = ei + EE;  cnt = g_cnt0; }
    else                 { dst = rei + EE; cnt = g_cnt1; }
    int4 d = ((const int4*)dst)[i];
    atomicAdd(&cnt[d.x], 1);
    atomicAdd(&cnt[d.y], 1);
    atomicAdd(&cnt[d.z], 1);
    atomicAdd(&cnt[d.w], 1);
}
__global__ void scan2_kernel() {
    __shared__ int wsum[32];
    int g = blockIdx.x;
    const int* cnt = g ? g_cnt1 : g_cnt0;
    int* rs        = g ? g_rs1  : g_rs0;
    int* cur       = g ? g_cur1 : g_cur0;
    float* dinv    = g ? g_dinv1 : g_dinv0;
    int t = threadIdx.x;
    int lane = t & 31, wid = t >> 5;
    int c[20];
    const int4* c4 = (const int4*)cnt;
#pragma unroll
    for (int i = 0; i < 5; i++) {
        int idx4 = t * 5 + i;
        int4 v = (idx4 < 5000) ? c4[idx4] : make_int4(0, 0, 0, 0);
        c[i * 4 + 0] = v.x; c[i * 4 + 1] = v.y; c[i * 4 + 2] = v.z; c[i * 4 + 3] = v.w;
    }
    int loc[20];
    int s = 0;
#pragma unroll
    for (int i = 0; i < 20; i++) { loc[i] = s; s += c[i]; }
    int x = s;
#pragma unroll
    for (int off = 1; off < 32; off <<= 1) {
        int y = __shfl_up_sync(0xffffffffu, x, off);
        if (lane >= off) x += y;
    }
    if (lane == 31) wsum[wid] = x;
    __syncthreads();
    if (wid == 0) {
        int v = wsum[lane];
#pragma unroll
        for (int off = 1; off < 32; off <<= 1) {
            int y = __shfl_up_sync(0xffffffffu, v, off);
            if (lane >= off) v += y;
        }
        wsum[lane] = v;
    }
    __syncthreads();
    int offset = (wid ? wsum[wid - 1] : 0) + (x - s);
    int4* rs4 = (int4*)rs;
    int4* cu4 = (int4*)cur;
    float4* dv4 = (float4*)dinv;
#pragma unroll
    for (int i = 0; i < 5; i++) {
        int idx4 = t * 5 + i;
        if (idx4 < 5000) {
            int4 r; float4 d;
            r.x = offset + loc[i * 4 + 0]; d.x = rsqrtf((float)(c[i * 4 + 0] + 1));
            r.y = offset + loc[i * 4 + 1]; d.y = rsqrtf((float)(c[i * 4 + 1] + 1));
            r.z = offset + loc[i * 4 + 2]; d.z = rsqrtf((float)(c[i * 4 + 2] + 1));
            r.w = offset + loc[i * 4 + 3]; d.w = rsqrtf((float)(c[i * 4 + 3] + 1));
            rs4[idx4] = r; cu4[idx4] = r; dv4[idx4] = d;
        }
    }
    if (t == 0) rs[NN] = EE;
}
__global__ void fill2_kernel(const int* __restrict__ ei, const int* __restrict__ rei) {
    int i = blockIdx.x * blockDim.x + threadIdx.x;
    if (i >= EE / 4) return;
    const int* src;
    const int* dst;
    int* cur;
    int* outp;
    if (blockIdx.y == 0) { src = ei;  dst = ei + EE;  cur = g_cur0; outp = g_src0; }
    else                 { src = rei; dst = rei + EE; cur = g_cur1; outp = g_src1; }
    int4 d = ((const int4*)dst)[i];
    int4 s = ((const int4*)src)[i];
    outp[atomicAdd(&cur[d.x], 1)] = s.x;
    outp[atomicAdd(&cur[d.y], 1)] = s.y;
    outp[atomicAdd(&cur[d.z], 1)] = s.z;
    outp[atomicAdd(&cur[d.w], 1)] = s.w;
}

// ---------------- fused GCN aggregation + relu (bf16 in/out), edge loop unrolled x4 ----------------
__global__ __launch_bounds__(256)
void gather_kernel(const uint4* __restrict__ hb, const float* __restrict__ bias,
                   const int* __restrict__ rs, const int* __restrict__ csr,
                   const float* __restrict__ dinv, __nv_bfloat16* __restrict__ outb) {
    int node = blockIdx.x * 8 + (threadIdx.x >> 5);
    int lane = threadIdx.x & 31;
    float di = dinv[node];
    float sw = di * di;
    float acc[8];
    {
        uint4 hv = hb[(size_t)node * 32 + lane];
        float f0, f1;
        unp(hv.x, f0, f1); acc[0] = f0 * sw; acc[1] = f1 * sw;
        unp(hv.y, f0, f1); acc[2] = f0 * sw; acc[3] = f1 * sw;
        unp(hv.z, f0, f1); acc[4] = f0 * sw; acc[5] = f1 * sw;
        unp(hv.w, f0, f1); acc[6] = f0 * sw; acc[7] = f1 * sw;
    }
    int e0 = rs[node], e1 = rs[node + 1];
    int e = e0;
    for (; e + 4 <= e1; e += 4) {
        int s0 = csr[e], s1 = csr[e + 1], s2 = csr[e + 2], s3 = csr[e + 3];
        float w0 = dinv[s0] * di, w1 = dinv[s1] * di;
        float w2 = dinv[s2] * di, w3 = dinv[s3] * di;
        uint4 h0 = hb[(size_t)s0 * 32 + lane];
        uint4 h1 = hb[(size_t)s1 * 32 + lane];
        uint4 h2 = hb[(size_t)s2 * 32 + lane];
        uint4 h3 = hb[(size_t)s3 * 32 + lane];
        float f0, f1;
        unp(h0.x, f0, f1); acc[0] = fmaf(f0, w0, acc[0]); acc[1] = fmaf(f1, w0, acc[1]);
        unp(h0.y, f0, f1); acc[2] = fmaf(f0, w0, acc[2]); acc[3] = fmaf(f1, w0, acc[3]);
        unp(h0.z, f0, f1); acc[4] = fmaf(f0, w0, acc[4]); acc[5] = fmaf(f1, w0, acc[5]);
        unp(h0.w, f0, f1); acc[6] = fmaf(f0, w0, acc[6]); acc[7] = fmaf(f1, w0, acc[7]);
        unp(h1.x, f0, f1); acc[0] = fmaf(f0, w1, acc[0]); acc[1] = fmaf(f1, w1, acc[1]);
        unp(h1.y, f0, f1); acc[2] = fmaf(f0, w1, acc[2]); acc[3] = fmaf(f1, w1, acc[3]);
        unp(h1.z, f0, f1); acc[4] = fmaf(f0, w1, acc[4]); acc[5] = fmaf(f1, w1, acc[5]);
        unp(h1.w, f0, f1); acc[6] = fmaf(f0, w1, acc[6]); acc[7] = fmaf(f1, w1, acc[7]);
        unp(h2.x, f0, f1); acc[0] = fmaf(f0, w2, acc[0]); acc[1] = fmaf(f1, w2, acc[1]);
        unp(h2.y, f0, f1); acc[2] = fmaf(f0, w2, acc[2]); acc[3] = fmaf(f1, w2, acc[3]);
        unp(h2.z, f0, f1); acc[4] = fmaf(f0, w2, acc[4]); acc[5] = fmaf(f1, w2, acc[5]);
        unp(h2.w, f0, f1); acc[6] = fmaf(f0, w2, acc[6]); acc[7] = fmaf(f1, w2, acc[7]);
        unp(h3.x, f0, f1); acc[0] = fmaf(f0, w3, acc[0]); acc[1] = fmaf(f1, w3, acc[1]);
        unp(h3.y, f0, f1); acc[2] = fmaf(f0, w3, acc[2]); acc[3] = fmaf(f1, w3, acc[3]);
        unp(h3.z, f0, f1); acc[4] = fmaf(f0, w3, acc[4]); acc[5] = fmaf(f1, w3, acc[5]);
        unp(h3.w, f0, f1); acc[6] = fmaf(f0, w3, acc[6]); acc[7] = fmaf(f1, w3, acc[7]);
    }
    for (; e < e1; e++) {
        int s = csr[e];
        float w = dinv[s] * di;
        uint4 hv = hb[(size_t)s * 32 + lane];
        float f0, f1;
        unp(hv.x, f0, f1); acc[0] = fmaf(f0, w, acc[0]); acc[1] = fmaf(f1, w, acc[1]);
        unp(hv.y, f0, f1); acc[2] = fmaf(f0, w, acc[2]); acc[3] = fmaf(f1, w, acc[3]);
        unp(hv.z, f0, f1); acc[4] = fmaf(f0, w, acc[4]); acc[5] = fmaf(f1, w, acc[5]);
        unp(hv.w, f0, f1); acc[6] = fmaf(f0, w, acc[6]); acc[7] = fmaf(f1, w, acc[7]);
    }
    float4 bb0 = ((const float4*)bias)[2 * lane];
    float4 bb1 = ((const float4*)bias)[2 * lane + 1];
    float v[8];
    v[0] = fmaxf(acc[0] + bb0.x, 0.f); v[1] = fmaxf(acc[1] + bb0.y, 0.f);
    v[2] = fmaxf(acc[2] + bb0.z, 0.f); v[3] = fmaxf(acc[3] + bb0.w, 0.f);
    v[4] = fmaxf(acc[4] + bb1.x, 0.f); v[5] = fmaxf(acc[5] + bb1.y, 0.f);
    v[6] = fmaxf(acc[6] + bb1.z, 0.f); v[7] = fmaxf(acc[7] + bb1.w, 0.f);
    uint4 o;
    o.x = packbf(v[0], v[1]); o.y = packbf(v[2], v[3]);
    o.z = packbf(v[4], v[5]); o.w = packbf(v[6], v[7]);
    ((uint4*)outb)[(size_t)node * 32 + lane] = o;
}

// ---------------- pooling over contiguous segments (bf16 input, no atomics) ----------------
template<int ISMAX>
__global__ void pool_kernel(const uint2* __restrict__ xb, float* __restrict__ out) {
    __shared__ float red[16 * 256];
    int b = blockIdx.x, t = threadIdx.x;
    int q = t & 63;
    int rp = t >> 6;         // 0..15
    int s = g_bounds[b], e = g_bounds[b + 1];
    float a0 = 0.f, a1 = 0.f, a2 = 0.f, a3 = 0.f;
    for (int i = s + rp; i < e; i += 16) {
        uint2 v = xb[(size_t)i * 64 + q];
        float f0, f1, f2, f3;
        unp(v.x, f0, f1); unp(v.y, f2, f3);
        if (ISMAX) {
            a0 = fmaxf(a0, f0); a1 = fmaxf(a1, f1);
            a2 = fmaxf(a2, f2); a3 = fmaxf(a3, f3);
        } else {
            a0 += f0; a1 += f1; a2 += f2; a3 += f3;
        }
    }
    red[rp * 256 + q * 4 + 0] = a0;
    red[rp * 256 + q * 4 + 1] = a1;
    red[rp * 256 + q * 4 + 2] = a2;
    red[rp * 256 + q * 4 + 3] = a3;
    __syncthreads();
    if (t < 256) {
        float r = red[t];
#pragma unroll
        for (int p = 1; p < 16; p++) {
            if (ISMAX) r = fmaxf(r, red[p * 256 + t]);
            else       r += red[p * 256 + t];
        }
        out[b * HH + t] = r;
    }
}

// ---------------- bf16 tensor-core GEMM (mma.sync) ----------------
template<int AF32, int ATOMIC>
__global__ __launch_bounds__(256)
void gemm_bf16(const void* __restrict__ Av, const uint32_t* __restrict__ Bp,
               float* __restrict__ C, uint16_t* __restrict__ Cb,
               int M, int N, int K, int KS) {
    constexpr int ABUFSZ = AF32 ? 23040 : 12800;
    constexpr int BBUFSZ = 16896;
    extern __shared__ __align__(16) uint8_t smraw[];
    int tid = threadIdx.x;
    int lane = tid & 31, wid = tid >> 5;
    int warp_m = wid & 1, warp_n = wid >> 1;
    int bm = blockIdx.y * 160;
    int bn = blockIdx.x * 256;
    int kbeg = blockIdx.z * KS;
    int kend = min(K, kbeg + KS);
    int ntiles = (kend - kbeg + 31) >> 5;
    uint32_t sbase = (uint32_t)__cvta_generic_to_shared(smraw);

    float acc[5][8][4];
#pragma unroll
    for (int mt = 0; mt < 5; mt++)
#pragma unroll
        for (int nt = 0; nt < 8; nt++)
#pragma unroll
            for (int q = 0; q < 4; q++) acc[mt][nt][q] = 0.f;

    auto prefetch = [&](int tile, int pbuf) {
        int k0 = kbeg + tile * 32;
        if (AF32) {
            const float* A = (const float*)Av;
#pragma unroll
            for (int i = 0; i < 5; i++) {
                int c = tid + 256 * i;
                int row = c >> 3, ch = c & 7;
                bool ok = (bm + row < M) && (k0 + ch * 4 < kend);
                const void* src = A + (size_t)(bm + row) * K + k0 + ch * 4;
                cpasync16(sbase + pbuf * ABUFSZ + row * 144 + ch * 16, ok ? src : A, ok);
            }
        } else {
            const __nv_bfloat16* A = (const __nv_bfloat16*)Av;
#pragma unroll
            for (int i = 0; i < 3; i++) {
                int c = tid + 256 * i;
                if (c < 640) {
                    int row = c >> 2, ch = c & 3;
                    bool ok = (bm + row < M) && (k0 + ch * 8 < kend);
                    const void* src = A + (size_t)(bm + row) * K + k0 + ch * 8;
                    cpasync16(sbase + pbuf * ABUFSZ + row * 80 + ch * 16, ok ? src : A, ok);
                }
            }
        }
#pragma unroll
        for (int i = 0; i < 4; i++) {
            int c = tid + 256 * i;
            int row = c >> 6, seg = c & 63;
            bool ok = (k0 + 2 * row < kend);
            const void* src = Bp + (size_t)(k0 / 2 + row) * N + bn + seg * 4;
            cpasync16(sbase + 2 * ABUFSZ + pbuf * BBUFSZ + row * 1056 + seg * 16,
                      ok ? src : Bp, ok);
        }
        cpcommit();
    };

    int buf = 0;
    prefetch(0, 0);
    for (int t = 0; t < ntiles; t++) {
        cpwait0();
        __syncthreads();
        if (t + 1 < ntiles) prefetch(t + 1, buf ^ 1);

        const uint32_t* Bsb = (const uint32_t*)(smraw + 2 * ABUFSZ + buf * BBUFSZ);
#pragma unroll
        for (int ks = 0; ks < 2; ks++) {
            int kk0 = ks * 16 + 2 * (lane & 3);
            uint32_t af[5][4];
            if (AF32) {
                const float* Asf = (const float*)(smraw + buf * ABUFSZ);
#pragma unroll
                for (int mt = 0; mt < 5; mt++) {
                    int r = warp_m * 80 + mt * 16 + (lane >> 2);
                    float2 v0 = *(const float2*)(Asf + r * 36 + kk0);
                    float2 v1 = *(const float2*)(Asf + (r + 8) * 36 + kk0);
                    float2 v2 = *(const float2*)(Asf + r * 36 + kk0 + 8);
                    float2 v3 = *(const float2*)(Asf + (r + 8) * 36 + kk0 + 8);
                    af[mt][0] = packbf(v0.x, v0.y);
                    af[mt][1] = packbf(v1.x, v1.y);
                    af[mt][2] = packbf(v2.x, v2.y);
                    af[mt][3] = packbf(v3.x, v3.y);
                }
            } else {
                const uint16_t* Asb = (const uint16_t*)(smraw + buf * ABUFSZ);
#pragma unroll
                for (int mt = 0; mt < 5; mt++) {
                    int r = warp_m * 80 + mt * 16 + (lane >> 2);
                    af[mt][0] = *(const uint32_t*)(Asb + r * 40 + kk0);
                    af[mt][1] = *(const uint32_t*)(Asb + (r + 8) * 40 + kk0);
                    af[mt][2] = *(const uint32_t*)(Asb + r * 40 + kk0 + 8);
                    af[mt][3] = *(const uint32_t*)(Asb + (r + 8) * 40 + kk0 + 8);
                }
            }
            int p = ks * 8 + (lane & 3);
#pragma unroll
            for (int nt = 0; nt < 8; nt++) {
                int cl = warp_n * 64 + nt * 8 + (lane >> 2);
                uint32_t b0 = Bsb[p * 264 + cl];
                uint32_t b1 = Bsb[(p + 4) * 264 + cl];
#pragma unroll
                for (int mt = 0; mt < 5; mt++) {
                    asm volatile(
                        "mma.sync.aligned.m16n8k16.row.col.f32.bf16.bf16.f32 "
                        "{%0,%1,%2,%3}, {%4,%5,%6,%7}, {%8,%9}, {%0,%1,%2,%3};\n"
                        : "+f"(acc[mt][nt][0]), "+f"(acc[mt][nt][1]),
                          "+f"(acc[mt][nt][2]), "+f"(acc[mt][nt][3])
                        : "r"(af[mt][0]), "r"(af[mt][1]), "r"(af[mt][2]), "r"(af[mt][3]),
                          "r"(b0), "r"(b1));
                }
            }
        }
        buf ^= 1;
        __syncthreads();
    }

#pragma unroll
    for (int mt = 0; mt < 5; mt++) {
#pragma unroll
        for (int nt = 0; nt < 8; nt++) {
            int row = bm + warp_m * 80 + mt * 16 + (lane >> 2);
            int col = bn + warp_n * 64 + nt * 8 + 2 * (lane & 3);
            if (ATOMIC) {
                if (row < M) {
                    atomicAdd(&C[(size_t)row * N + col],     acc[mt][nt][0]);
                    atomicAdd(&C[(size_t)row * N + col + 1], acc[mt][nt][1]);
                }
                if (row + 8 < M) {
                    atomicAdd(&C[(size_t)(row + 8) * N + col],     acc[mt][nt][2]);
                    atomicAdd(&C[(size_t)(row + 8) * N + col + 1], acc[mt][nt][3]);
                }
            } else {
                uint32_t* Cb32 = (uint32_t*)Cb;
                if (row < M)
                    Cb32[((size_t)row * N + col) >> 1] = packbf(acc[mt][nt][0], acc[mt][nt][1]);
                if (row + 8 < M)
                    Cb32[((size_t)(row + 8) * N + col) >> 1] = packbf(acc[mt][nt][2], acc[mt][nt][3]);
            }
        }
    }
}

// ---------------- branch2 front: segment mean only ----------------
__global__ void meanraw_kernel(const float* __restrict__ dx) {
    int f = blockIdx.x * 256 + threadIdx.x;
    if (f >= RAWF) return;
    int b = blockIdx.y;
    int s = g_bounds[b], e = g_bounds[b + 1];
    float acc = 0.f;
    for (int i = s; i < e; i++) acc += dx[(size_t)i * RAWF + f];
    int cnt = e - s; if (cnt < 1) cnt = 1;
    g_newxinb[(size_t)b * (2 * RAWF) + f] = __float2bfloat16(acc / (float)cnt);
}
__global__ void root_kernel(const float* __restrict__ dx, const int* __restrict__ root) {
    int f = blockIdx.x * 256 + threadIdx.x;
    if (f >= RAWF) return;
    int b = blockIdx.y;
    g_newxinb[(size_t)b * (2 * RAWF) + RAWF + f] =
        __float2bfloat16(dx[(size_t)root[b] * RAWF + f]);
}

// ---------------- small elementwise ----------------
__global__ void init_bias_kernel(float* __restrict__ p, const float* __restrict__ bias,
                                 int n, int mask) {
    int i = blockIdx.x * blockDim.x + threadIdx.x;
    if (i < n) p[i] = bias[i & mask];
}
__global__ void prelu_kernel(float* __restrict__ p, int n, const float* __restrict__ pa,
                             __nv_bfloat16* __restrict__ outb) {
    int i = blockIdx.x * blockDim.x + threadIdx.x;
    if (i >= n) return;
    float a = *pa;
    float v = p[i];
    v = v >= 0.f ? v : a * v;
    if (outb) outb[i] = __float2bfloat16(v);
    else p[i] = v;
}

// ---------------- final projection + log_softmax ----------------
__global__ void final_kernel(const float* __restrict__ W5, const float* __restrict__ b5,
                             float* __restrict__ out) {
    __shared__ float red[4][256];
    int b = blockIdx.x, t = threadIdx.x;
    int cnt = g_bounds[b + 1] - g_bounds[b];
    float inv = 1.f / (float)(cnt < 1 ? 1 : cnt);
    float acc[4] = {0.f, 0.f, 0.f, 0.f};
    for (int k = t; k < 5 * HH; k += 256) {
        int seg = k >> 8, f = k & 255;
        float v;
        if      (seg == 0) v = g_p0[b * HH + f] * inv;
        else if (seg == 1) v = g_p1[b * HH + f] * inv;
        else if (seg == 2) v = g_p2[b * HH + f] * inv;
        else if (seg == 3) v = g_newx[b * HH + f];
        else               v = g_xmax[b * HH + f];
#pragma unroll
        for (int c = 0; c < 4; c++) acc[c] += v * W5[k * 4 + c];
    }
#pragma unroll
    for (int c = 0; c < 4; c++) red[c][t] = acc[c];
    __syncthreads();
    for (int s = 128; s > 0; s >>= 1) {
        if (t < s) {
#pragma unroll
            for (int c = 0; c < 4; c++) red[c][t] += red[c][t + s];
        }
        __syncthreads();
    }
    if (t == 0) {
        float z[4];
#pragma unroll
        for (int c = 0; c < 4; c++) z[c] = red[c][0] + b5[c];
        float m = z[0];
#pragma unroll
        for (int c = 1; c < 4; c++) m = fmaxf(m, z[c]);
        float ssum = 0.f;
#pragma unroll
        for (int c = 0; c < 4; c++) ssum += expf(z[c] - m);
        float ls = logf(ssum);
#pragma unroll
        for (int c = 0; c < 4; c++) out[b * 4 + c] = z[c] - m - ls;
    }
}

// ---------------- host ----------------
extern "C" void kernel_launch(void* const* d_in, const int* in_sizes, int n_in,
                              void* d_out, int out_size) {
    const float* graph_x = (const float*)d_in[0];
    const float* data_x  = (const float*)d_in[2];
    const int*   ei      = (const int*)d_in[3];
    const int*   rei     = (const int*)d_in[4];
    const int*   gbatch  = (const int*)d_in[5];
    const int*   root    = (const int*)d_in[7];
    const float* W1  = (const float*)d_in[8];
    const float* b1  = (const float*)d_in[9];
    const float* Wc0 = (const float*)d_in[10];
    const float* bc0 = (const float*)d_in[11];
    const float* Wc1 = (const float*)d_in[12];
    const float* bc1 = (const float*)d_in[13];
    const float* Wc2 = (const float*)d_in[14];
    const float* bc2 = (const float*)d_in[15];
    const float* Wl1 = (const float*)d_in[16];
    const float* bl1 = (const float*)d_in[17];
    const float* Wl2 = (const float*)d_in[18];
    const float* bl2 = (const float*)d_in[19];
    const float* pa  = (const float*)d_in[20];
    const float* W5  = (const float*)d_in[21];
    const float* b5  = (const float*)d_in[22];
    float* out = (float*)d_out;

    static bool s_init = false;
    static cudaStream_t s1, s2;
    static cudaEvent_t evBounds, evCSR, evB2;
    if (!s_init) {
        cudaStreamCreateWithFlags(&s1, cudaStreamNonBlocking);
        cudaStreamCreateWithFlags(&s2, cudaStreamNonBlocking);
        cudaEventCreateWithFlags(&evBounds, cudaEventDisableTiming);
        cudaEventCreateWithFlags(&evCSR,    cudaEventDisableTiming);
        cudaEventCreateWithFlags(&evB2,     cudaEventDisableTiming);
        cudaFuncSetAttribute(gemm_bf16<1, 0>, cudaFuncAttributeMaxDynamicSharedMemorySize, 79872);
        cudaFuncSetAttribute(gemm_bf16<0, 0>, cudaFuncAttributeMaxDynamicSharedMemorySize, 59392);
        cudaFuncSetAttribute(gemm_bf16<0, 1>, cudaFuncAttributeMaxDynamicSharedMemorySize, 59392);
        s_init = true;
    }

    __nv_bfloat16 *phb, *paggb, *pl1b, *pnewxinb;
    float *pl1, *pnewx, *pxmax, *pp0, *pp1, *pp2;
    int *prs0, *prs1, *psrc0, *psrc1;
    float *pdinv0, *pdinv1;
    uint32_t *pwp;
    cudaGetSymbolAddress((void**)&phb,      g_hb);
    cudaGetSymbolAddress((void**)&paggb,    g_aggb);
    cudaGetSymbolAddress((void**)&pl1,      g_l1);
    cudaGetSymbolAddress((void**)&pl1b,     g_l1b);
    cudaGetSymbolAddress((void**)&pnewx,    g_newx);
    cudaGetSymbolAddress((void**)&pxmax,    g_xmax);
    cudaGetSymbolAddress((void**)&pp0,      g_p0);
    cudaGetSymbolAddress((void**)&pp1,      g_p1);
    cudaGetSymbolAddress((void**)&pp2,      g_p2);
    cudaGetSymbolAddress((void**)&pnewxinb, g_newxinb);
    cudaGetSymbolAddress((void**)&prs0,     g_rs0);
    cudaGetSymbolAddress((void**)&prs1,     g_rs1);
    cudaGetSymbolAddress((void**)&psrc0,    g_src0);
    cudaGetSymbolAddress((void**)&psrc1,    g_src1);
    cudaGetSymbolAddress((void**)&pdinv0,   g_dinv0);
    cudaGetSymbolAddress((void**)&pdinv1,   g_dinv1);
    cudaGetSymbolAddress((void**)&pwp,      g_wp);

    dim3 nodeGrid(1, (NN + 159) / 160, 1);   // 125 CTAs, one wave
    const int NB = (NN + 255) / 256;
    dim3 edgeGrid((EE / 4 + 255) / 256, 2);
    dim3 rawGrid((RAWF + 255) / 256, BB);

    // ===== stream 0: bounds -> branch1 GEMM -> (join CSR) gathers/branch3 =====
    bounds_kernel<<<1, 160>>>(gbatch);
    cudaEventRecord(evBounds, 0);
    cudaStreamWaitEvent(s1, evBounds, 0);
    cudaStreamWaitEvent(s2, evBounds, 0);

    // ===== stream s2: CSR build for both graphs (+ small branch3 weight preps) =====
    zero2_kernel<<<NB, 256, 0, s2>>>();
    hist2_kernel<<<edgeGrid, 256, 0, s2>>>(ei, rei);
    scan2_kernel<<<2, 1024, 0, s2>>>();
    fill2_kernel<<<edgeGrid, 256, 0, s2>>>(ei, rei);
    prep_w_kernel<<<((HH / 2) * HH + 255) / 256, 256, 0, s2>>>(Wc1, pwp + OFF_WC1, (HH / 2) * HH, HH);
    prep_w_kernel<<<((HH / 2) * HH + 255) / 256, 256, 0, s2>>>(Wc2, pwp + OFF_WC2, (HH / 2) * HH, HH);
    cudaEventRecord(evCSR, s2);

    // ===== stream 0 continues: branch-1 prep + GEMM overlap the CSR build =====
    prep_w_kernel<<<((FIN / 2) * HH + 255) / 256, 256>>>(W1,  pwp + OFF_W1,  (FIN / 2) * HH, HH);
    prep_w_kernel<<<((RAWF / 2) * HH + 255) / 256, 256>>>(Wc0, pwp + OFF_WC0, (RAWF / 2) * HH, HH);
    gemm_bf16<1, 0><<<nodeGrid, 256, 79872>>>(graph_x, pwp + OFF_W1, nullptr,
                                              (uint16_t*)phb, NN, HH, FIN, FIN);
    cudaStreamWaitEvent(0, evCSR, 0);
    gather_kernel<<<NN / 8, 256>>>((const uint4*)phb, b1, prs0, psrc0, pdinv0, paggb);
    pool_kernel<1><<<BB, 1024>>>((const uint2*)paggb, pxmax);

    // branch 3 (layer 0 reads data_x directly: fp32-A GEMM)
    gemm_bf16<1, 0><<<nodeGrid, 256, 79872>>>(data_x, pwp + OFF_WC0, nullptr,
                                              (uint16_t*)phb, NN, HH, RAWF, RAWF);
    gather_kernel<<<NN / 8, 256>>>((const uint4*)phb, bc0, prs1, psrc1, pdinv1, paggb);
    pool_kernel<0><<<BB, 1024>>>((const uint2*)paggb, pp0);
    gemm_bf16<0, 0><<<nodeGrid, 256, 59392>>>(paggb, pwp + OFF_WC1, nullptr,
                                              (uint16_t*)phb, NN, HH, HH, HH);
    gather_kernel<<<NN / 8, 256>>>((const uint4*)phb, bc1, prs1, psrc1, pdinv1, paggb);
    pool_kernel<0><<<BB, 1024>>>((const uint2*)paggb, pp1);
    gemm_bf16<0, 0><<<nodeGrid, 256, 59392>>>(paggb, pwp + OFF_WC2, nullptr,
                                              (uint16_t*)phb, NN, HH, HH, HH);
    gather_kernel<<<NN / 8, 256>>>((const uint4*)phb, bc2, prs1, psrc1, pdinv1, paggb);
    pool_kernel<0><<<BB, 1024>>>((const uint2*)paggb, pp2);

    // ===== stream s1: branch 2 (memory-bound; overlaps tensor-bound stream 0) =====
    prep_w_kernel<<<(RAWF * 512 + 255) / 256, 256, 0, s1>>>(Wl1, pwp + OFF_WL1, RAWF * 512, 512);
    prep_w_kernel<<<(256 * HH + 255) / 256, 256, 0, s1>>>(Wl2, pwp + OFF_WL2, 256 * HH, HH);
    meanraw_kernel<<<rawGrid, 256, 0, s1>>>(data_x);
    root_kernel<<<rawGrid, 256, 0, s1>>>(data_x, root);
    init_bias_kernel<<<(BB * 512 + 255) / 256, 256, 0, s1>>>(pl1, bl1, BB * 512, 511);
    gemm_bf16<0, 1><<<dim3(2, 1, 63), 256, 59392, s1>>>(pnewxinb, pwp + OFF_WL1, pl1,
                                                        nullptr, BB, 512, 2 * RAWF, 160);
    prelu_kernel<<<(BB * 512 + 255) / 256, 256, 0, s1>>>(pl1, BB * 512, pa, pl1b);
    init_bias_kernel<<<(BB * 256 + 255) / 256, 256, 0, s1>>>(pnewx, bl2, BB * 256, 255);
    gemm_bf16<0, 1><<<dim3(1, 1, 8), 256, 59392, s1>>>(pl1b, pwp + OFF_WL2, pnewx,
                                                       nullptr, BB, HH, 512, 64);
    prelu_kernel<<<(BB * 256 + 255) / 256, 256, 0, s1>>>(pnewx, BB * 256, pa, nullptr);
    cudaEventRecord(evB2, s1);

    // ===== join + final =====
    cudaStreamWaitEvent(0, evB2, 0);
    final_kernel<<<BB, 256>>>(W5, b5, out);
}

// round 15
// speedup vs baseline: 1.6632x; 1.0259x over previous
#include <cuda_runtime.h>
#include <cuda_bf16.h>
#include <cstdint>

#define NN   20000
#define BB   128
#define EE   320000
#define FIN  768
#define RAWF 5000
#define HH   256
#define CC   4

// ---------------- scratch (device globals) ----------------
__device__ __align__(16) __nv_bfloat16 g_hb[NN * HH];    // branch3 GEMM output (bf16)
__device__ __align__(16) __nv_bfloat16 g_hb0[NN * HH];   // branch1 GEMM output (bf16)
__device__ __align__(16) __nv_bfloat16 g_aggb[NN * HH];  // branch3 activation (bf16)
__device__ __align__(16) __nv_bfloat16 g_aggb0[NN * HH]; // branch1 activation (bf16)
__device__ __align__(16) float g_l1[BB * 512];
__device__ __align__(16) __nv_bfloat16 g_l1b[BB * 512];
__device__ __align__(16) float g_newx[BB * HH];
__device__ __align__(16) float g_xmax[BB * HH];
__device__ __align__(16) float g_p0[BB * HH];
__device__ __align__(16) float g_p1[BB * HH];
__device__ __align__(16) float g_p2[BB * HH];
__device__ __align__(16) __nv_bfloat16 g_newxinb[BB * 2 * RAWF];
// packed k2-interleaved bf16 weights
#define OFF_W1   0
#define OFF_WC0  98304
#define OFF_WC1  738304
#define OFF_WC2  771072
#define OFF_WL1  803840
#define OFF_WL2  3363840
__device__ __align__(16) uint32_t g_wp[3429376];
__device__ __align__(16) int   g_cnt0[NN];
__device__ __align__(16) int   g_cnt1[NN];
__device__ int   g_cur0[NN];
__device__ int   g_cur1[NN];
__device__ __align__(16) int   g_rs0[NN + 4];
__device__ __align__(16) int   g_rs1[NN + 4];
__device__ int   g_src0[EE];
__device__ int   g_src1[EE];
__device__ __align__(16) float g_dinv0[NN];
__device__ __align__(16) float g_dinv1[NN];
__device__ int   g_bounds[BB + 1];

// ---------------- helpers ----------------
__device__ __forceinline__ uint32_t packbf(float lo, float hi) {
    uint32_t r;
    asm("cvt.rn.bf16x2.f32 %0, %1, %2;" : "=r"(r) : "f"(hi), "f"(lo));
    return r;
}
__device__ __forceinline__ void cpasync16(uint32_t dst, const void* src, bool ok) {
    int ss = ok ? 16 : 0;
    asm volatile("cp.async.cg.shared.global [%0], [%1], 16, %2;\n" :: "r"(dst), "l"(src), "r"(ss));
}
__device__ __forceinline__ void cpcommit() { asm volatile("cp.async.commit_group;\n"); }
__device__ __forceinline__ void cpwait0()  { asm volatile("cp.async.wait_group 0;\n"); }
__device__ __forceinline__ void unp(uint32_t w, float& a, float& b) {
    a = __uint_as_float(w << 16);
    b = __uint_as_float(w & 0xffff0000u);
}

// ---------------- segment bounds ----------------
__global__ void bounds_kernel(const int* __restrict__ batch) {
    int b = threadIdx.x;
    if (b > BB) return;
    int lo = 0, hi = NN;
    while (lo < hi) {
        int mid = (lo + hi) >> 1;
        if (batch[mid] < b) lo = mid + 1; else hi = mid;
    }
    g_bounds[b] = lo;
}

// ---------------- weight prep ----------------
__global__ void prep_w_kernel(const float* __restrict__ W, uint32_t* __restrict__ Wp,
                              int cnt, int N) {
    int idx = blockIdx.x * blockDim.x + threadIdx.x;
    if (idx >= cnt) return;
    int p = idx / N, n = idx - p * N;
    Wp[idx] = packbf(W[(size_t)(2 * p) * N + n], W[(size_t)(2 * p + 1) * N + n]);
}

// ---------------- CSR build ----------------
__global__ void zero2_kernel() {
    int i = blockIdx.x * blockDim.x + threadIdx.x;
    if (i < NN) { g_cnt0[i] = 0; g_cnt1[i] = 0; }
}
__global__ void hist2_kernel(const int* __restrict__ ei, const int* __restrict__ rei) {
    int i = blockIdx.x * blockDim.x + threadIdx.x;
    if (i >= EE / 4) return;
    const int* dst;
    int* cnt;
    if (blockIdx.y == 0) { dst = ei + EE;  cnt = g_cnt0; }
    else                 { dst = rei + EE; cnt = g_cnt1; }
    int4 d = ((const int4*)dst)[i];
    atomicAdd(&cnt[d.x], 1);
    atomicAdd(&cnt[d.y], 1);
    atomicAdd(&cnt[d.z], 1);
    atomicAdd(&cnt[d.w], 1);
}
__global__ void scan2_kernel() {
    __shared__ int wsum[32];
    int g = blockIdx.x;
    const int* cnt = g ? g_cnt1 : g_cnt0;
    int* rs        = g ? g_rs1  : g_rs0;
    int* cur       = g ? g_cur1 : g_cur0;
    float* dinv    = g ? g_dinv1 : g_dinv0;
    int t = threadIdx.x;
    int lane = t & 31, wid = t >> 5;
    int c[20];
    const int4* c4 = (const int4*)cnt;
#pragma unroll
    for (int i = 0; i < 5; i++) {
        int idx4 = t * 5 + i;
        int4 v = (idx4 < 5000) ? c4[idx4] : make_int4(0, 0, 0, 0);
        c[i * 4 + 0] = v.x; c[i * 4 + 1] = v.y; c[i * 4 + 2] = v.z; c[i * 4 + 3] = v.w;
    }
    int loc[20];
    int s = 0;
#pragma unroll
    for (int i = 0; i < 20; i++) { loc[i] = s; s += c[i]; }
    int x = s;
#pragma unroll
    for (int off = 1; off < 32; off <<= 1) {
        int y = __shfl_up_sync(0xffffffffu, x, off);
        if (lane >= off) x += y;
    }
    if (lane == 31) wsum[wid] = x;
    __syncthreads();
    if (wid == 0) {
        int v = wsum[lane];
#pragma unroll
        for (int off = 1; off < 32; off <<= 1) {
            int y = __shfl_up_sync(0xffffffffu, v, off);
            if (lane >= off) v += y;
        }
        wsum[lane] = v;
    }
    __syncthreads();
    int offset = (wid ? wsum[wid - 1] : 0) + (x - s);
    int4* rs4 = (int4*)rs;
    int4* cu4 = (int4*)cur;
    float4* dv4 = (float4*)dinv;
#pragma unroll
    for (int i = 0; i < 5; i++) {
        int idx4 = t * 5 + i;
        if (idx4 < 5000) {
            int4 r; float4 d;
            r.x = offset + loc[i * 4 + 0]; d.x = rsqrtf((float)(c[i * 4 + 0] + 1));
            r.y = offset + loc[i * 4 + 1]; d.y = rsqrtf((float)(c[i * 4 + 1] + 1));
            r.z = offset + loc[i * 4 + 2]; d.z = rsqrtf((float)(c[i * 4 + 2] + 1));
            r.w = offset + loc[i * 4 + 3]; d.w = rsqrtf((float)(c[i * 4 + 3] + 1));
            rs4[idx4] = r; cu4[idx4] = r; dv4[idx4] = d;
        }
    }
    if (t == 0) rs[NN] = EE;
}
__global__ void fill2_kernel(const int* __restrict__ ei, const int* __restrict__ rei) {
    int i = blockIdx.x * blockDim.x + threadIdx.x;
    if (i >= EE / 4) return;
    const int* src;
    const int* dst;
    int* cur;
    int* outp;
    if (blockIdx.y == 0) { src = ei;  dst = ei + EE;  cur = g_cur0; outp = g_src0; }
    else                 { src = rei; dst = rei + EE; cur = g_cur1; outp = g_src1; }
    int4 d = ((const int4*)dst)[i];
    int4 s = ((const int4*)src)[i];
    outp[atomicAdd(&cur[d.x], 1)] = s.x;
    outp[atomicAdd(&cur[d.y], 1)] = s.y;
    outp[atomicAdd(&cur[d.z], 1)] = s.z;
    outp[atomicAdd(&cur[d.w], 1)] = s.w;
}

// ---------------- fused GCN aggregation + relu (bf16 in/out), edge loop unrolled x4 ----------------
__global__ __launch_bounds__(256)
void gather_kernel(const uint4* __restrict__ hb, const float* __restrict__ bias,
                   const int* __restrict__ rs, const int* __restrict__ csr,
                   const float* __restrict__ dinv, __nv_bfloat16* __restrict__ outb) {
    int node = blockIdx.x * 8 + (threadIdx.x >> 5);
    int lane = threadIdx.x & 31;
    float di = dinv[node];
    float sw = di * di;
    float acc[8];
    {
        uint4 hv = hb[(size_t)node * 32 + lane];
        float f0, f1;
        unp(hv.x, f0, f1); acc[0] = f0 * sw; acc[1] = f1 * sw;
        unp(hv.y, f0, f1); acc[2] = f0 * sw; acc[3] = f1 * sw;
        unp(hv.z, f0, f1); acc[4] = f0 * sw; acc[5] = f1 * sw;
        unp(hv.w, f0, f1); acc[6] = f0 * sw; acc[7] = f1 * sw;
    }
    int e0 = rs[node], e1 = rs[node + 1];
    int e = e0;
    for (; e + 4 <= e1; e += 4) {
        int s0 = csr[e], s1 = csr[e + 1], s2 = csr[e + 2], s3 = csr[e + 3];
        float w0 = dinv[s0] * di, w1 = dinv[s1] * di;
        float w2 = dinv[s2] * di, w3 = dinv[s3] * di;
        uint4 h0 = hb[(size_t)s0 * 32 + lane];
        uint4 h1 = hb[(size_t)s1 * 32 + lane];
        uint4 h2 = hb[(size_t)s2 * 32 + lane];
        uint4 h3 = hb[(size_t)s3 * 32 + lane];
        float f0, f1;
        unp(h0.x, f0, f1); acc[0] = fmaf(f0, w0, acc[0]); acc[1] = fmaf(f1, w0, acc[1]);
        unp(h0.y, f0, f1); acc[2] = fmaf(f0, w0, acc[2]); acc[3] = fmaf(f1, w0, acc[3]);
        unp(h0.z, f0, f1); acc[4] = fmaf(f0, w0, acc[4]); acc[5] = fmaf(f1, w0, acc[5]);
        unp(h0.w, f0, f1); acc[6] = fmaf(f0, w0, acc[6]); acc[7] = fmaf(f1, w0, acc[7]);
        unp(h1.x, f0, f1); acc[0] = fmaf(f0, w1, acc[0]); acc[1] = fmaf(f1, w1, acc[1]);
        unp(h1.y, f0, f1); acc[2] = fmaf(f0, w1, acc[2]); acc[3] = fmaf(f1, w1, acc[3]);
        unp(h1.z, f0, f1); acc[4] = fmaf(f0, w1, acc[4]); acc[5] = fmaf(f1, w1, acc[5]);
        unp(h1.w, f0, f1); acc[6] = fmaf(f0, w1, acc[6]); acc[7] = fmaf(f1, w1, acc[7]);
        unp(h2.x, f0, f1); acc[0] = fmaf(f0, w2, acc[0]); acc[1] = fmaf(f1, w2, acc[1]);
        unp(h2.y, f0, f1); acc[2] = fmaf(f0, w2, acc[2]); acc[3] = fmaf(f1, w2, acc[3]);
        unp(h2.z, f0, f1); acc[4] = fmaf(f0, w2, acc[4]); acc[5] = fmaf(f1, w2, acc[5]);
        unp(h2.w, f0, f1); acc[6] = fmaf(f0, w2, acc[6]); acc[7] = fmaf(f1, w2, acc[7]);
        unp(h3.x, f0, f1); acc[0] = fmaf(f0, w3, acc[0]); acc[1] = fmaf(f1, w3, acc[1]);
        unp(h3.y, f0, f1); acc[2] = fmaf(f0, w3, acc[2]); acc[3] = fmaf(f1, w3, acc[3]);
        unp(h3.z, f0, f1); acc[4] = fmaf(f0, w3, acc[4]); acc[5] = fmaf(f1, w3, acc[5]);
        unp(h3.w, f0, f1); acc[6] = fmaf(f0, w3, acc[6]); acc[7] = fmaf(f1, w3, acc[7]);
    }
    for (; e < e1; e++) {
        int s = csr[e];
        float w = dinv[s] * di;
        uint4 hv = hb[(size_t)s * 32 + lane];
        float f0, f1;
        unp(hv.x, f0, f1); acc[0] = fmaf(f0, w, acc[0]); acc[1] = fmaf(f1, w, acc[1]);
        unp(hv.y, f0, f1); acc[2] = fmaf(f0, w, acc[2]); acc[3] = fmaf(f1, w, acc[3]);
        unp(hv.z, f0, f1); acc[4] = fmaf(f0, w, acc[4]); acc[5] = fmaf(f1, w, acc[5]);
        unp(hv.w, f0, f1); acc[6] = fmaf(f0, w, acc[6]); acc[7] = fmaf(f1, w, acc[7]);
    }
    float4 bb0 = ((const float4*)bias)[2 * lane];
    float4 bb1 = ((const float4*)bias)[2 * lane + 1];
    float v[8];
    v[0] = fmaxf(acc[0] + bb0.x, 0.f); v[1] = fmaxf(acc[1] + bb0.y, 0.f);
    v[2] = fmaxf(acc[2] + bb0.z, 0.f); v[3] = fmaxf(acc[3] + bb0.w, 0.f);
    v[4] = fmaxf(acc[4] + bb1.x, 0.f); v[5] = fmaxf(acc[5] + bb1.y, 0.f);
    v[6] = fmaxf(acc[6] + bb1.z, 0.f); v[7] = fmaxf(acc[7] + bb1.w, 0.f);
    uint4 o;
    o.x = packbf(v[0], v[1]); o.y = packbf(v[2], v[3]);
    o.z = packbf(v[4], v[5]); o.w = packbf(v[6], v[7]);
    ((uint4*)outb)[(size_t)node * 32 + lane] = o;
}

// ---------------- pooling over contiguous segments (bf16 input, no atomics) ----------------
template<int ISMAX>
__global__ void pool_kernel(const uint2* __restrict__ xb, float* __restrict__ out) {
    __shared__ float red[16 * 256];
    int b = blockIdx.x, t = threadIdx.x;
    int q = t & 63;
    int rp = t >> 6;         // 0..15
    int s = g_bounds[b], e = g_bounds[b + 1];
    float a0 = 0.f, a1 = 0.f, a2 = 0.f, a3 = 0.f;
    for (int i = s + rp; i < e; i += 16) {
        uint2 v = xb[(size_t)i * 64 + q];
        float f0, f1, f2, f3;
        unp(v.x, f0, f1); unp(v.y, f2, f3);
        if (ISMAX) {
            a0 = fmaxf(a0, f0); a1 = fmaxf(a1, f1);
            a2 = fmaxf(a2, f2); a3 = fmaxf(a3, f3);
        } else {
            a0 += f0; a1 += f1; a2 += f2; a3 += f3;
        }
    }
    red[rp * 256 + q * 4 + 0] = a0;
    red[rp * 256 + q * 4 + 1] = a1;
    red[rp * 256 + q * 4 + 2] = a2;
    red[rp * 256 + q * 4 + 3] = a3;
    __syncthreads();
    if (t < 256) {
        float r = red[t];
#pragma unroll
        for (int p = 1; p < 16; p++) {
            if (ISMAX) r = fmaxf(r, red[p * 256 + t]);
            else       r += red[p * 256 + t];
        }
        out[b * HH + t] = r;
    }
}

// ---------------- bf16 tensor-core GEMM (mma.sync) ----------------
template<int AF32, int ATOMIC>
__global__ __launch_bounds__(256)
void gemm_bf16(const void* __restrict__ Av, const uint32_t* __restrict__ Bp,
               float* __restrict__ C, uint16_t* __restrict__ Cb,
               int M, int N, int K, int KS) {
    constexpr int ABUFSZ = AF32 ? 23040 : 12800;
    constexpr int BBUFSZ = 16896;
    extern __shared__ __align__(16) uint8_t smraw[];
    int tid = threadIdx.x;
    int lane = tid & 31, wid = tid >> 5;
    int warp_m = wid & 1, warp_n = wid >> 1;
    int bm = blockIdx.y * 160;
    int bn = blockIdx.x * 256;
    int kbeg = blockIdx.z * KS;
    int kend = min(K, kbeg + KS);
    int ntiles = (kend - kbeg + 31) >> 5;
    uint32_t sbase = (uint32_t)__cvta_generic_to_shared(smraw);

    float acc[5][8][4];
#pragma unroll
    for (int mt = 0; mt < 5; mt++)
#pragma unroll
        for (int nt = 0; nt < 8; nt++)
#pragma unroll
            for (int q = 0; q < 4; q++) acc[mt][nt][q] = 0.f;

    auto prefetch = [&](int tile, int pbuf) {
        int k0 = kbeg + tile * 32;
        if (AF32) {
            const float* A = (const float*)Av;
#pragma unroll
            for (int i = 0; i < 5; i++) {
                int c = tid + 256 * i;
                int row = c >> 3, ch = c & 7;
                bool ok = (bm + row < M) && (k0 + ch * 4 < kend);
                const void* src = A + (size_t)(bm + row) * K + k0 + ch * 4;
                cpasync16(sbase + pbuf * ABUFSZ + row * 144 + ch * 16, ok ? src : A, ok);
            }
        } else {
            const __nv_bfloat16* A = (const __nv_bfloat16*)Av;
#pragma unroll
            for (int i = 0; i < 3; i++) {
                int c = tid + 256 * i;
                if (c < 640) {
                    int row = c >> 2, ch = c & 3;
                    bool ok = (bm + row < M) && (k0 + ch * 8 < kend);
                    const void* src = A + (size_t)(bm + row) * K + k0 + ch * 8;
                    cpasync16(sbase + pbuf * ABUFSZ + row * 80 + ch * 16, ok ? src : A, ok);
                }
            }
        }
#pragma unroll
        for (int i = 0; i < 4; i++) {
            int c = tid + 256 * i;
            int row = c >> 6, seg = c & 63;
            bool ok = (k0 + 2 * row < kend);
            const void* src = Bp + (size_t)(k0 / 2 + row) * N + bn + seg * 4;
            cpasync16(sbase + 2 * ABUFSZ + pbuf * BBUFSZ + row * 1056 + seg * 16,
                      ok ? src : Bp, ok);
        }
        cpcommit();
    };

    int buf = 0;
    prefetch(0, 0);
    for (int t = 0; t < ntiles; t++) {
        cpwait0();
        __syncthreads();
        if (t + 1 < ntiles) prefetch(t + 1, buf ^ 1);

        const uint32_t* Bsb = (const uint32_t*)(smraw + 2 * ABUFSZ + buf * BBUFSZ);
#pragma unroll
        for (int ks = 0; ks < 2; ks++) {
            int kk0 = ks * 16 + 2 * (lane & 3);
            uint32_t af[5][4];
            if (AF32) {
                const float* Asf = (const float*)(smraw + buf * ABUFSZ);
#pragma unroll
                for (int mt = 0; mt < 5; mt++) {
                    int r = warp_m * 80 + mt * 16 + (lane >> 2);
                    float2 v0 = *(const float2*)(Asf + r * 36 + kk0);
                    float2 v1 = *(const float2*)(Asf + (r + 8) * 36 + kk0);
                    float2 v2 = *(const float2*)(Asf + r * 36 + kk0 + 8);
                    float2 v3 = *(const float2*)(Asf + (r + 8) * 36 + kk0 + 8);
                    af[mt][0] = packbf(v0.x, v0.y);
                    af[mt][1] = packbf(v1.x, v1.y);
                    af[mt][2] = packbf(v2.x, v2.y);
                    af[mt][3] = packbf(v3.x, v3.y);
                }
            } else {
                const uint16_t* Asb = (const uint16_t*)(smraw + buf * ABUFSZ);
#pragma unroll
                for (int mt = 0; mt < 5; mt++) {
                    int r = warp_m * 80 + mt * 16 + (lane >> 2);
                    af[mt][0] = *(const uint32_t*)(Asb + r * 40 + kk0);
                    af[mt][1] = *(const uint32_t*)(Asb + (r + 8) * 40 + kk0);
                    af[mt][2] = *(const uint32_t*)(Asb + r * 40 + kk0 + 8);
                    af[mt][3] = *(const uint32_t*)(Asb + (r + 8) * 40 + kk0 + 8);
                }
            }
            int p = ks * 8 + (lane & 3);
#pragma unroll
            for (int nt = 0; nt < 8; nt++) {
                int cl = warp_n * 64 + nt * 8 + (lane >> 2);
                uint32_t b0 = Bsb[p * 264 + cl];
                uint32_t b1 = Bsb[(p + 4) * 264 + cl];
#pragma unroll
                for (int mt = 0; mt < 5; mt++) {
                    asm volatile(
                        "mma.sync.aligned.m16n8k16.row.col.f32.bf16.bf16.f32 "
                        "{%0,%1,%2,%3}, {%4,%5,%6,%7}, {%8,%9}, {%0,%1,%2,%3};\n"
                        : "+f"(acc[mt][nt][0]), "+f"(acc[mt][nt][1]),
                          "+f"(acc[mt][nt][2]), "+f"(acc[mt][nt][3])
                        : "r"(af[mt][0]), "r"(af[mt][1]), "r"(af[mt][2]), "r"(af[mt][3]),
                          "r"(b0), "r"(b1));
                }
            }
        }
        buf ^= 1;
        __syncthreads();
    }

#pragma unroll
    for (int mt = 0; mt < 5; mt++) {
#pragma unroll
        for (int nt = 0; nt < 8; nt++) {
            int row = bm + warp_m * 80 + mt * 16 + (lane >> 2);
            int col = bn + warp_n * 64 + nt * 8 + 2 * (lane & 3);
            if (ATOMIC) {
                if (row < M) {
                    atomicAdd(&C[(size_t)row * N + col],     acc[mt][nt][0]);
                    atomicAdd(&C[(size_t)row * N + col + 1], acc[mt][nt][1]);
                }
                if (row + 8 < M) {
                    atomicAdd(&C[(size_t)(row + 8) * N + col],     acc[mt][nt][2]);
                    atomicAdd(&C[(size_t)(row + 8) * N + col + 1], acc[mt][nt][3]);
                }
            } else {
                uint32_t* Cb32 = (uint32_t*)Cb;
                if (row < M)
                    Cb32[((size_t)row * N + col) >> 1] = packbf(acc[mt][nt][0], acc[mt][nt][1]);
                if (row + 8 < M)
                    Cb32[((size_t)(row + 8) * N + col) >> 1] = packbf(acc[mt][nt][2], acc[mt][nt][3]);
            }
        }
    }
}

// ---------------- branch2 front: segment mean only ----------------
__global__ void meanraw_kernel(const float* __restrict__ dx) {
    int f = blockIdx.x * 256 + threadIdx.x;
    if (f >= RAWF) return;
    int b = blockIdx.y;
    int s = g_bounds[b], e = g_bounds[b + 1];
    float acc = 0.f;
    for (int i = s; i < e; i++) acc += dx[(size_t)i * RAWF + f];
    int cnt = e - s; if (cnt < 1) cnt = 1;
    g_newxinb[(size_t)b * (2 * RAWF) + f] = __float2bfloat16(acc / (float)cnt);
}
__global__ void root_kernel(const float* __restrict__ dx, const int* __restrict__ root) {
    int f = blockIdx.x * 256 + threadIdx.x;
    if (f >= RAWF) return;
    int b = blockIdx.y;
    g_newxinb[(size_t)b * (2 * RAWF) + RAWF + f] =
        __float2bfloat16(dx[(size_t)root[b] * RAWF + f]);
}

// ---------------- small elementwise ----------------
__global__ void init_bias_kernel(float* __restrict__ p, const float* __restrict__ bias,
                                 int n, int mask) {
    int i = blockIdx.x * blockDim.x + threadIdx.x;
    if (i < n) p[i] = bias[i & mask];
}
__global__ void prelu_kernel(float* __restrict__ p, int n, const float* __restrict__ pa,
                             __nv_bfloat16* __restrict__ outb) {
    int i = blockIdx.x * blockDim.x + threadIdx.x;
    if (i >= n) return;
    float a = *pa;
    float v = p[i];
    v = v >= 0.f ? v : a * v;
    if (outb) outb[i] = __float2bfloat16(v);
    else p[i] = v;
}

// ---------------- final projection + log_softmax ----------------
__global__ void final_kernel(const float* __restrict__ W5, const float* __restrict__ b5,
                             float* __restrict__ out) {
    __shared__ float red[4][256];
    int b = blockIdx.x, t = threadIdx.x;
    int cnt = g_bounds[b + 1] - g_bounds[b];
    float inv = 1.f / (float)(cnt < 1 ? 1 : cnt);
    float acc[4] = {0.f, 0.f, 0.f, 0.f};
    for (int k = t; k < 5 * HH; k += 256) {
        int seg = k >> 8, f = k & 255;
        float v;
        if      (seg == 0) v = g_p0[b * HH + f] * inv;
        else if (seg == 1) v = g_p1[b * HH + f] * inv;
        else if (seg == 2) v = g_p2[b * HH + f] * inv;
        else if (seg == 3) v = g_newx[b * HH + f];
        else               v = g_xmax[b * HH + f];
#pragma unroll
        for (int c = 0; c < 4; c++) acc[c] += v * W5[k * 4 + c];
    }
#pragma unroll
    for (int c = 0; c < 4; c++) red[c][t] = acc[c];
    __syncthreads();
    for (int s = 128; s > 0; s >>= 1) {
        if (t < s) {
#pragma unroll
            for (int c = 0; c < 4; c++) red[c][t] += red[c][t + s];
        }
        __syncthreads();
    }
    if (t == 0) {
        float z[4];
#pragma unroll
        for (int c = 0; c < 4; c++) z[c] = red[c][0] + b5[c];
        float m = z[0];
#pragma unroll
        for (int c = 1; c < 4; c++) m = fmaxf(m, z[c]);
        float ssum = 0.f;
#pragma unroll
        for (int c = 0; c < 4; c++) ssum += expf(z[c] - m);
        float ls = logf(ssum);
#pragma unroll
        for (int c = 0; c < 4; c++) out[b * 4 + c] = z[c] - m - ls;
    }
}

// ---------------- host ----------------
extern "C" void kernel_launch(void* const* d_in, const int* in_sizes, int n_in,
                              void* d_out, int out_size) {
    const float* graph_x = (const float*)d_in[0];
    const float* data_x  = (const float*)d_in[2];
    const int*   ei      = (const int*)d_in[3];
    const int*   rei     = (const int*)d_in[4];
    const int*   gbatch  = (const int*)d_in[5];
    const int*   root    = (const int*)d_in[7];
    const float* W1  = (const float*)d_in[8];
    const float* b1  = (const float*)d_in[9];
    const float* Wc0 = (const float*)d_in[10];
    const float* bc0 = (const float*)d_in[11];
    const float* Wc1 = (const float*)d_in[12];
    const float* bc1 = (const float*)d_in[13];
    const float* Wc2 = (const float*)d_in[14];
    const float* bc2 = (const float*)d_in[15];
    const float* Wl1 = (const float*)d_in[16];
    const float* bl1 = (const float*)d_in[17];
    const float* Wl2 = (const float*)d_in[18];
    const float* bl2 = (const float*)d_in[19];
    const float* pa  = (const float*)d_in[20];
    const float* W5  = (const float*)d_in[21];
    const float* b5  = (const float*)d_in[22];
    float* out = (float*)d_out;

    static bool s_init = false;
    static cudaStream_t s1, s2;
    static cudaEvent_t evBounds, evCSR, evW1, evG1, evG2, evP0, evP1, evB1, evB2;
    if (!s_init) {
        cudaStreamCreateWithFlags(&s1, cudaStreamNonBlocking);
        cudaStreamCreateWithFlags(&s2, cudaStreamNonBlocking);
        cudaEventCreateWithFlags(&evBounds, cudaEventDisableTiming);
        cudaEventCreateWithFlags(&evCSR,    cudaEventDisableTiming);
        cudaEventCreateWithFlags(&evW1,     cudaEventDisableTiming);
        cudaEventCreateWithFlags(&evG1,     cudaEventDisableTiming);
        cudaEventCreateWithFlags(&evG2,     cudaEventDisableTiming);
        cudaEventCreateWithFlags(&evP0,     cudaEventDisableTiming);
        cudaEventCreateWithFlags(&evP1,     cudaEventDisableTiming);
        cudaEventCreateWithFlags(&evB1,     cudaEventDisableTiming);
        cudaEventCreateWithFlags(&evB2,     cudaEventDisableTiming);
        cudaFuncSetAttribute(gemm_bf16<1, 0>, cudaFuncAttributeMaxDynamicSharedMemorySize, 79872);
        cudaFuncSetAttribute(gemm_bf16<0, 0>, cudaFuncAttributeMaxDynamicSharedMemorySize, 59392);
        cudaFuncSetAttribute(gemm_bf16<0, 1>, cudaFuncAttributeMaxDynamicSharedMemorySize, 59392);
        s_init = true;
    }

    __nv_bfloat16 *phb, *phb0, *paggb, *paggb0, *pl1b, *pnewxinb;
    float *pl1, *pnewx, *pxmax, *pp0, *pp1, *pp2;
    int *prs0, *prs1, *psrc0, *psrc1;
    float *pdinv0, *pdinv1;
    uint32_t *pwp;
    cudaGetSymbolAddress((void**)&phb,      g_hb);
    cudaGetSymbolAddress((void**)&phb0,     g_hb0);
    cudaGetSymbolAddress((void**)&paggb,    g_aggb);
    cudaGetSymbolAddress((void**)&paggb0,   g_aggb0);
    cudaGetSymbolAddress((void**)&pl1,      g_l1);
    cudaGetSymbolAddress((void**)&pl1b,     g_l1b);
    cudaGetSymbolAddress((void**)&pnewx,    g_newx);
    cudaGetSymbolAddress((void**)&pxmax,    g_xmax);
    cudaGetSymbolAddress((void**)&pp0,      g_p0);
    cudaGetSymbolAddress((void**)&pp1,      g_p1);
    cudaGetSymbolAddress((void**)&pp2,      g_p2);
    cudaGetSymbolAddress((void**)&pnewxinb, g_newxinb);
    cudaGetSymbolAddress((void**)&prs0,     g_rs0);
    cudaGetSymbolAddress((void**)&prs1,     g_rs1);
    cudaGetSymbolAddress((void**)&psrc0,    g_src0);
    cudaGetSymbolAddress((void**)&psrc1,    g_src1);
    cudaGetSymbolAddress((void**)&pdinv0,   g_dinv0);
    cudaGetSymbolAddress((void**)&pdinv1,   g_dinv1);
    cudaGetSymbolAddress((void**)&pwp,      g_wp);

    dim3 nodeGrid(1, (NN + 159) / 160, 1);   // 125 CTAs, one wave
    const int NB = (NN + 255) / 256;
    dim3 edgeGrid((EE / 4 + 255) / 256, 2);
    dim3 rawGrid((RAWF + 255) / 256, BB);

    // ===== stream 0: bounds -> W1 GEMM -> Wc0 GEMM -> branch3 chain =====
    bounds_kernel<<<1, 160>>>(gbatch);
    cudaEventRecord(evBounds, 0);
    cudaStreamWaitEvent(s1, evBounds, 0);
    cudaStreamWaitEvent(s2, evBounds, 0);

    // ===== stream s2: CSR build + Wc1/Wc2 preps =====
    zero2_kernel<<<NB, 256, 0, s2>>>();
    hist2_kernel<<<edgeGrid, 256, 0, s2>>>(ei, rei);
    scan2_kernel<<<2, 1024, 0, s2>>>();
    fill2_kernel<<<edgeGrid, 256, 0, s2>>>(ei, rei);
    prep_w_kernel<<<((HH / 2) * HH + 255) / 256, 256, 0, s2>>>(Wc1, pwp + OFF_WC1, (HH / 2) * HH, HH);
    prep_w_kernel<<<((HH / 2) * HH + 255) / 256, 256, 0, s2>>>(Wc2, pwp + OFF_WC2, (HH / 2) * HH, HH);
    cudaEventRecord(evCSR, s2);

    // ===== stream 0: W1 GEMM (overlaps CSR), then Wc0 GEMM =====
    prep_w_kernel<<<((FIN / 2) * HH + 255) / 256, 256>>>(W1,  pwp + OFF_W1,  (FIN / 2) * HH, HH);
    prep_w_kernel<<<((RAWF / 2) * HH + 255) / 256, 256>>>(Wc0, pwp + OFF_WC0, (RAWF / 2) * HH, HH);
    gemm_bf16<1, 0><<<nodeGrid, 256, 79872>>>(graph_x, pwp + OFF_W1, nullptr,
                                              (uint16_t*)phb0, NN, HH, FIN, FIN);
    cudaEventRecord(evW1, 0);

    // branch-1 gather + max-pool run on s2 UNDER the Wc0 GEMM (separate buffers)
    cudaStreamWaitEvent(s2, evW1, 0);
    gather_kernel<<<NN / 8, 256, 0, s2>>>((const uint4*)phb0, b1, prs0, psrc0, pdinv0, paggb0);
    pool_kernel<1><<<BB, 1024, 0, s2>>>((const uint2*)paggb0, pxmax);
    cudaEventRecord(evB1, s2);

    // branch 3 layer 0: fp32-A GEMM reads data_x directly
    gemm_bf16<1, 0><<<nodeGrid, 256, 79872>>>(data_x, pwp + OFF_WC0, nullptr,
                                              (uint16_t*)phb, NN, HH, RAWF, RAWF);
    cudaStreamWaitEvent(0, evCSR, 0);
    gather_kernel<<<NN / 8, 256>>>((const uint4*)phb, bc0, prs1, psrc1, pdinv1, paggb);
    cudaEventRecord(evG1, 0);
    // pool p0 on s2 (reads aggb), overlapping Wc1 GEMM (also reads aggb)
    cudaStreamWaitEvent(s2, evG1, 0);
    pool_kernel<0><<<BB, 1024, 0, s2>>>((const uint2*)paggb, pp0);
    cudaEventRecord(evP0, s2);

    gemm_bf16<0, 0><<<nodeGrid, 256, 59392>>>(paggb, pwp + OFF_WC1, nullptr,
                                              (uint16_t*)phb, NN, HH, HH, HH);
    cudaStreamWaitEvent(0, evP0, 0);     // gather2 overwrites aggb: wait for pool p0
    gather_kernel<<<NN / 8, 256>>>((const uint4*)phb, bc1, prs1, psrc1, pdinv1, paggb);
    cudaEventRecord(evG2, 0);
    cudaStreamWaitEvent(s2, evG2, 0);
    pool_kernel<0><<<BB, 1024, 0, s2>>>((const uint2*)paggb, pp1);
    cudaEventRecord(evP1, s2);

    gemm_bf16<0, 0><<<nodeGrid, 256, 59392>>>(paggb, pwp + OFF_WC2, nullptr,
                                              (uint16_t*)phb, NN, HH, HH, HH);
    cudaStreamWaitEvent(0, evP1, 0);     // gather3 overwrites aggb: wait for pool p1
    gather_kernel<<<NN / 8, 256>>>((const uint4*)phb, bc2, prs1, psrc1, pdinv1, paggb);
    pool_kernel<0><<<BB, 1024>>>((const uint2*)paggb, pp2);

    // ===== stream s1: branch 2 (memory-bound; overlaps tensor-bound stream 0) =====
    prep_w_kernel<<<(RAWF * 512 + 255) / 256, 256, 0, s1>>>(Wl1, pwp + OFF_WL1, RAWF * 512, 512);
    prep_w_kernel<<<(256 * HH + 255) / 256, 256, 0, s1>>>(Wl2, pwp + OFF_WL2, 256 * HH, HH);
    meanraw_kernel<<<rawGrid, 256, 0, s1>>>(data_x);
    root_kernel<<<rawGrid, 256, 0, s1>>>(data_x, root);
    init_bias_kernel<<<(BB * 512 + 255) / 256, 256, 0, s1>>>(pl1, bl1, BB * 512, 511);
    gemm_bf16<0, 1><<<dim3(2, 1, 63), 256, 59392, s1>>>(pnewxinb, pwp + OFF_WL1, pl1,
                                                        nullptr, BB, 512, 2 * RAWF, 160);
    prelu_kernel<<<(BB * 512 + 255) / 256, 256, 0, s1>>>(pl1, BB * 512, pa, pl1b);
    init_bias_kernel<<<(BB * 256 + 255) / 256, 256, 0, s1>>>(pnewx, bl2, BB * 256, 255);
    gemm_bf16<0, 1><<<dim3(1, 1, 8), 256, 59392, s1>>>(pl1b, pwp + OFF_WL2, pnewx,
                                                       nullptr, BB, HH, 512, 64);
    prelu_kernel<<<(BB * 256 + 255) / 256, 256, 0, s1>>>(pnewx, BB * 256, pa, nullptr);
    cudaEventRecord(evB2, s1);

    // ===== join + final =====
    cudaStreamWaitEvent(0, evB1, 0);
    cudaStreamWaitEvent(0, evB2, 0);
    final_kernel<<<BB, 256>>>(W5, b5, out);
}

// round 17
// speedup vs baseline: 1.6978x; 1.0208x over previous
#include <cuda_runtime.h>
#include <cuda_bf16.h>
#include <cstdint>

#define NN   20000
#define BB   128
#define EE   320000
#define FIN  768
#define RAWF 5000
#define HH   256
#define CC   4

// ---------------- scratch (device globals) ----------------
__device__ __align__(16) __nv_bfloat16 g_hb[NN * HH];    // branch3 GEMM output (bf16)
__device__ __align__(16) __nv_bfloat16 g_hb0[NN * HH];   // branch1 GEMM output (bf16)
__device__ __align__(16) __nv_bfloat16 g_aggb[NN * HH];  // branch3 activation (bf16)
__device__ __align__(16) __nv_bfloat16 g_aggb0[NN * HH]; // branch1 activation (bf16)
__device__ __align__(16) float g_l1[BB * 512];
__device__ __align__(16) __nv_bfloat16 g_l1b[BB * 512];
__device__ __align__(16) float g_newx[BB * HH];
__device__ __align__(16) float g_xmax[BB * HH];
__device__ __align__(16) float g_p0[BB * HH];
__device__ __align__(16) float g_p1[BB * HH];
__device__ __align__(16) float g_p2[BB * HH];
__device__ __align__(16) __nv_bfloat16 g_newxinb[BB * 2 * RAWF];
// packed k2-interleaved bf16 weights
#define OFF_W1   0
#define OFF_WC0  98304
#define OFF_WC1  738304
#define OFF_WC2  771072
#define OFF_WL1  803840
#define OFF_WL2  3363840
__device__ __align__(16) uint32_t g_wp[3429376];
__device__ __align__(16) int   g_cnt0[NN];
__device__ __align__(16) int   g_cnt1[NN];
__device__ int   g_cur0[NN];
__device__ int   g_cur1[NN];
__device__ __align__(16) int   g_rs0[NN + 4];
__device__ __align__(16) int   g_rs1[NN + 4];
__device__ int   g_src0[EE];
__device__ int   g_src1[EE];
__device__ __align__(16) float g_dinv0[NN];
__device__ __align__(16) float g_dinv1[NN];
__device__ int   g_bounds[BB + 1];

// ---------------- helpers ----------------
__device__ __forceinline__ uint32_t packbf(float lo, float hi) {
    uint32_t r;
    asm("cvt.rn.bf16x2.f32 %0, %1, %2;" : "=r"(r) : "f"(hi), "f"(lo));
    return r;
}
__device__ __forceinline__ void cpasync16(uint32_t dst, const void* src, bool ok) {
    int ss = ok ? 16 : 0;
    asm volatile("cp.async.cg.shared.global [%0], [%1], 16, %2;\n" :: "r"(dst), "l"(src), "r"(ss));
}
__device__ __forceinline__ void cpcommit() { asm volatile("cp.async.commit_group;\n"); }
__device__ __forceinline__ void cpwait0()  { asm volatile("cp.async.wait_group 0;\n"); }
__device__ __forceinline__ void unp(uint32_t w, float& a, float& b) {
    a = __uint_as_float(w << 16);
    b = __uint_as_float(w & 0xffff0000u);
}

// ---------------- segment bounds ----------------
__global__ void bounds_kernel(const int* __restrict__ batch) {
    int b = threadIdx.x;
    if (b > BB) return;
    int lo = 0, hi = NN;
    while (lo < hi) {
        int mid = (lo + hi) >> 1;
        if (batch[mid] < b) lo = mid + 1; else hi = mid;
    }
    g_bounds[b] = lo;
}

// ---------------- weight prep ----------------
__global__ void prep_w_kernel(const float* __restrict__ W, uint32_t* __restrict__ Wp,
                              int cnt, int N) {
    int idx = blockIdx.x * blockDim.x + threadIdx.x;
    if (idx >= cnt) return;
    int p = idx / N, n = idx - p * N;
    Wp[idx] = packbf(W[(size_t)(2 * p) * N + n], W[(size_t)(2 * p + 1) * N + n]);
}

// ---------------- CSR build ----------------
__global__ void zero2_kernel() {
    int i = blockIdx.x * blockDim.x + threadIdx.x;
    if (i < NN) { g_cnt0[i] = 0; g_cnt1[i] = 0; }
}
__global__ void hist2_kernel(const int* __restrict__ ei, const int* __restrict__ rei) {
    int i = blockIdx.x * blockDim.x + threadIdx.x;
    if (i >= EE / 4) return;
    const int* dst;
    int* cnt;
    if (blockIdx.y == 0) { dst = ei + EE;  cnt = g_cnt0; }
    else                 { dst = rei + EE; cnt = g_cnt1; }
    int4 d = ((const int4*)dst)[i];
    atomicAdd(&cnt[d.x], 1);
    atomicAdd(&cnt[d.y], 1);
    atomicAdd(&cnt[d.z], 1);
    atomicAdd(&cnt[d.w], 1);
}
__global__ void scan2_kernel() {
    __shared__ int wsum[32];
    int g = blockIdx.x;
    const int* cnt = g ? g_cnt1 : g_cnt0;
    int* rs        = g ? g_rs1  : g_rs0;
    int* cur       = g ? g_cur1 : g_cur0;
    float* dinv    = g ? g_dinv1 : g_dinv0;
    int t = threadIdx.x;
    int lane = t & 31, wid = t >> 5;
    int c[20];
    const int4* c4 = (const int4*)cnt;
#pragma unroll
    for (int i = 0; i < 5; i++) {
        int idx4 = t * 5 + i;
        int4 v = (idx4 < 5000) ? c4[idx4] : make_int4(0, 0, 0, 0);
        c[i * 4 + 0] = v.x; c[i * 4 + 1] = v.y; c[i * 4 + 2] = v.z; c[i * 4 + 3] = v.w;
    }
    int loc[20];
    int s = 0;
#pragma unroll
    for (int i = 0; i < 20; i++) { loc[i] = s; s += c[i]; }
    int x = s;
#pragma unroll
    for (int off = 1; off < 32; off <<= 1) {
        int y = __shfl_up_sync(0xffffffffu, x, off);
        if (lane >= off) x += y;
    }
    if (lane == 31) wsum[wid] = x;
    __syncthreads();
    if (wid == 0) {
        int v = wsum[lane];
#pragma unroll
        for (int off = 1; off < 32; off <<= 1) {
            int y = __shfl_up_sync(0xffffffffu, v, off);
            if (lane >= off) v += y;
        }
        wsum[lane] = v;
    }
    __syncthreads();
    int offset = (wid ? wsum[wid - 1] : 0) + (x - s);
    int4* rs4 = (int4*)rs;
    int4* cu4 = (int4*)cur;
    float4* dv4 = (float4*)dinv;
#pragma unroll
    for (int i = 0; i < 5; i++) {
        int idx4 = t * 5 + i;
        if (idx4 < 5000) {
            int4 r; float4 d;
            r.x = offset + loc[i * 4 + 0]; d.x = rsqrtf((float)(c[i * 4 + 0] + 1));
            r.y = offset + loc[i * 4 + 1]; d.y = rsqrtf((float)(c[i * 4 + 1] + 1));
            r.z = offset + loc[i * 4 + 2]; d.z = rsqrtf((float)(c[i * 4 + 2] + 1));
            r.w = offset + loc[i * 4 + 3]; d.w = rsqrtf((float)(c[i * 4 + 3] + 1));
            rs4[idx4] = r; cu4[idx4] = r; dv4[idx4] = d;
        }
    }
    if (t == 0) rs[NN] = EE;
}
__global__ void fill2_kernel(const int* __restrict__ ei, const int* __restrict__ rei) {
    int i = blockIdx.x * blockDim.x + threadIdx.x;
    if (i >= EE / 4) return;
    const int* src;
    const int* dst;
    int* cur;
    int* outp;
    if (blockIdx.y == 0) { src = ei;  dst = ei + EE;  cur = g_cur0; outp = g_src0; }
    else                 { src = rei; dst = rei + EE; cur = g_cur1; outp = g_src1; }
    int4 d = ((const int4*)dst)[i];
    int4 s = ((const int4*)src)[i];
    outp[atomicAdd(&cur[d.x], 1)] = s.x;
    outp[atomicAdd(&cur[d.y], 1)] = s.y;
    outp[atomicAdd(&cur[d.z], 1)] = s.z;
    outp[atomicAdd(&cur[d.w], 1)] = s.w;
}

// ---------------- fused GCN aggregation + relu (bf16 in/out), edge loop unrolled x4 ----------------
__global__ __launch_bounds__(256)
void gather_kernel(const uint4* __restrict__ hb, const float* __restrict__ bias,
                   const int* __restrict__ rs, const int* __restrict__ csr,
                   const float* __restrict__ dinv, __nv_bfloat16* __restrict__ outb) {
    int node = blockIdx.x * 8 + (threadIdx.x >> 5);
    int lane = threadIdx.x & 31;
    float di = dinv[node];
    float sw = di * di;
    float acc[8];
    {
        uint4 hv = hb[(size_t)node * 32 + lane];
        float f0, f1;
        unp(hv.x, f0, f1); acc[0] = f0 * sw; acc[1] = f1 * sw;
        unp(hv.y, f0, f1); acc[2] = f0 * sw; acc[3] = f1 * sw;
        unp(hv.z, f0, f1); acc[4] = f0 * sw; acc[5] = f1 * sw;
        unp(hv.w, f0, f1); acc[6] = f0 * sw; acc[7] = f1 * sw;
    }
    int e0 = rs[node], e1 = rs[node + 1];
    int e = e0;
    for (; e + 4 <= e1; e += 4) {
        int s0 = csr[e], s1 = csr[e + 1], s2 = csr[e + 2], s3 = csr[e + 3];
        float w0 = dinv[s0] * di, w1 = dinv[s1] * di;
        float w2 = dinv[s2] * di, w3 = dinv[s3] * di;
        uint4 h0 = hb[(size_t)s0 * 32 + lane];
        uint4 h1 = hb[(size_t)s1 * 32 + lane];
        uint4 h2 = hb[(size_t)s2 * 32 + lane];
        uint4 h3 = hb[(size_t)s3 * 32 + lane];
        float f0, f1;
        unp(h0.x, f0, f1); acc[0] = fmaf(f0, w0, acc[0]); acc[1] = fmaf(f1, w0, acc[1]);
        unp(h0.y, f0, f1); acc[2] = fmaf(f0, w0, acc[2]); acc[3] = fmaf(f1, w0, acc[3]);
        unp(h0.z, f0, f1); acc[4] = fmaf(f0, w0, acc[4]); acc[5] = fmaf(f1, w0, acc[5]);
        unp(h0.w, f0, f1); acc[6] = fmaf(f0, w0, acc[6]); acc[7] = fmaf(f1, w0, acc[7]);
        unp(h1.x, f0, f1); acc[0] = fmaf(f0, w1, acc[0]); acc[1] = fmaf(f1, w1, acc[1]);
        unp(h1.y, f0, f1); acc[2] = fmaf(f0, w1, acc[2]); acc[3] = fmaf(f1, w1, acc[3]);
        unp(h1.z, f0, f1); acc[4] = fmaf(f0, w1, acc[4]); acc[5] = fmaf(f1, w1, acc[5]);
        unp(h1.w, f0, f1); acc[6] = fmaf(f0, w1, acc[6]); acc[7] = fmaf(f1, w1, acc[7]);
        unp(h2.x, f0, f1); acc[0] = fmaf(f0, w2, acc[0]); acc[1] = fmaf(f1, w2, acc[1]);
        unp(h2.y, f0, f1); acc[2] = fmaf(f0, w2, acc[2]); acc[3] = fmaf(f1, w2, acc[3]);
        unp(h2.z, f0, f1); acc[4] = fmaf(f0, w2, acc[4]); acc[5] = fmaf(f1, w2, acc[5]);
        unp(h2.w, f0, f1); acc[6] = fmaf(f0, w2, acc[6]); acc[7] = fmaf(f1, w2, acc[7]);
        unp(h3.x, f0, f1); acc[0] = fmaf(f0, w3, acc[0]); acc[1] = fmaf(f1, w3, acc[1]);
        unp(h3.y, f0, f1); acc[2] = fmaf(f0, w3, acc[2]); acc[3] = fmaf(f1, w3, acc[3]);
        unp(h3.z, f0, f1); acc[4] = fmaf(f0, w3, acc[4]); acc[5] = fmaf(f1, w3, acc[5]);
        unp(h3.w, f0, f1); acc[6] = fmaf(f0, w3, acc[6]); acc[7] = fmaf(f1, w3, acc[7]);
    }
    for (; e < e1; e++) {
        int s = csr[e];
        float w = dinv[s] * di;
        uint4 hv = hb[(size_t)s * 32 + lane];
        float f0, f1;
        unp(hv.x, f0, f1); acc[0] = fmaf(f0, w, acc[0]); acc[1] = fmaf(f1, w, acc[1]);
        unp(hv.y, f0, f1); acc[2] = fmaf(f0, w, acc[2]); acc[3] = fmaf(f1, w, acc[3]);
        unp(hv.z, f0, f1); acc[4] = fmaf(f0, w, acc[4]); acc[5] = fmaf(f1, w, acc[5]);
        unp(hv.w, f0, f1); acc[6] = fmaf(f0, w, acc[6]); acc[7] = fmaf(f1, w, acc[7]);
    }
    float4 bb0 = ((const float4*)bias)[2 * lane];
    float4 bb1 = ((const float4*)bias)[2 * lane + 1];
    float v[8];
    v[0] = fmaxf(acc[0] + bb0.x, 0.f); v[1] = fmaxf(acc[1] + bb0.y, 0.f);
    v[2] = fmaxf(acc[2] + bb0.z, 0.f); v[3] = fmaxf(acc[3] + bb0.w, 0.f);
    v[4] = fmaxf(acc[4] + bb1.x, 0.f); v[5] = fmaxf(acc[5] + bb1.y, 0.f);
    v[6] = fmaxf(acc[6] + bb1.z, 0.f); v[7] = fmaxf(acc[7] + bb1.w, 0.f);
    uint4 o;
    o.x = packbf(v[0], v[1]); o.y = packbf(v[2], v[3]);
    o.z = packbf(v[4], v[5]); o.w = packbf(v[6], v[7]);
    ((uint4*)outb)[(size_t)node * 32 + lane] = o;
}

// ---------------- pooling over contiguous segments (bf16 input, no atomics) ----------------
template<int ISMAX>
__global__ void pool_kernel(const uint2* __restrict__ xb, float* __restrict__ out) {
    __shared__ float red[16 * 256];
    int b = blockIdx.x, t = threadIdx.x;
    int q = t & 63;
    int rp = t >> 6;         // 0..15
    int s = g_bounds[b], e = g_bounds[b + 1];
    float a0 = 0.f, a1 = 0.f, a2 = 0.f, a3 = 0.f;
    for (int i = s + rp; i < e; i += 16) {
        uint2 v = xb[(size_t)i * 64 + q];
        float f0, f1, f2, f3;
        unp(v.x, f0, f1); unp(v.y, f2, f3);
        if (ISMAX) {
            a0 = fmaxf(a0, f0); a1 = fmaxf(a1, f1);
            a2 = fmaxf(a2, f2); a3 = fmaxf(a3, f3);
        } else {
            a0 += f0; a1 += f1; a2 += f2; a3 += f3;
        }
    }
    red[rp * 256 + q * 4 + 0] = a0;
    red[rp * 256 + q * 4 + 1] = a1;
    red[rp * 256 + q * 4 + 2] = a2;
    red[rp * 256 + q * 4 + 3] = a3;
    __syncthreads();
    if (t < 256) {
        float r = red[t];
#pragma unroll
        for (int p = 1; p < 16; p++) {
            if (ISMAX) r = fmaxf(r, red[p * 256 + t]);
            else       r += red[p * 256 + t];
        }
        out[b * HH + t] = r;
    }
}

// ---------------- bf16 tensor-core GEMM (mma.sync) ----------------
template<int AF32, int ATOMIC>
__global__ __launch_bounds__(256)
void gemm_bf16(const void* __restrict__ Av, const uint32_t* __restrict__ Bp,
               float* __restrict__ C, uint16_t* __restrict__ Cb,
               int M, int N, int K, int KS) {
    constexpr int ABUFSZ = AF32 ? 23040 : 12800;
    constexpr int BBUFSZ = 16896;
    extern __shared__ __align__(16) uint8_t smraw[];
    int tid = threadIdx.x;
    int lane = tid & 31, wid = tid >> 5;
    int warp_m = wid & 1, warp_n = wid >> 1;
    int bm = blockIdx.y * 160;
    int bn = blockIdx.x * 256;
    int kbeg = blockIdx.z * KS;
    int kend = min(K, kbeg + KS);
    int ntiles = (kend - kbeg + 31) >> 5;
    uint32_t sbase = (uint32_t)__cvta_generic_to_shared(smraw);

    float acc[5][8][4];
#pragma unroll
    for (int mt = 0; mt < 5; mt++)
#pragma unroll
        for (int nt = 0; nt < 8; nt++)
#pragma unroll
            for (int q = 0; q < 4; q++) acc[mt][nt][q] = 0.f;

    auto prefetch = [&](int tile, int pbuf) {
        int k0 = kbeg + tile * 32;
        if (AF32) {
            const float* A = (const float*)Av;
#pragma unroll
            for (int i = 0; i < 5; i++) {
                int c = tid + 256 * i;
                int row = c >> 3, ch = c & 7;
                bool ok = (bm + row < M) && (k0 + ch * 4 < kend);
                const void* src = A + (size_t)(bm + row) * K + k0 + ch * 4;
                cpasync16(sbase + pbuf * ABUFSZ + row * 144 + ch * 16, ok ? src : A, ok);
            }
        } else {
            const __nv_bfloat16* A = (const __nv_bfloat16*)Av;
#pragma unroll
            for (int i = 0; i < 3; i++) {
                int c = tid + 256 * i;
                if (c < 640) {
                    int row = c >> 2, ch = c & 3;
                    bool ok = (bm + row < M) && (k0 + ch * 8 < kend);
                    const void* src = A + (size_t)(bm + row) * K + k0 + ch * 8;
                    cpasync16(sbase + pbuf * ABUFSZ + row * 80 + ch * 16, ok ? src : A, ok);
                }
            }
        }
#pragma unroll
        for (int i = 0; i < 4; i++) {
            int c = tid + 256 * i;
            int row = c >> 6, seg = c & 63;
            bool ok = (k0 + 2 * row < kend);
            const void* src = Bp + (size_t)(k0 / 2 + row) * N + bn + seg * 4;
            cpasync16(sbase + 2 * ABUFSZ + pbuf * BBUFSZ + row * 1056 + seg * 16,
                      ok ? src : Bp, ok);
        }
        cpcommit();
    };

    int buf = 0;
    prefetch(0, 0);
    for (int t = 0; t < ntiles; t++) {
        cpwait0();
        __syncthreads();
        if (t + 1 < ntiles) prefetch(t + 1, buf ^ 1);

        const uint32_t* Bsb = (const uint32_t*)(smraw + 2 * ABUFSZ + buf * BBUFSZ);
#pragma unroll
        for (int ks = 0; ks < 2; ks++) {
            int kk0 = ks * 16 + 2 * (lane & 3);
            uint32_t af[5][4];
            if (AF32) {
                const float* Asf = (const float*)(smraw + buf * ABUFSZ);
#pragma unroll
                for (int mt = 0; mt < 5; mt++) {
                    int r = warp_m * 80 + mt * 16 + (lane >> 2);
                    float2 v0 = *(const float2*)(Asf + r * 36 + kk0);
                    float2 v1 = *(const float2*)(Asf + (r + 8) * 36 + kk0);
                    float2 v2 = *(const float2*)(Asf + r * 36 + kk0 + 8);
                    float2 v3 = *(const float2*)(Asf + (r + 8) * 36 + kk0 + 8);
                    af[mt][0] = packbf(v0.x, v0.y);
                    af[mt][1] = packbf(v1.x, v1.y);
                    af[mt][2] = packbf(v2.x, v2.y);
                    af[mt][3] = packbf(v3.x, v3.y);
                }
            } else {
                const uint16_t* Asb = (const uint16_t*)(smraw + buf * ABUFSZ);
#pragma unroll
                for (int mt = 0; mt < 5; mt++) {
                    int r = warp_m * 80 + mt * 16 + (lane >> 2);
                    af[mt][0] = *(const uint32_t*)(Asb + r * 40 + kk0);
                    af[mt][1] = *(const uint32_t*)(Asb + (r + 8) * 40 + kk0);
                    af[mt][2] = *(const uint32_t*)(Asb + r * 40 + kk0 + 8);
                    af[mt][3] = *(const uint32_t*)(Asb + (r + 8) * 40 + kk0 + 8);
                }
            }
            int p = ks * 8 + (lane & 3);
#pragma unroll
            for (int nt = 0; nt < 8; nt++) {
                int cl = warp_n * 64 + nt * 8 + (lane >> 2);
                uint32_t b0 = Bsb[p * 264 + cl];
                uint32_t b1 = Bsb[(p + 4) * 264 + cl];
#pragma unroll
                for (int mt = 0; mt < 5; mt++) {
                    asm volatile(
                        "mma.sync.aligned.m16n8k16.row.col.f32.bf16.bf16.f32 "
                        "{%0,%1,%2,%3}, {%4,%5,%6,%7}, {%8,%9}, {%0,%1,%2,%3};\n"
                        : "+f"(acc[mt][nt][0]), "+f"(acc[mt][nt][1]),
                          "+f"(acc[mt][nt][2]), "+f"(acc[mt][nt][3])
                        : "r"(af[mt][0]), "r"(af[mt][1]), "r"(af[mt][2]), "r"(af[mt][3]),
                          "r"(b0), "r"(b1));
                }
            }
        }
        buf ^= 1;
        __syncthreads();
    }

#pragma unroll
    for (int mt = 0; mt < 5; mt++) {
#pragma unroll
        for (int nt = 0; nt < 8; nt++) {
            int row = bm + warp_m * 80 + mt * 16 + (lane >> 2);
            int col = bn + warp_n * 64 + nt * 8 + 2 * (lane & 3);
            if (ATOMIC) {
                if (row < M) {
                    atomicAdd(&C[(size_t)row * N + col],     acc[mt][nt][0]);
                    atomicAdd(&C[(size_t)row * N + col + 1], acc[mt][nt][1]);
                }
                if (row + 8 < M) {
                    atomicAdd(&C[(size_t)(row + 8) * N + col],     acc[mt][nt][2]);
                    atomicAdd(&C[(size_t)(row + 8) * N + col + 1], acc[mt][nt][3]);
                }
            } else {
                uint32_t* Cb32 = (uint32_t*)Cb;
                if (row < M)
                    Cb32[((size_t)row * N + col) >> 1] = packbf(acc[mt][nt][0], acc[mt][nt][1]);
                if (row + 8 < M)
                    Cb32[((size_t)(row + 8) * N + col) >> 1] = packbf(acc[mt][nt][2], acc[mt][nt][3]);
            }
        }
    }
}

// ---------------- branch2 front: segment mean only ----------------
__global__ void meanraw_kernel(const float* __restrict__ dx) {
    int f = blockIdx.x * 256 + threadIdx.x;
    if (f >= RAWF) return;
    int b = blockIdx.y;
    int s = g_bounds[b], e = g_bounds[b + 1];
    float acc = 0.f;
    for (int i = s; i < e; i++) acc += dx[(size_t)i * RAWF + f];
    int cnt = e - s; if (cnt < 1) cnt = 1;
    g_newxinb[(size_t)b * (2 * RAWF) + f] = __float2bfloat16(acc / (float)cnt);
}
__global__ void root_kernel(const float* __restrict__ dx, const int* __restrict__ root) {
    int f = blockIdx.x * 256 + threadIdx.x;
    if (f >= RAWF) return;
    int b = blockIdx.y;
    g_newxinb[(size_t)b * (2 * RAWF) + RAWF + f] =
        __float2bfloat16(dx[(size_t)root[b] * RAWF + f]);
}

// ---------------- small elementwise ----------------
__global__ void init_bias_kernel(float* __restrict__ p, const float* __restrict__ bias,
                                 int n, int mask) {
    int i = blockIdx.x * blockDim.x + threadIdx.x;
    if (i < n) p[i] = bias[i & mask];
}
__global__ void prelu_kernel(float* __restrict__ p, int n, const float* __restrict__ pa,
                             __nv_bfloat16* __restrict__ outb) {
    int i = blockIdx.x * blockDim.x + threadIdx.x;
    if (i >= n) return;
    float a = *pa;
    float v = p[i];
    v = v >= 0.f ? v : a * v;
    if (outb) outb[i] = __float2bfloat16(v);
    else p[i] = v;
}

// ---------------- final projection + log_softmax ----------------
__global__ void final_kernel(const float* __restrict__ W5, const float* __restrict__ b5,
                             float* __restrict__ out) {
    __shared__ float red[4][256];
    int b = blockIdx.x, t = threadIdx.x;
    int cnt = g_bounds[b + 1] - g_bounds[b];
    float inv = 1.f / (float)(cnt < 1 ? 1 : cnt);
    float acc[4] = {0.f, 0.f, 0.f, 0.f};
    for (int k = t; k < 5 * HH; k += 256) {
        int seg = k >> 8, f = k & 255;
        float v;
        if      (seg == 0) v = g_p0[b * HH + f] * inv;
        else if (seg == 1) v = g_p1[b * HH + f] * inv;
        else if (seg == 2) v = g_p2[b * HH + f] * inv;
        else if (seg == 3) v = g_newx[b * HH + f];
        else               v = g_xmax[b * HH + f];
#pragma unroll
        for (int c = 0; c < 4; c++) acc[c] += v * W5[k * 4 + c];
    }
#pragma unroll
    for (int c = 0; c < 4; c++) red[c][t] = acc[c];
    __syncthreads();
    for (int s = 128; s > 0; s >>= 1) {
        if (t < s) {
#pragma unroll
            for (int c = 0; c < 4; c++) red[c][t] += red[c][t + s];
        }
        __syncthreads();
    }
    if (t == 0) {
        float z[4];
#pragma unroll
        for (int c = 0; c < 4; c++) z[c] = red[c][0] + b5[c];
        float m = z[0];
#pragma unroll
        for (int c = 1; c < 4; c++) m = fmaxf(m, z[c]);
        float ssum = 0.f;
#pragma unroll
        for (int c = 0; c < 4; c++) ssum += expf(z[c] - m);
        float ls = logf(ssum);
#pragma unroll
        for (int c = 0; c < 4; c++) out[b * 4 + c] = z[c] - m - ls;
    }
}

// ---------------- host ----------------
extern "C" void kernel_launch(void* const* d_in, const int* in_sizes, int n_in,
                              void* d_out, int out_size) {
    const float* graph_x = (const float*)d_in[0];
    const float* data_x  = (const float*)d_in[2];
    const int*   ei      = (const int*)d_in[3];
    const int*   rei     = (const int*)d_in[4];
    const int*   gbatch  = (const int*)d_in[5];
    const int*   root    = (const int*)d_in[7];
    const float* W1  = (const float*)d_in[8];
    const float* b1  = (const float*)d_in[9];
    const float* Wc0 = (const float*)d_in[10];
    const float* bc0 = (const float*)d_in[11];
    const float* Wc1 = (const float*)d_in[12];
    const float* bc1 = (const float*)d_in[13];
    const float* Wc2 = (const float*)d_in[14];
    const float* bc2 = (const float*)d_in[15];
    const float* Wl1 = (const float*)d_in[16];
    const float* bl1 = (const float*)d_in[17];
    const float* Wl2 = (const float*)d_in[18];
    const float* bl2 = (const float*)d_in[19];
    const float* pa  = (const float*)d_in[20];
    const float* W5  = (const float*)d_in[21];
    const float* b5  = (const float*)d_in[22];
    float* out = (float*)d_out;

    static bool s_init = false;
    static cudaStream_t s1, s2;
    static cudaEvent_t evStart, evBounds, evCSR, evW1, evG1, evG2, evP0, evP1, evB1, evB2;
    if (!s_init) {
        cudaStreamCreateWithFlags(&s1, cudaStreamNonBlocking);
        cudaStreamCreateWithFlags(&s2, cudaStreamNonBlocking);
        cudaEventCreateWithFlags(&evStart,  cudaEventDisableTiming);
        cudaEventCreateWithFlags(&evBounds, cudaEventDisableTiming);
        cudaEventCreateWithFlags(&evCSR,    cudaEventDisableTiming);
        cudaEventCreateWithFlags(&evW1,     cudaEventDisableTiming);
        cudaEventCreateWithFlags(&evG1,     cudaEventDisableTiming);
        cudaEventCreateWithFlags(&evG2,     cudaEventDisableTiming);
        cudaEventCreateWithFlags(&evP0,     cudaEventDisableTiming);
        cudaEventCreateWithFlags(&evP1,     cudaEventDisableTiming);
        cudaEventCreateWithFlags(&evB1,     cudaEventDisableTiming);
        cudaEventCreateWithFlags(&evB2,     cudaEventDisableTiming);
        cudaFuncSetAttribute(gemm_bf16<1, 0>, cudaFuncAttributeMaxDynamicSharedMemorySize, 79872);
        cudaFuncSetAttribute(gemm_bf16<0, 0>, cudaFuncAttributeMaxDynamicSharedMemorySize, 59392);
        cudaFuncSetAttribute(gemm_bf16<0, 1>, cudaFuncAttributeMaxDynamicSharedMemorySize, 59392);
        s_init = true;
    }

    __nv_bfloat16 *phb, *phb0, *paggb, *paggb0, *pl1b, *pnewxinb;
    float *pl1, *pnewx, *pxmax, *pp0, *pp1, *pp2;
    int *prs0, *prs1, *psrc0, *psrc1;
    float *pdinv0, *pdinv1;
    uint32_t *pwp;
    cudaGetSymbolAddress((void**)&phb,      g_hb);
    cudaGetSymbolAddress((void**)&phb0,     g_hb0);
    cudaGetSymbolAddress((void**)&paggb,    g_aggb);
    cudaGetSymbolAddress((void**)&paggb0,   g_aggb0);
    cudaGetSymbolAddress((void**)&pl1,      g_l1);
    cudaGetSymbolAddress((void**)&pl1b,     g_l1b);
    cudaGetSymbolAddress((void**)&pnewx,    g_newx);
    cudaGetSymbolAddress((void**)&pxmax,    g_xmax);
    cudaGetSymbolAddress((void**)&pp0,      g_p0);
    cudaGetSymbolAddress((void**)&pp1,      g_p1);
    cudaGetSymbolAddress((void**)&pp2,      g_p2);
    cudaGetSymbolAddress((void**)&pnewxinb, g_newxinb);
    cudaGetSymbolAddress((void**)&prs0,     g_rs0);
    cudaGetSymbolAddress((void**)&prs1,     g_rs1);
    cudaGetSymbolAddress((void**)&psrc0,    g_src0);
    cudaGetSymbolAddress((void**)&psrc1,    g_src1);
    cudaGetSymbolAddress((void**)&pdinv0,   g_dinv0);
    cudaGetSymbolAddress((void**)&pdinv1,   g_dinv1);
    cudaGetSymbolAddress((void**)&pwp,      g_wp);

    dim3 nodeGrid(1, (NN + 159) / 160, 1);   // 125 CTAs, one wave
    const int NB = (NN + 255) / 256;
    dim3 edgeGrid((EE / 4 + 255) / 256, 2);
    dim3 rawGrid((RAWF + 255) / 256, BB);

    // ===== fork: all side streams branch from the origin stream's first node =====
    cudaEventRecord(evStart, 0);
    cudaStreamWaitEvent(s1, evStart, 0);
    cudaStreamWaitEvent(s2, evStart, 0);

    // ===== stream s2: CSR build (concurrent with bounds + W1 GEMM) =====
    zero2_kernel<<<NB, 256, 0, s2>>>();
    hist2_kernel<<<edgeGrid, 256, 0, s2>>>(ei, rei);
    scan2_kernel<<<2, 1024, 0, s2>>>();
    fill2_kernel<<<edgeGrid, 256, 0, s2>>>(ei, rei);
    prep_w_kernel<<<((HH / 2) * HH + 255) / 256, 256, 0, s2>>>(Wc1, pwp + OFF_WC1, (HH / 2) * HH, HH);
    prep_w_kernel<<<((HH / 2) * HH + 255) / 256, 256, 0, s2>>>(Wc2, pwp + OFF_WC2, (HH / 2) * HH, HH);
    cudaEventRecord(evCSR, s2);

    // ===== stream s1: weight preps + root (no bounds dep) =====
    prep_w_kernel<<<(RAWF * 512 + 255) / 256, 256, 0, s1>>>(Wl1, pwp + OFF_WL1, RAWF * 512, 512);
    prep_w_kernel<<<(256 * HH + 255) / 256, 256, 0, s1>>>(Wl2, pwp + OFF_WL2, 256 * HH, HH);
    root_kernel<<<rawGrid, 256, 0, s1>>>(data_x, root);

    // ===== stream 0: bounds -> W1 GEMM -> Wc0 GEMM -> branch3 chain =====
    bounds_kernel<<<1, 160>>>(gbatch);
    cudaEventRecord(evBounds, 0);
    cudaStreamWaitEvent(s1, evBounds, 0);   // meanraw needs bounds

    prep_w_kernel<<<((FIN / 2) * HH + 255) / 256, 256>>>(W1,  pwp + OFF_W1,  (FIN / 2) * HH, HH);
    prep_w_kernel<<<((RAWF / 2) * HH + 255) / 256, 256>>>(Wc0, pwp + OFF_WC0, (RAWF / 2) * HH, HH);
    gemm_bf16<1, 0><<<nodeGrid, 256, 79872>>>(graph_x, pwp + OFF_W1, nullptr,
                                              (uint16_t*)phb0, NN, HH, FIN, FIN);
    cudaEventRecord(evW1, 0);

    // branch-1 gather + max-pool on s2 UNDER the Wc0 GEMM (separate buffers)
    cudaStreamWaitEvent(s2, evW1, 0);       // also implies evBounds (recorded earlier on 0)
    gather_kernel<<<NN / 8, 256, 0, s2>>>((const uint4*)phb0, b1, prs0, psrc0, pdinv0, paggb0);
    pool_kernel<1><<<BB, 1024, 0, s2>>>((const uint2*)paggb0, pxmax);
    cudaEventRecord(evB1, s2);

    // branch 3 layer 0: fp32-A GEMM reads data_x directly
    gemm_bf16<1, 0><<<nodeGrid, 256, 79872>>>(data_x, pwp + OFF_WC0, nullptr,
                                              (uint16_t*)phb, NN, HH, RAWF, RAWF);
    cudaStreamWaitEvent(0, evCSR, 0);
    gather_kernel<<<NN / 8, 256>>>((const uint4*)phb, bc0, prs1, psrc1, pdinv1, paggb);
    cudaEventRecord(evG1, 0);
    cudaStreamWaitEvent(s2, evG1, 0);
    pool_kernel<0><<<BB, 1024, 0, s2>>>((const uint2*)paggb, pp0);
    cudaEventRecord(evP0, s2);

    gemm_bf16<0, 0><<<nodeGrid, 256, 59392>>>(paggb, pwp + OFF_WC1, nullptr,
                                              (uint16_t*)phb, NN, HH, HH, HH);
    cudaStreamWaitEvent(0, evP0, 0);     // gather2 overwrites aggb: wait for pool p0
    gather_kernel<<<NN / 8, 256>>>((const uint4*)phb, bc1, prs1, psrc1, pdinv1, paggb);
    cudaEventRecord(evG2, 0);
    cudaStreamWaitEvent(s2, evG2, 0);
    pool_kernel<0><<<BB, 1024, 0, s2>>>((const uint2*)paggb, pp1);
    cudaEventRecord(evP1, s2);

    gemm_bf16<0, 0><<<nodeGrid, 256, 59392>>>(paggb, pwp + OFF_WC2, nullptr,
                                              (uint16_t*)phb, NN, HH, HH, HH);
    cudaStreamWaitEvent(0, evP1, 0);     // gather3 overwrites aggb: wait for pool p1
    gather_kernel<<<NN / 8, 256>>>((const uint4*)phb, bc2, prs1, psrc1, pdinv1, paggb);
    pool_kernel<0><<<BB, 1024>>>((const uint2*)paggb, pp2);

    // ===== stream s1 (continues after bounds): branch 2 =====
    meanraw_kernel<<<rawGrid, 256, 0, s1>>>(data_x);
    init_bias_kernel<<<(BB * 512 + 255) / 256, 256, 0, s1>>>(pl1, bl1, BB * 512, 511);
    gemm_bf16<0, 1><<<dim3(2, 1, 63), 256, 59392, s1>>>(pnewxinb, pwp + OFF_WL1, pl1,
                                                        nullptr, BB, 512, 2 * RAWF, 160);
    prelu_kernel<<<(BB * 512 + 255) / 256, 256, 0, s1>>>(pl1, BB * 512, pa, pl1b);
    init_bias_kernel<<<(BB * 256 + 255) / 256, 256, 0, s1>>>(pnewx, bl2, BB * 256, 255);
    gemm_bf16<0, 1><<<dim3(1, 1, 8), 256, 59392, s1>>>(pl1b, pwp + OFF_WL2, pnewx,
                                                       nullptr, BB, HH, 512, 64);
    prelu_kernel<<<(BB * 256 + 255) / 256, 256, 0, s1>>>(pnewx, BB * 256, pa, nullptr);
    cudaEventRecord(evB2, s1);

    // ===== join + final =====
    cudaStreamWaitEvent(0, evB1, 0);
    cudaStreamWaitEvent(0, evB2, 0);
    final_kernel<<<BB, 256>>>(W5, b5, out);
}